// round 6
// baseline (speedup 1.0000x reference)
#include <cuda_runtime.h>
#include <cuda_bf16.h>
#include <math.h>
#include <cstdint>

// Problem constants
#define T_LEN 2048
#define DIMX 2048
#define NH 16
#define NOPE 128
#define ROPE 64
#define VDIM 128
#define QKD 192
#define Q_LORA 768
#define KV_LORA 512
#define KVA_OUT 576
#define SOFTSCALE (-96.0f)
#define EPS 1e-6f

// ==================== scratch ====================
__device__ float g_qa  [(size_t)T_LEN * Q_LORA];
__device__ float g_q   [(size_t)T_LEN * NH * QKD];
__device__ float g_kvf [(size_t)T_LEN * KVA_OUT];
__device__ float g_ckvn[(size_t)T_LEN * KV_LORA];
__device__ float g_kpe [(size_t)T_LEN * ROPE];
__device__ float g_kv  [(size_t)T_LEN * NH * (NOPE + VDIM)];
__device__ float g_qh  [(size_t)NH * T_LEN * QKD];
__device__ float g_kh  [(size_t)NH * T_LEN * QKD];
__device__ float g_v   [(size_t)NH * T_LEN * VDIM];
__device__ float g_y   [(size_t)T_LEN * NH * VDIM];

// bf16 split buffers (hi/lo)
__device__ __nv_bfloat16 g_xh [(size_t)T_LEN * DIMX],      g_xl [(size_t)T_LEN * DIMX];
__device__ __nv_bfloat16 g_wqah[(size_t)Q_LORA * DIMX],    g_wqal[(size_t)Q_LORA * DIMX];
__device__ __nv_bfloat16 g_qah[(size_t)T_LEN * Q_LORA],    g_qal[(size_t)T_LEN * Q_LORA];
__device__ __nv_bfloat16 g_wqbh[(size_t)NH * QKD * Q_LORA],g_wqbl[(size_t)NH * QKD * Q_LORA];
__device__ __nv_bfloat16 g_wkvah[(size_t)KVA_OUT * DIMX],  g_wkval[(size_t)KVA_OUT * DIMX];
__device__ __nv_bfloat16 g_ckvnh[(size_t)T_LEN * KV_LORA], g_ckvnl[(size_t)T_LEN * KV_LORA];
__device__ __nv_bfloat16 g_wkvbh[(size_t)4096 * KV_LORA],  g_wkvbl[(size_t)4096 * KV_LORA];
__device__ __nv_bfloat16 g_yh [(size_t)T_LEN * DIMX],      g_yl [(size_t)T_LEN * DIMX];
__device__ __nv_bfloat16 g_woh[(size_t)DIMX * DIMX],       g_wol[(size_t)DIMX * DIMX];

// ==================== PTX helpers (all legal on plain sm_103) ====================
__device__ __forceinline__ uint32_t smem_u32(const void* p) {
    uint32_t a;
    asm("{ .reg .u64 t; cvta.to.shared.u64 t, %1; cvt.u32.u64 %0, t; }" : "=r"(a) : "l"(p));
    return a;
}
#define CPA(dst, src) \
    asm volatile("cp.async.cg.shared.global [%0], [%1], 16;" :: "r"(dst), "l"(src))
#define CPA_SZ(dst, src, sz) \
    asm volatile("cp.async.cg.shared.global [%0], [%1], 16, %2;" :: "r"(dst), "l"(src), "r"(sz))
#define CPA_COMMIT() asm volatile("cp.async.commit_group;" ::: "memory")
#define CPA_WAIT1()  asm volatile("cp.async.wait_group 1;" ::: "memory")

#define LDSM_X4(r0, r1, r2, r3, addr) \
    asm volatile("ldmatrix.sync.aligned.m8n8.x4.shared.b16 {%0,%1,%2,%3}, [%4];" \
        : "=r"(r0), "=r"(r1), "=r"(r2), "=r"(r3) : "r"(addr))

#define MMA_BF16(d, a, b0, b1) \
    asm volatile("mma.sync.aligned.m16n8k16.row.col.f32.bf16.bf16.f32 " \
        "{%0,%1,%2,%3}, {%4,%5,%6,%7}, {%8,%9}, {%0,%1,%2,%3};" \
        : "+f"((d)[0]), "+f"((d)[1]), "+f"((d)[2]), "+f"((d)[3]) \
        : "r"((a)[0]), "r"((a)[1]), "r"((a)[2]), "r"((a)[3]), "r"(b0), "r"(b1))

// ==================== split fp32 -> bf16 hi/lo ====================
__global__ __launch_bounds__(256)
void split_bf16(const float* __restrict__ in, __nv_bfloat16* __restrict__ hi,
                __nv_bfloat16* __restrict__ lo, int n4)
{
    int i = blockIdx.x * 256 + threadIdx.x;
    if (i >= n4) return;
    float4 v = ((const float4*)in)[i];
    __nv_bfloat16 h0 = __float2bfloat16(v.x);
    __nv_bfloat16 h1 = __float2bfloat16(v.y);
    __nv_bfloat16 h2 = __float2bfloat16(v.z);
    __nv_bfloat16 h3 = __float2bfloat16(v.w);
    __nv_bfloat16 l0 = __float2bfloat16(v.x - __bfloat162float(h0));
    __nv_bfloat16 l1 = __float2bfloat16(v.y - __bfloat162float(h1));
    __nv_bfloat16 l2 = __float2bfloat16(v.z - __bfloat162float(h2));
    __nv_bfloat16 l3 = __float2bfloat16(v.w - __bfloat162float(h3));
    ((__nv_bfloat162*)hi)[i * 2 + 0] = __nv_bfloat162(h0, h1);
    ((__nv_bfloat162*)hi)[i * 2 + 1] = __nv_bfloat162(h2, h3);
    ((__nv_bfloat162*)lo)[i * 2 + 0] = __nv_bfloat162(l0, l1);
    ((__nv_bfloat162*)lo)[i * 2 + 1] = __nv_bfloat162(l2, l3);
}

// ==================== split-bf16 tensor-core GEMM via mma.sync ====================
// C[M,N] = A[M,K]*B[N,K]^T  ~=  Ah*Bh + Ah*Bl + Al*Bh, fp32 accum.
// CTA tile 128x128, 256 thr = 8 warps (4 m x 2 n), per warp 32x64.
// K staged 32, cp.async double buffer. Smem rows padded to 40 halves.
// M%128==0, K%32==0; N ragged allowed.
#define SH 40                        // smem row stride in halves
#define TILE_HB (128 * SH * 2)       // 10240 bytes per tile
#define STG_B   (4 * TILE_HB)        // Ah|Al|Bh|Bl = 40960 bytes
#define GEMM_SMEM (2 * STG_B)

__global__ __launch_bounds__(256, 1)
void gemm_mma(const __nv_bfloat16* __restrict__ Ah, const __nv_bfloat16* __restrict__ Al,
              const __nv_bfloat16* __restrict__ Bh, const __nv_bfloat16* __restrict__ Bl,
              float* __restrict__ C, int M, int N, int K)
{
    extern __shared__ char sm[];
    const uint32_t sb = smem_u32(sm);
    const int tid  = threadIdx.x;
    const int wid  = tid >> 5, lane = tid & 31;
    const int wm   = wid & 3;        // warp row block (32 rows)
    const int wn   = wid >> 2;       // warp col block (64 cols)
    const int bm   = blockIdx.y * 128, bn = blockIdx.x * 128;

    // ---- loader thread mapping: row = tid>>1 (0..127), part = tid&1 (16 halves) ----
    const int lrow = tid >> 1;
    const int lpart = tid & 1;
    const __nv_bfloat16* pAh = Ah + (size_t)(bm + lrow) * K;
    const __nv_bfloat16* pAl = Al + (size_t)(bm + lrow) * K;
    const int brow_raw = bn + lrow;
    const bool bval = brow_raw < N;
    const int brow = bval ? brow_raw : 0;
    const __nv_bfloat16* pBh = Bh + (size_t)brow * K;
    const __nv_bfloat16* pBl = Bl + (size_t)brow * K;
    const uint32_t bsz = bval ? 16u : 0u;
    const uint32_t dofs = (uint32_t)lrow * (SH * 2) + lpart * 32;

    auto issue = [&](int c, int buf) {
        const int ho = c * 32 + lpart * 16;            // half offset into K
        const uint32_t stg = sb + buf * STG_B;
        const char* sAh = (const char*)(pAh + ho);
        const char* sAl = (const char*)(pAl + ho);
        const char* sBh = (const char*)(pBh + ho);
        const char* sBl = (const char*)(pBl + ho);
        uint32_t d0 = stg + 0 * TILE_HB + dofs;
        uint32_t d1 = stg + 1 * TILE_HB + dofs;
        uint32_t d2 = stg + 2 * TILE_HB + dofs;
        uint32_t d3 = stg + 3 * TILE_HB + dofs;
        CPA(d0, sAh);           CPA(d0 + 16, sAh + 16);
        CPA(d1, sAl);           CPA(d1 + 16, sAl + 16);
        CPA_SZ(d2, sBh, bsz);   CPA_SZ(d2 + 16, sBh + 16, bsz);
        CPA_SZ(d3, sBl, bsz);   CPA_SZ(d3 + 16, sBl + 16, bsz);
    };

    float acc[2][8][4];
#pragma unroll
    for (int i = 0; i < 2; i++)
#pragma unroll
        for (int j = 0; j < 8; j++)
#pragma unroll
            for (int q = 0; q < 4; q++) acc[i][j][q] = 0.f;

    // ldmatrix per-lane base indices
    const int arow = wm * 32 + (lane & 15);            // + mi*16
    const int akad = (lane >> 4) * 8;                  // k sub-offset
    const int brow_l = wn * 64 + ((lane >> 4) & 1) * 8 + (lane & 7);   // + gp*16
    const int bkad  = ((lane >> 3) & 1) * 8;

    const int NC = K / 32;
    issue(0, 0); CPA_COMMIT();
    issue(1, 1); CPA_COMMIT();

    for (int c = 0; c < NC; c++) {
        CPA_WAIT1();
        __syncthreads();
        const uint32_t stg = sb + (c & 1) * STG_B;
        const uint32_t aB_h = stg + 0 * TILE_HB;
        const uint32_t aB_l = stg + 1 * TILE_HB;
        const uint32_t bB_h = stg + 2 * TILE_HB;
        const uint32_t bB_l = stg + 3 * TILE_HB;

#pragma unroll
        for (int kh = 0; kh < 2; kh++) {               // two k16 chunks in stage
            const int kofs = kh * 16;
            uint32_t ah[2][4], al[2][4];
#pragma unroll
            for (int mi = 0; mi < 2; mi++) {
                const uint32_t ao = (uint32_t)((arow + mi * 16) * SH + kofs + akad) * 2;
                LDSM_X4(ah[mi][0], ah[mi][1], ah[mi][2], ah[mi][3], aB_h + ao);
                LDSM_X4(al[mi][0], al[mi][1], al[mi][2], al[mi][3], aB_l + ao);
            }
            uint32_t bh[8][2], bl[8][2];
#pragma unroll
            for (int gp = 0; gp < 4; gp++) {
                const uint32_t bo = (uint32_t)((brow_l + gp * 16) * SH + kofs + bkad) * 2;
                LDSM_X4(bh[2*gp][0], bh[2*gp][1], bh[2*gp+1][0], bh[2*gp+1][1], bB_h + bo);
                LDSM_X4(bl[2*gp][0], bl[2*gp][1], bl[2*gp+1][0], bl[2*gp+1][1], bB_l + bo);
            }
#pragma unroll
            for (int mi = 0; mi < 2; mi++)
#pragma unroll
                for (int ni = 0; ni < 8; ni++) {
                    MMA_BF16(acc[mi][ni], ah[mi], bh[ni][0], bh[ni][1]);
                    MMA_BF16(acc[mi][ni], ah[mi], bl[ni][0], bl[ni][1]);
                    MMA_BF16(acc[mi][ni], al[mi], bh[ni][0], bh[ni][1]);
                }
        }
        __syncthreads();
        if (c + 2 < NC) issue(c + 2, c & 1);
        CPA_COMMIT();
    }

    // ---- epilogue: frag (row=lane>>2 / +8, colpair=(lane&3)*2) ----
    const int er = bm + wm * 32 + (lane >> 2);
    const int ec = bn + wn * 64 + (lane & 3) * 2;
#pragma unroll
    for (int mi = 0; mi < 2; mi++) {
#pragma unroll
        for (int ni = 0; ni < 8; ni++) {
            const int cc = ec + ni * 8;
            if (cc < N) {
                const int r0 = er + mi * 16;
                *(float2*)(C + (size_t)r0 * N + cc) =
                    make_float2(acc[mi][ni][0], acc[mi][ni][1]);
                *(float2*)(C + (size_t)(r0 + 8) * N + cc) =
                    make_float2(acc[mi][ni][2], acc[mi][ni][3]);
            }
        }
    }
}

// ==================== elementwise kernels ====================
__global__ __launch_bounds__(256)
void rmsnorm_qa(const float* __restrict__ w)
{
    __shared__ float red[256];
    __shared__ float s_inv;
    const int t = blockIdx.x;
    float* row = g_qa + (size_t)t * Q_LORA;
    float s = 0.f;
    for (int i = threadIdx.x; i < Q_LORA; i += 256) { float v = row[i]; s = fmaf(v, v, s); }
    red[threadIdx.x] = s; __syncthreads();
    for (int st = 128; st > 0; st >>= 1) {
        if (threadIdx.x < st) red[threadIdx.x] += red[threadIdx.x + st];
        __syncthreads();
    }
    if (threadIdx.x == 0) s_inv = rsqrtf(red[0] / (float)Q_LORA + EPS);
    __syncthreads();
    const float inv = s_inv;
    for (int i = threadIdx.x; i < Q_LORA; i += 256) row[i] = row[i] * inv * w[i];
}

__global__ __launch_bounds__(256)
void kv_prep(const float* __restrict__ w, const float* __restrict__ freqs)
{
    __shared__ float red[256];
    __shared__ float s_inv;
    const int t = blockIdx.x;
    const float* row = g_kvf + (size_t)t * KVA_OUT;
    float s = 0.f;
    for (int i = threadIdx.x; i < KV_LORA; i += 256) { float v = row[i]; s = fmaf(v, v, s); }
    red[threadIdx.x] = s; __syncthreads();
    for (int st = 128; st > 0; st >>= 1) {
        if (threadIdx.x < st) red[threadIdx.x] += red[threadIdx.x + st];
        __syncthreads();
    }
    if (threadIdx.x == 0) s_inv = rsqrtf(red[0] / (float)KV_LORA + EPS);
    __syncthreads();
    const float inv = s_inv;
    for (int i = threadIdx.x; i < KV_LORA; i += 256)
        g_ckvn[(size_t)t * KV_LORA + i] = row[i] * inv * w[i];

    if (threadIdx.x < ROPE / 2) {
        int i = threadIdx.x;
        float x1 = row[KV_LORA + 2 * i];
        float x2 = row[KV_LORA + 2 * i + 1];
        float f = freqs[(size_t)t * (ROPE / 2) + i];
        float c = cosf(f), sn = sinf(f);
        g_kpe[(size_t)t * ROPE + 2 * i]     = x1 * c - x2 * sn;
        g_kpe[(size_t)t * ROPE + 2 * i + 1] = x1 * sn + x2 * c;
    }
}

__global__ __launch_bounds__(256)
void assemble(const float* __restrict__ freqs)
{
    const int t = blockIdx.x;
    const int tid = threadIdx.x;
    for (int idx = tid; idx < NH * NOPE; idx += 256) {
        int hh = idx >> 7, d = idx & 127;
        size_t base = ((size_t)hh * T_LEN + t) * QKD;
        g_qh[base + d] = g_q[(size_t)t * NH * QKD + hh * QKD + d];
        g_kh[base + d] = g_kv[(size_t)t * NH * 256 + hh * 256 + d];
        g_v[((size_t)hh * T_LEN + t) * VDIM + d] = g_kv[(size_t)t * NH * 256 + hh * 256 + 128 + d];
    }
    for (int idx = tid; idx < NH * (ROPE / 2); idx += 256) {
        int hh = idx >> 5, i = idx & 31;
        float f = freqs[(size_t)t * (ROPE / 2) + i];
        float c = cosf(f), sn = sinf(f);
        const float* qp = g_q + (size_t)t * NH * QKD + hh * QKD + NOPE;
        float x1 = qp[2 * i], x2 = qp[2 * i + 1];
        size_t base = ((size_t)hh * T_LEN + t) * QKD + NOPE;
        g_qh[base + 2 * i]     = x1 * c - x2 * sn;
        g_qh[base + 2 * i + 1] = x1 * sn + x2 * c;
        g_kh[base + 2 * i]     = g_kpe[(size_t)t * ROPE + 2 * i];
        g_kh[base + 2 * i + 1] = g_kpe[(size_t)t * ROPE + 2 * i + 1];
    }
}

// ==================== attention (unchanged from R3) ====================
#define KSW 193
__global__ __launch_bounds__(256)
void mla_attn2()
{
    extern __shared__ float smf[];
    float* Qs = smf;
    float* Ks = smf + 32 * QKD;
    float* Vs = Ks + 32 * KSW;

    const int h = blockIdx.y;
    const int qb = blockIdx.x * 32;
    const int tid = threadIdx.x;
    const int warp = tid >> 5, lane = tid & 31;

    const float* Qg = g_qh + ((size_t)h * T_LEN + qb) * QKD;
    for (int idx = tid; idx < 32 * QKD / 4; idx += 256)
        ((float4*)Qs)[idx] = ((const float4*)Qg)[idx];

    float m[4], l[4], o[4][4];
#pragma unroll
    for (int j = 0; j < 4; j++) {
        m[j] = -1e30f; l[j] = 0.f;
        o[j][0] = o[j][1] = o[j][2] = o[j][3] = 0.f;
    }

    const float* Kh = g_kh + (size_t)h * T_LEN * QKD;
    const float* Vh = g_v  + (size_t)h * T_LEN * VDIM;
    const int q0i = qb + warp * 4;

    for (int kb = 0; kb <= qb + 31; kb += 32) {
        __syncthreads();
        for (int idx = tid; idx < 32 * 48; idx += 256) {
            int key = idx / 48, d4 = idx % 48;
            float4 v = ((const float4*)(Kh + (size_t)(kb + key) * QKD))[d4];
            float* dst = Ks + key * KSW + d4 * 4;
            dst[0] = v.x; dst[1] = v.y; dst[2] = v.z; dst[3] = v.w;
        }
        for (int idx = tid; idx < 32 * 32; idx += 256)
            ((float4*)Vs)[idx] = ((const float4*)(Vh + (size_t)kb * VDIM))[idx];
        __syncthreads();

        const float* krow = Ks + lane * KSW;
        const float4* q40 = (const float4*)(Qs + (warp * 4 + 0) * QKD);
        const float4* q41 = (const float4*)(Qs + (warp * 4 + 1) * QKD);
        const float4* q42 = (const float4*)(Qs + (warp * 4 + 2) * QKD);
        const float4* q43 = (const float4*)(Qs + (warp * 4 + 3) * QKD);
        float acc[4] = {0.f, 0.f, 0.f, 0.f};
#pragma unroll 8
        for (int d4 = 0; d4 < 48; d4++) {
            float k0v = krow[d4 * 4 + 0];
            float k1v = krow[d4 * 4 + 1];
            float k2v = krow[d4 * 4 + 2];
            float k3v = krow[d4 * 4 + 3];
            float4 a;
            a = q40[d4]; acc[0] = fmaf(a.x,k0v,fmaf(a.y,k1v,fmaf(a.z,k2v,fmaf(a.w,k3v,acc[0]))));
            a = q41[d4]; acc[1] = fmaf(a.x,k0v,fmaf(a.y,k1v,fmaf(a.z,k2v,fmaf(a.w,k3v,acc[1]))));
            a = q42[d4]; acc[2] = fmaf(a.x,k0v,fmaf(a.y,k1v,fmaf(a.z,k2v,fmaf(a.w,k3v,acc[2]))));
            a = q43[d4]; acc[3] = fmaf(a.x,k0v,fmaf(a.y,k1v,fmaf(a.z,k2v,fmaf(a.w,k3v,acc[3]))));
        }

        const int key = kb + lane;
        float p[4];
#pragma unroll
        for (int j = 0; j < 4; j++) {
            float logit = (key <= q0i + j) ? SOFTSCALE * acc[j] : -INFINITY;
            float tmax = logit;
#pragma unroll
            for (int off = 16; off; off >>= 1)
                tmax = fmaxf(tmax, __shfl_xor_sync(0xffffffffu, tmax, off));
            float nm = fmaxf(m[j], tmax);
            float sc = __expf(m[j] - nm);
            p[j] = __expf(logit - nm);
            float ts = p[j];
#pragma unroll
            for (int off = 16; off; off >>= 1)
                ts += __shfl_xor_sync(0xffffffffu, ts, off);
            l[j] = l[j] * sc + ts;
            m[j] = nm;
            o[j][0] *= sc; o[j][1] *= sc; o[j][2] *= sc; o[j][3] *= sc;
        }

#pragma unroll 4
        for (int k = 0; k < 32; k++) {
            float4 vv = ((const float4*)(Vs + k * VDIM))[lane];
#pragma unroll
            for (int j = 0; j < 4; j++) {
                float pk = __shfl_sync(0xffffffffu, p[j], k);
                o[j][0] = fmaf(pk, vv.x, o[j][0]);
                o[j][1] = fmaf(pk, vv.y, o[j][1]);
                o[j][2] = fmaf(pk, vv.z, o[j][2]);
                o[j][3] = fmaf(pk, vv.w, o[j][3]);
            }
        }
    }

#pragma unroll
    for (int j = 0; j < 4; j++) {
        float inv = 1.f / l[j];
        float4 r = make_float4(o[j][0]*inv, o[j][1]*inv, o[j][2]*inv, o[j][3]*inv);
        *(float4*)(g_y + (size_t)(q0i + j) * (NH * VDIM) + h * VDIM + lane * 4) = r;
    }
}

#define ATTN_SMEM ((32 * QKD + 32 * KSW + 32 * VDIM) * 4)

// ==================== launch ====================
extern "C" void kernel_launch(void* const* d_in, const int* in_sizes, int n_in,
                              void* d_out, int out_size)
{
    const float* x        = (const float*)d_in[0];
    const float* freqs    = (const float*)d_in[1];
    const float* wq_a     = (const float*)d_in[3];
    const float* q_norm_w = (const float*)d_in[4];
    const float* wq_b     = (const float*)d_in[5];
    const float* wkv_a    = (const float*)d_in[6];
    const float* kv_norm_w= (const float*)d_in[7];
    const float* wkv_b    = (const float*)d_in[8];
    const float* wo       = (const float*)d_in[9];
    float* out = (float*)d_out;

    float *qa, *q_p, *kvf, *ckvn, *kv_p, *y;
    cudaGetSymbolAddress((void**)&qa,   g_qa);
    cudaGetSymbolAddress((void**)&q_p,  g_q);
    cudaGetSymbolAddress((void**)&kvf,  g_kvf);
    cudaGetSymbolAddress((void**)&ckvn, g_ckvn);
    cudaGetSymbolAddress((void**)&kv_p, g_kv);
    cudaGetSymbolAddress((void**)&y,    g_y);

    __nv_bfloat16 *xh,*xl,*wqah,*wqal,*qah,*qal,*wqbh,*wqbl,*wkvah,*wkval,
                  *ckvnh,*ckvnl,*wkvbh,*wkvbl,*yh,*yl,*woh,*wol;
    cudaGetSymbolAddress((void**)&xh, g_xh);     cudaGetSymbolAddress((void**)&xl, g_xl);
    cudaGetSymbolAddress((void**)&wqah, g_wqah); cudaGetSymbolAddress((void**)&wqal, g_wqal);
    cudaGetSymbolAddress((void**)&qah, g_qah);   cudaGetSymbolAddress((void**)&qal, g_qal);
    cudaGetSymbolAddress((void**)&wqbh, g_wqbh); cudaGetSymbolAddress((void**)&wqbl, g_wqbl);
    cudaGetSymbolAddress((void**)&wkvah, g_wkvah); cudaGetSymbolAddress((void**)&wkval, g_wkval);
    cudaGetSymbolAddress((void**)&ckvnh, g_ckvnh); cudaGetSymbolAddress((void**)&ckvnl, g_ckvnl);
    cudaGetSymbolAddress((void**)&wkvbh, g_wkvbh); cudaGetSymbolAddress((void**)&wkvbl, g_wkvbl);
    cudaGetSymbolAddress((void**)&yh, g_yh);     cudaGetSymbolAddress((void**)&yl, g_yl);
    cudaGetSymbolAddress((void**)&woh, g_woh);   cudaGetSymbolAddress((void**)&wol, g_wol);

    cudaFuncSetAttribute(gemm_mma, cudaFuncAttributeMaxDynamicSharedMemorySize, GEMM_SMEM);
    cudaFuncSetAttribute(mla_attn2, cudaFuncAttributeMaxDynamicSharedMemorySize, ATTN_SMEM);

    dim3 blk(256);
    auto splits = [&](const float* src, __nv_bfloat16* h, __nv_bfloat16* l, size_t n) {
        int n4 = (int)(n / 4);
        split_bf16<<<(n4 + 255) / 256, 256>>>(src, h, l, n4);
    };

    // weight + input splits
    splits(x, xh, xl, (size_t)T_LEN * DIMX);
    splits(wq_a, wqah, wqal, (size_t)Q_LORA * DIMX);
    splits(wq_b, wqbh, wqbl, (size_t)NH * QKD * Q_LORA);
    splits(wkv_a, wkvah, wkval, (size_t)KVA_OUT * DIMX);
    splits(wkv_b, wkvbh, wkvbl, (size_t)4096 * KV_LORA);
    splits(wo, woh, wol, (size_t)DIMX * DIMX);

    // qa = x @ wq_a^T ; rmsnorm ; split
    gemm_mma<<<dim3(Q_LORA / 128, T_LEN / 128), blk, GEMM_SMEM>>>(xh, xl, wqah, wqal, qa, T_LEN, Q_LORA, DIMX);
    rmsnorm_qa<<<T_LEN, blk>>>(q_norm_w);
    splits(qa, qah, qal, (size_t)T_LEN * Q_LORA);
    // q = qa @ wq_b^T
    gemm_mma<<<dim3(NH * QKD / 128, T_LEN / 128), blk, GEMM_SMEM>>>(qah, qal, wqbh, wqbl, q_p, T_LEN, NH * QKD, Q_LORA);
    // kvf = x @ wkv_a^T  (N=576 ragged)
    gemm_mma<<<dim3((KVA_OUT + 127) / 128, T_LEN / 128), blk, GEMM_SMEM>>>(xh, xl, wkvah, wkval, kvf, T_LEN, KVA_OUT, DIMX);
    // rmsnorm(c_kv) + rope(k_pe) ; split
    kv_prep<<<T_LEN, blk>>>(kv_norm_w, freqs);
    splits(ckvn, ckvnh, ckvnl, (size_t)T_LEN * KV_LORA);
    // kv = ckvn @ wkv_b^T
    gemm_mma<<<dim3(4096 / 128, T_LEN / 128), blk, GEMM_SMEM>>>(ckvnh, ckvnl, wkvbh, wkvbl, kv_p, T_LEN, 4096, KV_LORA);
    // assemble + attention
    assemble<<<T_LEN, blk>>>(freqs);
    mla_attn2<<<dim3(T_LEN / 32, NH), blk, ATTN_SMEM>>>();
    // out = y @ wo^T
    splits(y, yh, yl, (size_t)T_LEN * NH * VDIM);
    gemm_mma<<<dim3(DIMX / 128, T_LEN / 128), blk, GEMM_SMEM>>>(yh, yl, woh, wol, out, T_LEN, DIMX, NH * VDIM);
}

// round 8
// speedup vs baseline: 1.6085x; 1.6085x over previous
#include <cuda_runtime.h>
#include <cuda_bf16.h>
#include <math.h>
#include <cstdint>

// Problem constants
#define T_LEN 2048
#define DIMX 2048
#define NH 16
#define NOPE 128
#define ROPE 64
#define VDIM 128
#define QKD 192
#define Q_LORA 768
#define KV_LORA 512
#define KVA_OUT 576
#define SOFTSCALE (-96.0f)
#define EPS 1e-6f

// ==================== scratch ====================
__device__ float g_qa  [(size_t)T_LEN * Q_LORA];
__device__ float g_q   [(size_t)T_LEN * NH * QKD];
__device__ float g_kvf [(size_t)T_LEN * KVA_OUT];
__device__ float g_kpe [(size_t)T_LEN * ROPE];
__device__ float g_kv  [(size_t)T_LEN * NH * (NOPE + VDIM)];
__device__ float g_qh  [(size_t)NH * T_LEN * QKD];
__device__ float g_kh  [(size_t)NH * T_LEN * QKD];
__device__ float g_v   [(size_t)NH * T_LEN * VDIM];

// bf16 split buffers (hi/lo)
__device__ __nv_bfloat16 g_xh [(size_t)T_LEN * DIMX],      g_xl [(size_t)T_LEN * DIMX];
__device__ __nv_bfloat16 g_wqah[(size_t)Q_LORA * DIMX],    g_wqal[(size_t)Q_LORA * DIMX];
__device__ __nv_bfloat16 g_qah[(size_t)T_LEN * Q_LORA],    g_qal[(size_t)T_LEN * Q_LORA];
__device__ __nv_bfloat16 g_wqbh[(size_t)NH * QKD * Q_LORA],g_wqbl[(size_t)NH * QKD * Q_LORA];
__device__ __nv_bfloat16 g_wkvah[(size_t)KVA_OUT * DIMX],  g_wkval[(size_t)KVA_OUT * DIMX];
__device__ __nv_bfloat16 g_ckvnh[(size_t)T_LEN * KV_LORA], g_ckvnl[(size_t)T_LEN * KV_LORA];
__device__ __nv_bfloat16 g_wkvbh[(size_t)4096 * KV_LORA],  g_wkvbl[(size_t)4096 * KV_LORA];
__device__ __nv_bfloat16 g_yh [(size_t)T_LEN * DIMX],      g_yl [(size_t)T_LEN * DIMX];
__device__ __nv_bfloat16 g_woh[(size_t)DIMX * DIMX],       g_wol[(size_t)DIMX * DIMX];

// ==================== PTX helpers (plain sm_103 legal) ====================
__device__ __forceinline__ uint32_t smem_u32(const void* p) {
    uint32_t a;
    asm("{ .reg .u64 t; cvta.to.shared.u64 t, %1; cvt.u32.u64 %0, t; }" : "=r"(a) : "l"(p));
    return a;
}
#define CPA(dst, src) \
    asm volatile("cp.async.cg.shared.global [%0], [%1], 16;" :: "r"(dst), "l"(src))
#define CPA_SZ(dst, src, sz) \
    asm volatile("cp.async.cg.shared.global [%0], [%1], 16, %2;" :: "r"(dst), "l"(src), "r"(sz))
#define CPA_COMMIT() asm volatile("cp.async.commit_group;" ::: "memory")
#define CPA_WAIT1()  asm volatile("cp.async.wait_group 1;" ::: "memory")

#define LDSM_X4(r0, r1, r2, r3, addr) \
    asm volatile("ldmatrix.sync.aligned.m8n8.x4.shared.b16 {%0,%1,%2,%3}, [%4];" \
        : "=r"(r0), "=r"(r1), "=r"(r2), "=r"(r3) : "r"(addr))

#define MMA_BF16(d, a, b0, b1) \
    asm volatile("mma.sync.aligned.m16n8k16.row.col.f32.bf16.bf16.f32 " \
        "{%0,%1,%2,%3}, {%4,%5,%6,%7}, {%8,%9}, {%0,%1,%2,%3};" \
        : "+f"((d)[0]), "+f"((d)[1]), "+f"((d)[2]), "+f"((d)[3]) \
        : "r"((a)[0]), "r"((a)[1]), "r"((a)[2]), "r"((a)[3]), "r"(b0), "r"(b1))

__device__ __forceinline__ void split1(float v, __nv_bfloat16& h, __nv_bfloat16& l) {
    h = __float2bfloat16(v);
    l = __float2bfloat16(v - __bfloat162float(h));
}

// ==================== split fp32 -> bf16 hi/lo (standalone, for weights/x) ====
__global__ __launch_bounds__(256)
void split_bf16(const float* __restrict__ in, __nv_bfloat16* __restrict__ hi,
                __nv_bfloat16* __restrict__ lo, int n4)
{
    int i = blockIdx.x * 256 + threadIdx.x;
    if (i >= n4) return;
    float4 v = ((const float4*)in)[i];
    __nv_bfloat16 h0, h1, h2, h3, l0, l1, l2, l3;
    split1(v.x, h0, l0); split1(v.y, h1, l1);
    split1(v.z, h2, l2); split1(v.w, h3, l3);
    ((__nv_bfloat162*)hi)[i * 2 + 0] = __nv_bfloat162(h0, h1);
    ((__nv_bfloat162*)hi)[i * 2 + 1] = __nv_bfloat162(h2, h3);
    ((__nv_bfloat162*)lo)[i * 2 + 0] = __nv_bfloat162(l0, l1);
    ((__nv_bfloat162*)lo)[i * 2 + 1] = __nv_bfloat162(l2, l3);
}

// ==================== split-bf16 tensor-core GEMM via mma.sync ====================
// C[M,N] = A[M,K]*B[N,K]^T ~= Ah*Bh + Ah*Bl + Al*Bh, fp32 accum.
// CTA 128x128, 8 warps (4m x 2n), warp 32x64. K staged 32, cp.async x2 buffer.
#define SH 40                        // smem row stride in halves
#define TILE_HB (128 * SH * 2)       // bytes per tile
#define STG_B   (4 * TILE_HB)        // Ah|Al|Bh|Bl
#define GEMM_SMEM (2 * STG_B)

__global__ __launch_bounds__(256, 2)
void gemm_mma(const __nv_bfloat16* __restrict__ Ah, const __nv_bfloat16* __restrict__ Al,
              const __nv_bfloat16* __restrict__ Bh, const __nv_bfloat16* __restrict__ Bl,
              float* __restrict__ C, int M, int N, int K)
{
    extern __shared__ char sm[];
    const uint32_t sb = smem_u32(sm);
    const int tid  = threadIdx.x;
    const int wid  = tid >> 5, lane = tid & 31;
    const int wm   = wid & 3;
    const int wn   = wid >> 2;
    const int bm   = blockIdx.y * 128, bn = blockIdx.x * 128;

    const int lrow = tid >> 1;
    const int lpart = tid & 1;
    const __nv_bfloat16* pAh = Ah + (size_t)(bm + lrow) * K;
    const __nv_bfloat16* pAl = Al + (size_t)(bm + lrow) * K;
    const int brow_raw = bn + lrow;
    const bool bval = brow_raw < N;
    const int brow = bval ? brow_raw : 0;
    const __nv_bfloat16* pBh = Bh + (size_t)brow * K;
    const __nv_bfloat16* pBl = Bl + (size_t)brow * K;
    const uint32_t bsz = bval ? 16u : 0u;
    const uint32_t dofs = (uint32_t)lrow * (SH * 2) + lpart * 32;

    auto issue = [&](int c, int buf) {
        const int ho = c * 32 + lpart * 16;
        const uint32_t stg = sb + buf * STG_B;
        const char* sAh = (const char*)(pAh + ho);
        const char* sAl = (const char*)(pAl + ho);
        const char* sBh = (const char*)(pBh + ho);
        const char* sBl = (const char*)(pBl + ho);
        uint32_t d0 = stg + 0 * TILE_HB + dofs;
        uint32_t d1 = stg + 1 * TILE_HB + dofs;
        uint32_t d2 = stg + 2 * TILE_HB + dofs;
        uint32_t d3 = stg + 3 * TILE_HB + dofs;
        CPA(d0, sAh);           CPA(d0 + 16, sAh + 16);
        CPA(d1, sAl);           CPA(d1 + 16, sAl + 16);
        CPA_SZ(d2, sBh, bsz);   CPA_SZ(d2 + 16, sBh + 16, bsz);
        CPA_SZ(d3, sBl, bsz);   CPA_SZ(d3 + 16, sBl + 16, bsz);
    };

    float acc[2][8][4];
#pragma unroll
    for (int i = 0; i < 2; i++)
#pragma unroll
        for (int j = 0; j < 8; j++)
#pragma unroll
            for (int q = 0; q < 4; q++) acc[i][j][q] = 0.f;

    const int arow = wm * 32 + (lane & 15);
    const int akad = (lane >> 4) * 8;
    const int brow_l = wn * 64 + ((lane >> 4) & 1) * 8 + (lane & 7);
    const int bkad  = ((lane >> 3) & 1) * 8;

    const int NC = K / 32;
    issue(0, 0); CPA_COMMIT();
    issue(1, 1); CPA_COMMIT();

    for (int c = 0; c < NC; c++) {
        CPA_WAIT1();
        __syncthreads();
        const uint32_t stg = sb + (c & 1) * STG_B;
        const uint32_t aB_h = stg + 0 * TILE_HB;
        const uint32_t aB_l = stg + 1 * TILE_HB;
        const uint32_t bB_h = stg + 2 * TILE_HB;
        const uint32_t bB_l = stg + 3 * TILE_HB;

#pragma unroll
        for (int kh = 0; kh < 2; kh++) {
            const int kofs = kh * 16;
            uint32_t ah[2][4], al[2][4];
#pragma unroll
            for (int mi = 0; mi < 2; mi++) {
                const uint32_t ao = (uint32_t)((arow + mi * 16) * SH + kofs + akad) * 2;
                LDSM_X4(ah[mi][0], ah[mi][1], ah[mi][2], ah[mi][3], aB_h + ao);
                LDSM_X4(al[mi][0], al[mi][1], al[mi][2], al[mi][3], aB_l + ao);
            }
#pragma unroll
            for (int gp = 0; gp < 4; gp++) {
                uint32_t b0h[2], b1h[2], b0l[2], b1l[2];
                const uint32_t bo = (uint32_t)((brow_l + gp * 16) * SH + kofs + bkad) * 2;
                LDSM_X4(b0h[0], b0h[1], b1h[0], b1h[1], bB_h + bo);
                LDSM_X4(b0l[0], b0l[1], b1l[0], b1l[1], bB_l + bo);
#pragma unroll
                for (int mi = 0; mi < 2; mi++) {
                    MMA_BF16(acc[mi][2*gp],   ah[mi], b0h[0], b0h[1]);
                    MMA_BF16(acc[mi][2*gp],   ah[mi], b0l[0], b0l[1]);
                    MMA_BF16(acc[mi][2*gp],   al[mi], b0h[0], b0h[1]);
                    MMA_BF16(acc[mi][2*gp+1], ah[mi], b1h[0], b1h[1]);
                    MMA_BF16(acc[mi][2*gp+1], ah[mi], b1l[0], b1l[1]);
                    MMA_BF16(acc[mi][2*gp+1], al[mi], b1h[0], b1h[1]);
                }
            }
        }
        __syncthreads();
        if (c + 2 < NC) issue(c + 2, c & 1);
        CPA_COMMIT();
    }

    const int er = bm + wm * 32 + (lane >> 2);
    const int ec = bn + wn * 64 + (lane & 3) * 2;
#pragma unroll
    for (int mi = 0; mi < 2; mi++) {
#pragma unroll
        for (int ni = 0; ni < 8; ni++) {
            const int cc = ec + ni * 8;
            if (cc < N) {
                const int r0 = er + mi * 16;
                *(float2*)(C + (size_t)r0 * N + cc) =
                    make_float2(acc[mi][ni][0], acc[mi][ni][1]);
                *(float2*)(C + (size_t)(r0 + 8) * N + cc) =
                    make_float2(acc[mi][ni][2], acc[mi][ni][3]);
            }
        }
    }
}

// ==================== elementwise (fused hi/lo splits) ====================
__global__ __launch_bounds__(256)
void rmsnorm_split_qa(const float* __restrict__ w)
{
    __shared__ float red[256];
    __shared__ float s_inv;
    const int t = blockIdx.x;
    const float* row = g_qa + (size_t)t * Q_LORA;
    float s = 0.f;
    for (int i = threadIdx.x; i < Q_LORA; i += 256) { float v = row[i]; s = fmaf(v, v, s); }
    red[threadIdx.x] = s; __syncthreads();
    for (int st = 128; st > 0; st >>= 1) {
        if (threadIdx.x < st) red[threadIdx.x] += red[threadIdx.x + st];
        __syncthreads();
    }
    if (threadIdx.x == 0) s_inv = rsqrtf(red[0] / (float)Q_LORA + EPS);
    __syncthreads();
    const float inv = s_inv;
    for (int i = threadIdx.x; i < Q_LORA; i += 256) {
        float v = row[i] * inv * w[i];
        __nv_bfloat16 h, l; split1(v, h, l);
        g_qah[(size_t)t * Q_LORA + i] = h;
        g_qal[(size_t)t * Q_LORA + i] = l;
    }
}

__global__ __launch_bounds__(256)
void kv_prep(const float* __restrict__ w, const float* __restrict__ freqs)
{
    __shared__ float red[256];
    __shared__ float s_inv;
    const int t = blockIdx.x;
    const float* row = g_kvf + (size_t)t * KVA_OUT;
    float s = 0.f;
    for (int i = threadIdx.x; i < KV_LORA; i += 256) { float v = row[i]; s = fmaf(v, v, s); }
    red[threadIdx.x] = s; __syncthreads();
    for (int st = 128; st > 0; st >>= 1) {
        if (threadIdx.x < st) red[threadIdx.x] += red[threadIdx.x + st];
        __syncthreads();
    }
    if (threadIdx.x == 0) s_inv = rsqrtf(red[0] / (float)KV_LORA + EPS);
    __syncthreads();
    const float inv = s_inv;
    for (int i = threadIdx.x; i < KV_LORA; i += 256) {
        float v = row[i] * inv * w[i];
        __nv_bfloat16 h, l; split1(v, h, l);
        g_ckvnh[(size_t)t * KV_LORA + i] = h;
        g_ckvnl[(size_t)t * KV_LORA + i] = l;
    }

    if (threadIdx.x < ROPE / 2) {
        int i = threadIdx.x;
        float x1 = row[KV_LORA + 2 * i];
        float x2 = row[KV_LORA + 2 * i + 1];
        float f = freqs[(size_t)t * (ROPE / 2) + i];
        float c = cosf(f), sn = sinf(f);
        g_kpe[(size_t)t * ROPE + 2 * i]     = x1 * c - x2 * sn;
        g_kpe[(size_t)t * ROPE + 2 * i + 1] = x1 * sn + x2 * c;
    }
}

__global__ __launch_bounds__(256)
void assemble(const float* __restrict__ freqs)
{
    const int t = blockIdx.x;
    const int tid = threadIdx.x;
    for (int idx = tid; idx < NH * NOPE; idx += 256) {
        int hh = idx >> 7, d = idx & 127;
        size_t base = ((size_t)hh * T_LEN + t) * QKD;
        g_qh[base + d] = g_q[(size_t)t * NH * QKD + hh * QKD + d];
        g_kh[base + d] = g_kv[(size_t)t * NH * 256 + hh * 256 + d];
        g_v[((size_t)hh * T_LEN + t) * VDIM + d] = g_kv[(size_t)t * NH * 256 + hh * 256 + 128 + d];
    }
    for (int idx = tid; idx < NH * (ROPE / 2); idx += 256) {
        int hh = idx >> 5, i = idx & 31;
        float f = freqs[(size_t)t * (ROPE / 2) + i];
        float c = cosf(f), sn = sinf(f);
        const float* qp = g_q + (size_t)t * NH * QKD + hh * QKD + NOPE;
        float x1 = qp[2 * i], x2 = qp[2 * i + 1];
        size_t base = ((size_t)hh * T_LEN + t) * QKD + NOPE;
        g_qh[base + 2 * i]     = x1 * c - x2 * sn;
        g_qh[base + 2 * i + 1] = x1 * sn + x2 * c;
        g_kh[base + 2 * i]     = g_kpe[(size_t)t * ROPE + 2 * i];
        g_kh[base + 2 * i + 1] = g_kpe[(size_t)t * ROPE + 2 * i + 1];
    }
}

// ==================== attention (epilogue writes split y) ====================
#define KSW 193
__global__ __launch_bounds__(256)
void mla_attn2()
{
    extern __shared__ float smf[];
    float* Qs = smf;
    float* Ks = smf + 32 * QKD;
    float* Vs = Ks + 32 * KSW;

    const int h = blockIdx.y;
    const int qb = blockIdx.x * 32;
    const int tid = threadIdx.x;
    const int warp = tid >> 5, lane = tid & 31;

    const float* Qg = g_qh + ((size_t)h * T_LEN + qb) * QKD;
    for (int idx = tid; idx < 32 * QKD / 4; idx += 256)
        ((float4*)Qs)[idx] = ((const float4*)Qg)[idx];

    float m[4], l[4], o[4][4];
#pragma unroll
    for (int j = 0; j < 4; j++) {
        m[j] = -1e30f; l[j] = 0.f;
        o[j][0] = o[j][1] = o[j][2] = o[j][3] = 0.f;
    }

    const float* Kh = g_kh + (size_t)h * T_LEN * QKD;
    const float* Vh = g_v  + (size_t)h * T_LEN * VDIM;
    const int q0i = qb + warp * 4;

    for (int kb = 0; kb <= qb + 31; kb += 32) {
        __syncthreads();
        for (int idx = tid; idx < 32 * 48; idx += 256) {
            int key = idx / 48, d4 = idx % 48;
            float4 v = ((const float4*)(Kh + (size_t)(kb + key) * QKD))[d4];
            float* dst = Ks + key * KSW + d4 * 4;
            dst[0] = v.x; dst[1] = v.y; dst[2] = v.z; dst[3] = v.w;
        }
        for (int idx = tid; idx < 32 * 32; idx += 256)
            ((float4*)Vs)[idx] = ((const float4*)(Vh + (size_t)kb * VDIM))[idx];
        __syncthreads();

        const float* krow = Ks + lane * KSW;
        const float4* q40 = (const float4*)(Qs + (warp * 4 + 0) * QKD);
        const float4* q41 = (const float4*)(Qs + (warp * 4 + 1) * QKD);
        const float4* q42 = (const float4*)(Qs + (warp * 4 + 2) * QKD);
        const float4* q43 = (const float4*)(Qs + (warp * 4 + 3) * QKD);
        float acc[4] = {0.f, 0.f, 0.f, 0.f};
#pragma unroll 8
        for (int d4 = 0; d4 < 48; d4++) {
            float k0v = krow[d4 * 4 + 0];
            float k1v = krow[d4 * 4 + 1];
            float k2v = krow[d4 * 4 + 2];
            float k3v = krow[d4 * 4 + 3];
            float4 a;
            a = q40[d4]; acc[0] = fmaf(a.x,k0v,fmaf(a.y,k1v,fmaf(a.z,k2v,fmaf(a.w,k3v,acc[0]))));
            a = q41[d4]; acc[1] = fmaf(a.x,k0v,fmaf(a.y,k1v,fmaf(a.z,k2v,fmaf(a.w,k3v,acc[1]))));
            a = q42[d4]; acc[2] = fmaf(a.x,k0v,fmaf(a.y,k1v,fmaf(a.z,k2v,fmaf(a.w,k3v,acc[2]))));
            a = q43[d4]; acc[3] = fmaf(a.x,k0v,fmaf(a.y,k1v,fmaf(a.z,k2v,fmaf(a.w,k3v,acc[3]))));
        }

        const int key = kb + lane;
        float p[4];
#pragma unroll
        for (int j = 0; j < 4; j++) {
            float logit = (key <= q0i + j) ? SOFTSCALE * acc[j] : -INFINITY;
            float tmax = logit;
#pragma unroll
            for (int off = 16; off; off >>= 1)
                tmax = fmaxf(tmax, __shfl_xor_sync(0xffffffffu, tmax, off));
            float nm = fmaxf(m[j], tmax);
            float sc = __expf(m[j] - nm);
            p[j] = __expf(logit - nm);
            float ts = p[j];
#pragma unroll
            for (int off = 16; off; off >>= 1)
                ts += __shfl_xor_sync(0xffffffffu, ts, off);
            l[j] = l[j] * sc + ts;
            m[j] = nm;
            o[j][0] *= sc; o[j][1] *= sc; o[j][2] *= sc; o[j][3] *= sc;
        }

#pragma unroll 4
        for (int k = 0; k < 32; k++) {
            float4 vv = ((const float4*)(Vs + k * VDIM))[lane];
#pragma unroll
            for (int j = 0; j < 4; j++) {
                float pk = __shfl_sync(0xffffffffu, p[j], k);
                o[j][0] = fmaf(pk, vv.x, o[j][0]);
                o[j][1] = fmaf(pk, vv.y, o[j][1]);
                o[j][2] = fmaf(pk, vv.z, o[j][2]);
                o[j][3] = fmaf(pk, vv.w, o[j][3]);
            }
        }
    }

#pragma unroll
    for (int j = 0; j < 4; j++) {
        float inv = 1.f / l[j];
        const size_t base = (size_t)(q0i + j) * (NH * VDIM) + h * VDIM + lane * 4;
        __nv_bfloat16 h0,h1,h2,h3,l0,l1,l2,l3;
        split1(o[j][0]*inv, h0, l0); split1(o[j][1]*inv, h1, l1);
        split1(o[j][2]*inv, h2, l2); split1(o[j][3]*inv, h3, l3);
        *(__nv_bfloat162*)(g_yh + base)     = __nv_bfloat162(h0, h1);
        *(__nv_bfloat162*)(g_yh + base + 2) = __nv_bfloat162(h2, h3);
        *(__nv_bfloat162*)(g_yl + base)     = __nv_bfloat162(l0, l1);
        *(__nv_bfloat162*)(g_yl + base + 2) = __nv_bfloat162(l2, l3);
    }
}

#define ATTN_SMEM ((32 * QKD + 32 * KSW + 32 * VDIM) * 4)

// ==================== launch ====================
extern "C" void kernel_launch(void* const* d_in, const int* in_sizes, int n_in,
                              void* d_out, int out_size)
{
    const float* x        = (const float*)d_in[0];
    const float* freqs    = (const float*)d_in[1];
    const float* wq_a     = (const float*)d_in[3];
    const float* q_norm_w = (const float*)d_in[4];
    const float* wq_b     = (const float*)d_in[5];
    const float* wkv_a    = (const float*)d_in[6];
    const float* kv_norm_w= (const float*)d_in[7];
    const float* wkv_b    = (const float*)d_in[8];
    const float* wo       = (const float*)d_in[9];
    float* out = (float*)d_out;

    float *qa, *q_p, *kvf, *kv_p;
    cudaGetSymbolAddress((void**)&qa,   g_qa);
    cudaGetSymbolAddress((void**)&q_p,  g_q);
    cudaGetSymbolAddress((void**)&kvf,  g_kvf);
    cudaGetSymbolAddress((void**)&kv_p, g_kv);

    __nv_bfloat16 *xh,*xl,*wqah,*wqal,*qah,*qal,*wqbh,*wqbl,*wkvah,*wkval,
                  *ckvnh,*ckvnl,*wkvbh,*wkvbl,*yh,*yl,*woh,*wol;
    cudaGetSymbolAddress((void**)&xh, g_xh);     cudaGetSymbolAddress((void**)&xl, g_xl);
    cudaGetSymbolAddress((void**)&wqah, g_wqah); cudaGetSymbolAddress((void**)&wqal, g_wqal);
    cudaGetSymbolAddress((void**)&qah, g_qah);   cudaGetSymbolAddress((void**)&qal, g_qal);
    cudaGetSymbolAddress((void**)&wqbh, g_wqbh); cudaGetSymbolAddress((void**)&wqbl, g_wqbl);
    cudaGetSymbolAddress((void**)&wkvah, g_wkvah); cudaGetSymbolAddress((void**)&wkval, g_wkval);
    cudaGetSymbolAddress((void**)&ckvnh, g_ckvnh); cudaGetSymbolAddress((void**)&ckvnl, g_ckvnl);
    cudaGetSymbolAddress((void**)&wkvbh, g_wkvbh); cudaGetSymbolAddress((void**)&wkvbl, g_wkvbl);
    cudaGetSymbolAddress((void**)&yh, g_yh);     cudaGetSymbolAddress((void**)&yl, g_yl);
    cudaGetSymbolAddress((void**)&woh, g_woh);   cudaGetSymbolAddress((void**)&wol, g_wol);

    cudaFuncSetAttribute(gemm_mma, cudaFuncAttributeMaxDynamicSharedMemorySize, GEMM_SMEM);
    cudaFuncSetAttribute(mla_attn2, cudaFuncAttributeMaxDynamicSharedMemorySize, ATTN_SMEM);

    dim3 blk(256);
    auto splits = [&](const float* src, __nv_bfloat16* h, __nv_bfloat16* l, size_t n) {
        int n4 = (int)(n / 4);
        split_bf16<<<(n4 + 255) / 256, 256>>>(src, h, l, n4);
    };

    // #1-3
    splits(x, xh, xl, (size_t)T_LEN * DIMX);
    splits(wq_a, wqah, wqal, (size_t)Q_LORA * DIMX);
    splits(wq_b, wqbh, wqbl, (size_t)NH * QKD * Q_LORA);
    // #4 <- profiled launch
    gemm_mma<<<dim3(Q_LORA / 128, T_LEN / 128), blk, GEMM_SMEM>>>(xh, xl, wqah, wqal, qa, T_LEN, Q_LORA, DIMX);
    // rest
    rmsnorm_split_qa<<<T_LEN, blk>>>(q_norm_w);
    gemm_mma<<<dim3(NH * QKD / 128, T_LEN / 128), blk, GEMM_SMEM>>>(qah, qal, wqbh, wqbl, q_p, T_LEN, NH * QKD, Q_LORA);
    splits(wkv_a, wkvah, wkval, (size_t)KVA_OUT * DIMX);
    gemm_mma<<<dim3((KVA_OUT + 127) / 128, T_LEN / 128), blk, GEMM_SMEM>>>(xh, xl, wkvah, wkval, kvf, T_LEN, KVA_OUT, DIMX);
    kv_prep<<<T_LEN, blk>>>(kv_norm_w, freqs);
    splits(wkv_b, wkvbh, wkvbl, (size_t)4096 * KV_LORA);
    gemm_mma<<<dim3(4096 / 128, T_LEN / 128), blk, GEMM_SMEM>>>(ckvnh, ckvnl, wkvbh, wkvbl, kv_p, T_LEN, 4096, KV_LORA);
    assemble<<<T_LEN, blk>>>(freqs);
    mla_attn2<<<dim3(T_LEN / 32, NH), blk, ATTN_SMEM>>>();
    splits(wo, woh, wol, (size_t)DIMX * DIMX);
    gemm_mma<<<dim3(DIMX / 128, T_LEN / 128), blk, GEMM_SMEM>>>(yh, yl, woh, wol, out, T_LEN, DIMX, NH * VDIM);
}

// round 9
// speedup vs baseline: 2.3448x; 1.4578x over previous
#include <cuda_runtime.h>
#include <cuda_bf16.h>
#include <math.h>
#include <cstdint>

// Problem constants
#define T_LEN 2048
#define DIMX 2048
#define NH 16
#define NOPE 128
#define ROPE 64
#define VDIM 128
#define QKD 192
#define Q_LORA 768
#define KV_LORA 512
#define KVA_OUT 576
#define SOFTSCALE (-96.0f)
#define EPS 1e-6f

// ==================== scratch ====================
__device__ float g_qa  [(size_t)T_LEN * Q_LORA];
__device__ float g_q   [(size_t)T_LEN * NH * QKD];
__device__ float g_kvf [(size_t)T_LEN * KVA_OUT];
__device__ float g_kpe [(size_t)T_LEN * ROPE];
__device__ float g_kv  [(size_t)T_LEN * NH * (NOPE + VDIM)];

// bf16 split buffers (hi/lo)
__device__ __nv_bfloat16 g_xh [(size_t)T_LEN * DIMX],      g_xl [(size_t)T_LEN * DIMX];
__device__ __nv_bfloat16 g_wqah[(size_t)Q_LORA * DIMX],    g_wqal[(size_t)Q_LORA * DIMX];
__device__ __nv_bfloat16 g_qah[(size_t)T_LEN * Q_LORA],    g_qal[(size_t)T_LEN * Q_LORA];
__device__ __nv_bfloat16 g_wqbh[(size_t)NH * QKD * Q_LORA],g_wqbl[(size_t)NH * QKD * Q_LORA];
__device__ __nv_bfloat16 g_wkvah[(size_t)KVA_OUT * DIMX],  g_wkval[(size_t)KVA_OUT * DIMX];
__device__ __nv_bfloat16 g_ckvnh[(size_t)T_LEN * KV_LORA], g_ckvnl[(size_t)T_LEN * KV_LORA];
__device__ __nv_bfloat16 g_wkvbh[(size_t)4096 * KV_LORA],  g_wkvbl[(size_t)4096 * KV_LORA];
__device__ __nv_bfloat16 g_yh [(size_t)T_LEN * DIMX],      g_yl [(size_t)T_LEN * DIMX];
__device__ __nv_bfloat16 g_woh[(size_t)DIMX * DIMX],       g_wol[(size_t)DIMX * DIMX];

// attention bf16 split operands, per-head layout
__device__ __nv_bfloat16 g_aqh[(size_t)NH * T_LEN * QKD], g_aql[(size_t)NH * T_LEN * QKD];
__device__ __nv_bfloat16 g_akh[(size_t)NH * T_LEN * QKD], g_akl[(size_t)NH * T_LEN * QKD];
__device__ __nv_bfloat16 g_avh[(size_t)NH * T_LEN * VDIM], g_avl[(size_t)NH * T_LEN * VDIM];

// ==================== PTX helpers (plain sm_103 legal) ====================
__device__ __forceinline__ uint32_t smem_u32(const void* p) {
    uint32_t a;
    asm("{ .reg .u64 t; cvta.to.shared.u64 t, %1; cvt.u32.u64 %0, t; }" : "=r"(a) : "l"(p));
    return a;
}
#define CPA(dst, src) \
    asm volatile("cp.async.cg.shared.global [%0], [%1], 16;" :: "r"(dst), "l"(src))
#define CPA_SZ(dst, src, sz) \
    asm volatile("cp.async.cg.shared.global [%0], [%1], 16, %2;" :: "r"(dst), "l"(src), "r"(sz))
#define CPA_COMMIT() asm volatile("cp.async.commit_group;" ::: "memory")
#define CPA_WAIT1()  asm volatile("cp.async.wait_group 1;" ::: "memory")
#define CPA_WAIT0()  asm volatile("cp.async.wait_group 0;" ::: "memory")

#define LDSM_X4(r0, r1, r2, r3, addr) \
    asm volatile("ldmatrix.sync.aligned.m8n8.x4.shared.b16 {%0,%1,%2,%3}, [%4];" \
        : "=r"(r0), "=r"(r1), "=r"(r2), "=r"(r3) : "r"(addr))
#define LDSM_X4_T(r0, r1, r2, r3, addr) \
    asm volatile("ldmatrix.sync.aligned.m8n8.x4.trans.shared.b16 {%0,%1,%2,%3}, [%4];" \
        : "=r"(r0), "=r"(r1), "=r"(r2), "=r"(r3) : "r"(addr))

#define MMA_BF16(d, a, b0, b1) \
    asm volatile("mma.sync.aligned.m16n8k16.row.col.f32.bf16.bf16.f32 " \
        "{%0,%1,%2,%3}, {%4,%5,%6,%7}, {%8,%9}, {%0,%1,%2,%3};" \
        : "+f"((d)[0]), "+f"((d)[1]), "+f"((d)[2]), "+f"((d)[3]) \
        : "r"((a)[0]), "r"((a)[1]), "r"((a)[2]), "r"((a)[3]), "r"(b0), "r"(b1))

__device__ __forceinline__ void split1(float v, __nv_bfloat16& h, __nv_bfloat16& l) {
    h = __float2bfloat16(v);
    l = __float2bfloat16(v - __bfloat162float(h));
}
__device__ __forceinline__ void pack2(float x, float y, uint32_t& hi, uint32_t& lo) {
    __nv_bfloat16 hx, lx, hy, ly;
    split1(x, hx, lx); split1(y, hy, ly);
    __nv_bfloat162 H(hx, hy), L(lx, ly);
    hi = *(uint32_t*)&H; lo = *(uint32_t*)&L;
}

// ==================== split fp32 -> bf16 hi/lo ====================
__global__ __launch_bounds__(256)
void split_bf16(const float* __restrict__ in, __nv_bfloat16* __restrict__ hi,
                __nv_bfloat16* __restrict__ lo, int n4)
{
    int i = blockIdx.x * 256 + threadIdx.x;
    if (i >= n4) return;
    float4 v = ((const float4*)in)[i];
    __nv_bfloat16 h0, h1, h2, h3, l0, l1, l2, l3;
    split1(v.x, h0, l0); split1(v.y, h1, l1);
    split1(v.z, h2, l2); split1(v.w, h3, l3);
    ((__nv_bfloat162*)hi)[i * 2 + 0] = __nv_bfloat162(h0, h1);
    ((__nv_bfloat162*)hi)[i * 2 + 1] = __nv_bfloat162(h2, h3);
    ((__nv_bfloat162*)lo)[i * 2 + 0] = __nv_bfloat162(l0, l1);
    ((__nv_bfloat162*)lo)[i * 2 + 1] = __nv_bfloat162(l2, l3);
}

// ==================== split-bf16 tensor-core GEMM via mma.sync ====================
#define SH 40
#define TILE_HB (128 * SH * 2)
#define STG_B   (4 * TILE_HB)
#define GEMM_SMEM (2 * STG_B)

__global__ __launch_bounds__(256, 2)
void gemm_mma(const __nv_bfloat16* __restrict__ Ah, const __nv_bfloat16* __restrict__ Al,
              const __nv_bfloat16* __restrict__ Bh, const __nv_bfloat16* __restrict__ Bl,
              float* __restrict__ C, int M, int N, int K)
{
    extern __shared__ char sm[];
    const uint32_t sb = smem_u32(sm);
    const int tid  = threadIdx.x;
    const int wid  = tid >> 5, lane = tid & 31;
    const int wm   = wid & 3;
    const int wn   = wid >> 2;
    const int bm   = blockIdx.y * 128, bn = blockIdx.x * 128;

    const int lrow = tid >> 1;
    const int lpart = tid & 1;
    const __nv_bfloat16* pAh = Ah + (size_t)(bm + lrow) * K;
    const __nv_bfloat16* pAl = Al + (size_t)(bm + lrow) * K;
    const int brow_raw = bn + lrow;
    const bool bval = brow_raw < N;
    const int brow = bval ? brow_raw : 0;
    const __nv_bfloat16* pBh = Bh + (size_t)brow * K;
    const __nv_bfloat16* pBl = Bl + (size_t)brow * K;
    const uint32_t bsz = bval ? 16u : 0u;
    const uint32_t dofs = (uint32_t)lrow * (SH * 2) + lpart * 32;

    auto issue = [&](int c, int buf) {
        const int ho = c * 32 + lpart * 16;
        const uint32_t stg = sb + buf * STG_B;
        const char* sAh = (const char*)(pAh + ho);
        const char* sAl = (const char*)(pAl + ho);
        const char* sBh = (const char*)(pBh + ho);
        const char* sBl = (const char*)(pBl + ho);
        uint32_t d0 = stg + 0 * TILE_HB + dofs;
        uint32_t d1 = stg + 1 * TILE_HB + dofs;
        uint32_t d2 = stg + 2 * TILE_HB + dofs;
        uint32_t d3 = stg + 3 * TILE_HB + dofs;
        CPA(d0, sAh);           CPA(d0 + 16, sAh + 16);
        CPA(d1, sAl);           CPA(d1 + 16, sAl + 16);
        CPA_SZ(d2, sBh, bsz);   CPA_SZ(d2 + 16, sBh + 16, bsz);
        CPA_SZ(d3, sBl, bsz);   CPA_SZ(d3 + 16, sBl + 16, bsz);
    };

    float acc[2][8][4];
#pragma unroll
    for (int i = 0; i < 2; i++)
#pragma unroll
        for (int j = 0; j < 8; j++)
#pragma unroll
            for (int q = 0; q < 4; q++) acc[i][j][q] = 0.f;

    const int arow = wm * 32 + (lane & 15);
    const int akad = (lane >> 4) * 8;
    const int brow_l = wn * 64 + ((lane >> 4) & 1) * 8 + (lane & 7);
    const int bkad  = ((lane >> 3) & 1) * 8;

    const int NC = K / 32;
    issue(0, 0); CPA_COMMIT();
    issue(1, 1); CPA_COMMIT();

    for (int c = 0; c < NC; c++) {
        CPA_WAIT1();
        __syncthreads();
        const uint32_t stg = sb + (c & 1) * STG_B;
        const uint32_t aB_h = stg + 0 * TILE_HB;
        const uint32_t aB_l = stg + 1 * TILE_HB;
        const uint32_t bB_h = stg + 2 * TILE_HB;
        const uint32_t bB_l = stg + 3 * TILE_HB;

#pragma unroll
        for (int kh = 0; kh < 2; kh++) {
            const int kofs = kh * 16;
            uint32_t ah[2][4], al[2][4];
#pragma unroll
            for (int mi = 0; mi < 2; mi++) {
                const uint32_t ao = (uint32_t)((arow + mi * 16) * SH + kofs + akad) * 2;
                LDSM_X4(ah[mi][0], ah[mi][1], ah[mi][2], ah[mi][3], aB_h + ao);
                LDSM_X4(al[mi][0], al[mi][1], al[mi][2], al[mi][3], aB_l + ao);
            }
#pragma unroll
            for (int gp = 0; gp < 4; gp++) {
                uint32_t b0h[2], b1h[2], b0l[2], b1l[2];
                const uint32_t bo = (uint32_t)((brow_l + gp * 16) * SH + kofs + bkad) * 2;
                LDSM_X4(b0h[0], b0h[1], b1h[0], b1h[1], bB_h + bo);
                LDSM_X4(b0l[0], b0l[1], b1l[0], b1l[1], bB_l + bo);
                // pass-major: accumulator reuse distance 4
                MMA_BF16(acc[0][2*gp],   ah[0], b0h[0], b0h[1]);
                MMA_BF16(acc[0][2*gp+1], ah[0], b1h[0], b1h[1]);
                MMA_BF16(acc[1][2*gp],   ah[1], b0h[0], b0h[1]);
                MMA_BF16(acc[1][2*gp+1], ah[1], b1h[0], b1h[1]);
                MMA_BF16(acc[0][2*gp],   ah[0], b0l[0], b0l[1]);
                MMA_BF16(acc[0][2*gp+1], ah[0], b1l[0], b1l[1]);
                MMA_BF16(acc[1][2*gp],   ah[1], b0l[0], b0l[1]);
                MMA_BF16(acc[1][2*gp+1], ah[1], b1l[0], b1l[1]);
                MMA_BF16(acc[0][2*gp],   al[0], b0h[0], b0h[1]);
                MMA_BF16(acc[0][2*gp+1], al[0], b1h[0], b1h[1]);
                MMA_BF16(acc[1][2*gp],   al[1], b0h[0], b0h[1]);
                MMA_BF16(acc[1][2*gp+1], al[1], b1h[0], b1h[1]);
            }
        }
        __syncthreads();
        if (c + 2 < NC) issue(c + 2, c & 1);
        CPA_COMMIT();
    }

    const int er = bm + wm * 32 + (lane >> 2);
    const int ec = bn + wn * 64 + (lane & 3) * 2;
#pragma unroll
    for (int mi = 0; mi < 2; mi++) {
#pragma unroll
        for (int ni = 0; ni < 8; ni++) {
            const int cc = ec + ni * 8;
            if (cc < N) {
                const int r0 = er + mi * 16;
                *(float2*)(C + (size_t)r0 * N + cc) =
                    make_float2(acc[mi][ni][0], acc[mi][ni][1]);
                *(float2*)(C + (size_t)(r0 + 8) * N + cc) =
                    make_float2(acc[mi][ni][2], acc[mi][ni][3]);
            }
        }
    }
}

// ==================== elementwise (fused hi/lo splits) ====================
__global__ __launch_bounds__(256)
void rmsnorm_split_qa(const float* __restrict__ w)
{
    __shared__ float red[256];
    __shared__ float s_inv;
    const int t = blockIdx.x;
    const float* row = g_qa + (size_t)t * Q_LORA;
    float s = 0.f;
    for (int i = threadIdx.x; i < Q_LORA; i += 256) { float v = row[i]; s = fmaf(v, v, s); }
    red[threadIdx.x] = s; __syncthreads();
    for (int st = 128; st > 0; st >>= 1) {
        if (threadIdx.x < st) red[threadIdx.x] += red[threadIdx.x + st];
        __syncthreads();
    }
    if (threadIdx.x == 0) s_inv = rsqrtf(red[0] / (float)Q_LORA + EPS);
    __syncthreads();
    const float inv = s_inv;
    for (int i = threadIdx.x; i < Q_LORA; i += 256) {
        float v = row[i] * inv * w[i];
        __nv_bfloat16 h, l; split1(v, h, l);
        g_qah[(size_t)t * Q_LORA + i] = h;
        g_qal[(size_t)t * Q_LORA + i] = l;
    }
}

__global__ __launch_bounds__(256)
void kv_prep(const float* __restrict__ w, const float* __restrict__ freqs)
{
    __shared__ float red[256];
    __shared__ float s_inv;
    const int t = blockIdx.x;
    const float* row = g_kvf + (size_t)t * KVA_OUT;
    float s = 0.f;
    for (int i = threadIdx.x; i < KV_LORA; i += 256) { float v = row[i]; s = fmaf(v, v, s); }
    red[threadIdx.x] = s; __syncthreads();
    for (int st = 128; st > 0; st >>= 1) {
        if (threadIdx.x < st) red[threadIdx.x] += red[threadIdx.x + st];
        __syncthreads();
    }
    if (threadIdx.x == 0) s_inv = rsqrtf(red[0] / (float)KV_LORA + EPS);
    __syncthreads();
    const float inv = s_inv;
    for (int i = threadIdx.x; i < KV_LORA; i += 256) {
        float v = row[i] * inv * w[i];
        __nv_bfloat16 h, l; split1(v, h, l);
        g_ckvnh[(size_t)t * KV_LORA + i] = h;
        g_ckvnl[(size_t)t * KV_LORA + i] = l;
    }

    if (threadIdx.x < ROPE / 2) {
        int i = threadIdx.x;
        float x1 = row[KV_LORA + 2 * i];
        float x2 = row[KV_LORA + 2 * i + 1];
        float f = freqs[(size_t)t * (ROPE / 2) + i];
        float c = cosf(f), sn = sinf(f);
        g_kpe[(size_t)t * ROPE + 2 * i]     = x1 * c - x2 * sn;
        g_kpe[(size_t)t * ROPE + 2 * i + 1] = x1 * sn + x2 * c;
    }
}

// assemble per-head split-bf16 Q/K/V for the mma attention
__global__ __launch_bounds__(256)
void assemble(const float* __restrict__ freqs)
{
    const int t = blockIdx.x;
    const int tid = threadIdx.x;
    for (int idx = tid; idx < NH * NOPE; idx += 256) {
        int hh = idx >> 7, d = idx & 127;
        size_t qk = ((size_t)hh * T_LEN + t) * QKD + d;
        __nv_bfloat16 h, l;
        split1(g_q[(size_t)t * NH * QKD + hh * QKD + d], h, l);
        g_aqh[qk] = h; g_aql[qk] = l;
        split1(g_kv[(size_t)t * NH * 256 + hh * 256 + d], h, l);
        g_akh[qk] = h; g_akl[qk] = l;
        size_t vv = ((size_t)hh * T_LEN + t) * VDIM + d;
        split1(g_kv[(size_t)t * NH * 256 + hh * 256 + 128 + d], h, l);
        g_avh[vv] = h; g_avl[vv] = l;
    }
    for (int idx = tid; idx < NH * (ROPE / 2); idx += 256) {
        int hh = idx >> 5, i = idx & 31;
        float f = freqs[(size_t)t * (ROPE / 2) + i];
        float c = cosf(f), sn = sinf(f);
        const float* qp = g_q + (size_t)t * NH * QKD + hh * QKD + NOPE;
        float x1 = qp[2 * i], x2 = qp[2 * i + 1];
        size_t base = ((size_t)hh * T_LEN + t) * QKD + NOPE;
        __nv_bfloat16 h, l;
        split1(x1 * c - x2 * sn, h, l);  g_aqh[base + 2*i] = h;   g_aql[base + 2*i] = l;
        split1(x1 * sn + x2 * c, h, l);  g_aqh[base + 2*i+1] = h; g_aql[base + 2*i+1] = l;
        split1(g_kpe[(size_t)t * ROPE + 2*i], h, l);     g_akh[base + 2*i] = h;   g_akl[base + 2*i] = l;
        split1(g_kpe[(size_t)t * ROPE + 2*i + 1], h, l); g_akh[base + 2*i+1] = h; g_akl[base + 2*i+1] = l;
    }
}

// ==================== tensor-core flash attention ====================
// Block: 1 head x 128 queries; 64-key tiles. 8 warps, warp = 16 query rows.
// QK^T and PV via split-bf16 mma (3 passes each); online softmax in fp32.
#define BQ 128
#define BK 64
#define SQH 200
#define SVH 136
#define ATT_SMEM ((2 * BQ * SQH + 2 * BK * SQH + 2 * BK * SVH) * 2)

__global__ __launch_bounds__(256, 1)
void mla_attn_mma()
{
    extern __shared__ char smraw[];
    const uint32_t sb  = smem_u32(smraw);
    const uint32_t uQh = sb;
    const uint32_t uQl = uQh + BQ * SQH * 2;
    const uint32_t uKh = uQl + BQ * SQH * 2;
    const uint32_t uKl = uKh + BK * SQH * 2;
    const uint32_t uVh = uKl + BK * SQH * 2;
    const uint32_t uVl = uVh + BK * SVH * 2;

    const int h  = blockIdx.x;
    const int qi = (int)gridDim.y - 1 - (int)blockIdx.y;   // heavy blocks first
    const int q0 = qi * BQ;
    const int tid = threadIdx.x, wid = tid >> 5, lane = tid & 31;
    const int mrow = wid * 16;

    const __nv_bfloat16* gQh = g_aqh + ((size_t)h * T_LEN + q0) * QKD;
    const __nv_bfloat16* gQl = g_aql + ((size_t)h * T_LEN + q0) * QKD;
    const __nv_bfloat16* gKh = g_akh + (size_t)h * T_LEN * QKD;
    const __nv_bfloat16* gKl = g_akl + (size_t)h * T_LEN * QKD;
    const __nv_bfloat16* gVh = g_avh + (size_t)h * T_LEN * VDIM;
    const __nv_bfloat16* gVl = g_avl + (size_t)h * T_LEN * VDIM;

    // Q load (once)
    for (int i = tid; i < BQ * 24; i += 256) {
        int r = i / 24, c = i % 24;
        uint32_t d = (uint32_t)(r * SQH + c * 8) * 2;
        CPA(uQh + d, (const char*)(gQh + (size_t)r * QKD + c * 8));
        CPA(uQl + d, (const char*)(gQl + (size_t)r * QKD + c * 8));
    }
    CPA_COMMIT();

    float Oa[16][4];
#pragma unroll
    for (int n = 0; n < 16; n++)
#pragma unroll
        for (int j = 0; j < 4; j++) Oa[n][j] = 0.f;
    float mr0 = -1e30f, mr1 = -1e30f, lr0 = 0.f, lr1 = 0.f;

    // frag lane addressing
    const uint32_t qa_base = uQh + (uint32_t)((mrow + (lane & 15)) * SQH + (lane >> 4) * 8) * 2;
    const uint32_t ql_rel  = BQ * SQH * 2;
    const int kb_row = ((lane >> 4) & 1) * 8 + (lane & 7);
    const int kb_kad = ((lane >> 3) & 1) * 8;
    const int va_row = lane & 15;
    const int va_cad = (lane >> 4) * 8;

    const int nkt = 2 * qi + 2;
    for (int kt = 0; kt < nkt; kt++) {
        // K/V tile load
        for (int i = tid; i < BK * 24; i += 256) {
            int r = i / 24, c = i % 24;
            const size_t go = (size_t)(kt * BK + r) * QKD + c * 8;
            uint32_t d = (uint32_t)(r * SQH + c * 8) * 2;
            CPA(uKh + d, (const char*)(gKh + go));
            CPA(uKl + d, (const char*)(gKl + go));
        }
        for (int i = tid; i < BK * 16; i += 256) {
            int r = i / 16, c = i % 16;
            const size_t go = (size_t)(kt * BK + r) * VDIM + c * 8;
            uint32_t d = (uint32_t)(r * SVH + c * 8) * 2;
            CPA(uVh + d, (const char*)(gVh + go));
            CPA(uVl + d, (const char*)(gVl + go));
        }
        CPA_COMMIT();
        CPA_WAIT0();
        __syncthreads();

        const int kbase = kt * BK;
        const bool active = kbase <= (q0 + mrow + 15);
        if (active) {
            // ---- S = Q @ K^T (split, 3 passes) ----
            float Sa[8][4];
#pragma unroll
            for (int n = 0; n < 8; n++)
#pragma unroll
                for (int j = 0; j < 4; j++) Sa[n][j] = 0.f;

#pragma unroll
            for (int ks = 0; ks < 12; ks++) {
                uint32_t ah[4], al[4];
                const uint32_t qo = qa_base + ks * 32;
                LDSM_X4(ah[0], ah[1], ah[2], ah[3], qo);
                LDSM_X4(al[0], al[1], al[2], al[3], qo + ql_rel);
                uint32_t bh[8][2], bl[8][2];
#pragma unroll
                for (int np = 0; np < 4; np++) {
                    const uint32_t bo = (uint32_t)((np * 16 + kb_row) * SQH + ks * 16 + kb_kad) * 2;
                    LDSM_X4(bh[2*np][0], bh[2*np][1], bh[2*np+1][0], bh[2*np+1][1], uKh + bo);
                    LDSM_X4(bl[2*np][0], bl[2*np][1], bl[2*np+1][0], bl[2*np+1][1], uKl + bo);
                }
#pragma unroll
                for (int n = 0; n < 8; n++) MMA_BF16(Sa[n], ah, bh[n][0], bh[n][1]);
#pragma unroll
                for (int n = 0; n < 8; n++) MMA_BF16(Sa[n], ah, bl[n][0], bl[n][1]);
#pragma unroll
                for (int n = 0; n < 8; n++) MMA_BF16(Sa[n], al, bh[n][0], bh[n][1]);
            }

            // ---- softmax update ----
            const int r0g = q0 + mrow + (lane >> 2);
            const int r1g = r0g + 8;
            const bool needmask = (kbase + BK - 1) > (q0 + mrow);
            float tm0 = -INFINITY, tm1 = -INFINITY;
#pragma unroll
            for (int n = 0; n < 8; n++) {
                const int c0 = kbase + n * 8 + (lane & 3) * 2;
                float v0 = Sa[n][0] * SOFTSCALE, v1 = Sa[n][1] * SOFTSCALE;
                float v2 = Sa[n][2] * SOFTSCALE, v3 = Sa[n][3] * SOFTSCALE;
                if (needmask) {
                    if (c0     > r0g) v0 = -INFINITY;
                    if (c0 + 1 > r0g) v1 = -INFINITY;
                    if (c0     > r1g) v2 = -INFINITY;
                    if (c0 + 1 > r1g) v3 = -INFINITY;
                }
                Sa[n][0] = v0; Sa[n][1] = v1; Sa[n][2] = v2; Sa[n][3] = v3;
                tm0 = fmaxf(tm0, fmaxf(v0, v1));
                tm1 = fmaxf(tm1, fmaxf(v2, v3));
            }
            tm0 = fmaxf(tm0, __shfl_xor_sync(0xffffffffu, tm0, 1));
            tm0 = fmaxf(tm0, __shfl_xor_sync(0xffffffffu, tm0, 2));
            tm1 = fmaxf(tm1, __shfl_xor_sync(0xffffffffu, tm1, 1));
            tm1 = fmaxf(tm1, __shfl_xor_sync(0xffffffffu, tm1, 2));
            const float nm0 = fmaxf(mr0, tm0), nm1 = fmaxf(mr1, tm1);
            const float sc0 = __expf(mr0 - nm0), sc1 = __expf(mr1 - nm1);
            float rs0 = 0.f, rs1 = 0.f;
#pragma unroll
            for (int n = 0; n < 8; n++) {
                Sa[n][0] = __expf(Sa[n][0] - nm0); rs0 += Sa[n][0];
                Sa[n][1] = __expf(Sa[n][1] - nm0); rs0 += Sa[n][1];
                Sa[n][2] = __expf(Sa[n][2] - nm1); rs1 += Sa[n][2];
                Sa[n][3] = __expf(Sa[n][3] - nm1); rs1 += Sa[n][3];
            }
            rs0 += __shfl_xor_sync(0xffffffffu, rs0, 1);
            rs0 += __shfl_xor_sync(0xffffffffu, rs0, 2);
            rs1 += __shfl_xor_sync(0xffffffffu, rs1, 1);
            rs1 += __shfl_xor_sync(0xffffffffu, rs1, 2);
            lr0 = lr0 * sc0 + rs0;
            lr1 = lr1 * sc1 + rs1;
            mr0 = nm0; mr1 = nm1;
#pragma unroll
            for (int n = 0; n < 16; n++) {
                Oa[n][0] *= sc0; Oa[n][1] *= sc0;
                Oa[n][2] *= sc1; Oa[n][3] *= sc1;
            }

            // ---- pack P frags (S acc -> A-operand, hi/lo) ----
            uint32_t ph[4][4], pl[4][4];
#pragma unroll
            for (int kf = 0; kf < 4; kf++) {
                pack2(Sa[2*kf][0],   Sa[2*kf][1],   ph[kf][0], pl[kf][0]);
                pack2(Sa[2*kf][2],   Sa[2*kf][3],   ph[kf][1], pl[kf][1]);
                pack2(Sa[2*kf+1][0], Sa[2*kf+1][1], ph[kf][2], pl[kf][2]);
                pack2(Sa[2*kf+1][2], Sa[2*kf+1][3], ph[kf][3], pl[kf][3]);
            }

            // ---- O += P @ V (split, 3 passes) ----
#pragma unroll
            for (int kf = 0; kf < 4; kf++) {
                uint32_t vbh[16][2], vbl[16][2];
#pragma unroll
                for (int np = 0; np < 8; np++) {
                    const uint32_t vo = (uint32_t)((kf * 16 + va_row) * SVH + np * 16 + va_cad) * 2;
                    LDSM_X4_T(vbh[2*np][0], vbh[2*np][1], vbh[2*np+1][0], vbh[2*np+1][1], uVh + vo);
                    LDSM_X4_T(vbl[2*np][0], vbl[2*np][1], vbl[2*np+1][0], vbl[2*np+1][1], uVl + vo);
                }
#pragma unroll
                for (int n = 0; n < 16; n++) MMA_BF16(Oa[n], ph[kf], vbh[n][0], vbh[n][1]);
#pragma unroll
                for (int n = 0; n < 16; n++) MMA_BF16(Oa[n], ph[kf], vbl[n][0], vbl[n][1]);
#pragma unroll
                for (int n = 0; n < 16; n++) MMA_BF16(Oa[n], pl[kf], vbh[n][0], vbh[n][1]);
            }
        }
        __syncthreads();
    }

    // ---- epilogue: normalize + split-write y ----
    const float inv0 = 1.f / lr0, inv1 = 1.f / lr1;
    const int r0g = q0 + mrow + (lane >> 2);
#pragma unroll
    for (int n = 0; n < 16; n++) {
        const int col = h * VDIM + n * 8 + (lane & 3) * 2;
        __nv_bfloat16 h0, l0, h1, l1;
        split1(Oa[n][0] * inv0, h0, l0);
        split1(Oa[n][1] * inv0, h1, l1);
        *(__nv_bfloat162*)(g_yh + (size_t)r0g * DIMX + col) = __nv_bfloat162(h0, h1);
        *(__nv_bfloat162*)(g_yl + (size_t)r0g * DIMX + col) = __nv_bfloat162(l0, l1);
        split1(Oa[n][2] * inv1, h0, l0);
        split1(Oa[n][3] * inv1, h1, l1);
        *(__nv_bfloat162*)(g_yh + (size_t)(r0g + 8) * DIMX + col) = __nv_bfloat162(h0, h1);
        *(__nv_bfloat162*)(g_yl + (size_t)(r0g + 8) * DIMX + col) = __nv_bfloat162(l0, l1);
    }
}

// ==================== launch ====================
extern "C" void kernel_launch(void* const* d_in, const int* in_sizes, int n_in,
                              void* d_out, int out_size)
{
    const float* x        = (const float*)d_in[0];
    const float* freqs    = (const float*)d_in[1];
    const float* wq_a     = (const float*)d_in[3];
    const float* q_norm_w = (const float*)d_in[4];
    const float* wq_b     = (const float*)d_in[5];
    const float* wkv_a    = (const float*)d_in[6];
    const float* kv_norm_w= (const float*)d_in[7];
    const float* wkv_b    = (const float*)d_in[8];
    const float* wo       = (const float*)d_in[9];
    float* out = (float*)d_out;

    float *qa, *q_p, *kvf, *kv_p;
    cudaGetSymbolAddress((void**)&qa,   g_qa);
    cudaGetSymbolAddress((void**)&q_p,  g_q);
    cudaGetSymbolAddress((void**)&kvf,  g_kvf);
    cudaGetSymbolAddress((void**)&kv_p, g_kv);

    __nv_bfloat16 *xh,*xl,*wqah,*wqal,*qah,*qal,*wqbh,*wqbl,*wkvah,*wkval,
                  *ckvnh,*ckvnl,*wkvbh,*wkvbl,*yh,*yl,*woh,*wol;
    cudaGetSymbolAddress((void**)&xh, g_xh);     cudaGetSymbolAddress((void**)&xl, g_xl);
    cudaGetSymbolAddress((void**)&wqah, g_wqah); cudaGetSymbolAddress((void**)&wqal, g_wqal);
    cudaGetSymbolAddress((void**)&qah, g_qah);   cudaGetSymbolAddress((void**)&qal, g_qal);
    cudaGetSymbolAddress((void**)&wqbh, g_wqbh); cudaGetSymbolAddress((void**)&wqbl, g_wqbl);
    cudaGetSymbolAddress((void**)&wkvah, g_wkvah); cudaGetSymbolAddress((void**)&wkval, g_wkval);
    cudaGetSymbolAddress((void**)&ckvnh, g_ckvnh); cudaGetSymbolAddress((void**)&ckvnl, g_ckvnl);
    cudaGetSymbolAddress((void**)&wkvbh, g_wkvbh); cudaGetSymbolAddress((void**)&wkvbl, g_wkvbl);
    cudaGetSymbolAddress((void**)&yh, g_yh);     cudaGetSymbolAddress((void**)&yl, g_yl);
    cudaGetSymbolAddress((void**)&woh, g_woh);   cudaGetSymbolAddress((void**)&wol, g_wol);

    cudaFuncSetAttribute(gemm_mma, cudaFuncAttributeMaxDynamicSharedMemorySize, GEMM_SMEM);
    cudaFuncSetAttribute(mla_attn_mma, cudaFuncAttributeMaxDynamicSharedMemorySize, ATT_SMEM);

    dim3 blk(256);
    auto splits = [&](const float* src, __nv_bfloat16* h, __nv_bfloat16* l, size_t n) {
        int n4 = (int)(n / 4);
        split_bf16<<<(n4 + 255) / 256, 256>>>(src, h, l, n4);
    };

    // #1-3
    splits(x, xh, xl, (size_t)T_LEN * DIMX);
    splits(wq_a, wqah, wqal, (size_t)Q_LORA * DIMX);
    splits(wq_b, wqbh, wqbl, (size_t)NH * QKD * Q_LORA);
    // #4 <- profiled launch (A/B comparable with R8)
    gemm_mma<<<dim3(Q_LORA / 128, T_LEN / 128), blk, GEMM_SMEM>>>(xh, xl, wqah, wqal, qa, T_LEN, Q_LORA, DIMX);
    rmsnorm_split_qa<<<T_LEN, blk>>>(q_norm_w);
    gemm_mma<<<dim3(NH * QKD / 128, T_LEN / 128), blk, GEMM_SMEM>>>(qah, qal, wqbh, wqbl, q_p, T_LEN, NH * QKD, Q_LORA);
    splits(wkv_a, wkvah, wkval, (size_t)KVA_OUT * DIMX);
    gemm_mma<<<dim3((KVA_OUT + 127) / 128, T_LEN / 128), blk, GEMM_SMEM>>>(xh, xl, wkvah, wkval, kvf, T_LEN, KVA_OUT, DIMX);
    kv_prep<<<T_LEN, blk>>>(kv_norm_w, freqs);
    splits(wkv_b, wkvbh, wkvbl, (size_t)4096 * KV_LORA);
    gemm_mma<<<dim3(4096 / 128, T_LEN / 128), blk, GEMM_SMEM>>>(ckvnh, ckvnl, wkvbh, wkvbl, kv_p, T_LEN, 4096, KV_LORA);
    assemble<<<T_LEN, blk>>>(freqs);
    mla_attn_mma<<<dim3(NH, T_LEN / BQ), blk, ATT_SMEM>>>();
    splits(wo, woh, wol, (size_t)DIMX * DIMX);
    gemm_mma<<<dim3(DIMX / 128, T_LEN / 128), blk, GEMM_SMEM>>>(yh, yl, woh, wol, out, T_LEN, DIMX, NH * VDIM);
}

// round 10
// speedup vs baseline: 3.2000x; 1.3647x over previous
#include <cuda_runtime.h>
#include <cuda_bf16.h>
#include <math.h>
#include <cstdint>

// Problem constants
#define T_LEN 2048
#define DIMX 2048
#define NH 16
#define NOPE 128
#define ROPE 64
#define VDIM 128
#define QKD 192
#define Q_LORA 768
#define KV_LORA 512
#define KVA_OUT 576
#define NAB (Q_LORA + KVA_OUT)   // 1344 fused qa|kvf output cols
#define SOFTSCALE (-96.0f)
#define EPS 1e-6f

// ==================== scratch ====================
__device__ float g_qakvf[(size_t)T_LEN * NAB];     // fused [qa | kvf]
__device__ float g_q   [(size_t)T_LEN * NH * QKD];
__device__ float g_kpe [(size_t)T_LEN * ROPE];
__device__ float g_kv  [(size_t)T_LEN * NH * (NOPE + VDIM)];

// bf16 split buffers (hi/lo)
__device__ __nv_bfloat16 g_xh [(size_t)T_LEN * DIMX],      g_xl [(size_t)T_LEN * DIMX];
__device__ __nv_bfloat16 g_wabh[(size_t)NAB * DIMX],       g_wabl[(size_t)NAB * DIMX];
__device__ __nv_bfloat16 g_qah[(size_t)T_LEN * Q_LORA],    g_qal[(size_t)T_LEN * Q_LORA];
__device__ __nv_bfloat16 g_wqbh[(size_t)NH * QKD * Q_LORA],g_wqbl[(size_t)NH * QKD * Q_LORA];
__device__ __nv_bfloat16 g_ckvnh[(size_t)T_LEN * KV_LORA], g_ckvnl[(size_t)T_LEN * KV_LORA];
__device__ __nv_bfloat16 g_wkvbh[(size_t)4096 * KV_LORA],  g_wkvbl[(size_t)4096 * KV_LORA];
__device__ __nv_bfloat16 g_yh [(size_t)T_LEN * DIMX],      g_yl [(size_t)T_LEN * DIMX];
__device__ __nv_bfloat16 g_woh[(size_t)DIMX * DIMX],       g_wol[(size_t)DIMX * DIMX];

// attention bf16 split operands, per-head layout
__device__ __nv_bfloat16 g_aqh[(size_t)NH * T_LEN * QKD], g_aql[(size_t)NH * T_LEN * QKD];
__device__ __nv_bfloat16 g_akh[(size_t)NH * T_LEN * QKD], g_akl[(size_t)NH * T_LEN * QKD];
__device__ __nv_bfloat16 g_avh[(size_t)NH * T_LEN * VDIM], g_avl[(size_t)NH * T_LEN * VDIM];

// ==================== PTX helpers (plain sm_103 legal) ====================
__device__ __forceinline__ uint32_t smem_u32(const void* p) {
    uint32_t a;
    asm("{ .reg .u64 t; cvta.to.shared.u64 t, %1; cvt.u32.u64 %0, t; }" : "=r"(a) : "l"(p));
    return a;
}
#define CPA(dst, src) \
    asm volatile("cp.async.cg.shared.global [%0], [%1], 16;" :: "r"(dst), "l"(src))
#define CPA_SZ(dst, src, sz) \
    asm volatile("cp.async.cg.shared.global [%0], [%1], 16, %2;" :: "r"(dst), "l"(src), "r"(sz))
#define CPA_COMMIT() asm volatile("cp.async.commit_group;" ::: "memory")
#define CPA_WAIT1()  asm volatile("cp.async.wait_group 1;" ::: "memory")
#define CPA_WAIT0()  asm volatile("cp.async.wait_group 0;" ::: "memory")

#define LDSM_X4(r0, r1, r2, r3, addr) \
    asm volatile("ldmatrix.sync.aligned.m8n8.x4.shared.b16 {%0,%1,%2,%3}, [%4];" \
        : "=r"(r0), "=r"(r1), "=r"(r2), "=r"(r3) : "r"(addr))
#define LDSM_X4_T(r0, r1, r2, r3, addr) \
    asm volatile("ldmatrix.sync.aligned.m8n8.x4.trans.shared.b16 {%0,%1,%2,%3}, [%4];" \
        : "=r"(r0), "=r"(r1), "=r"(r2), "=r"(r3) : "r"(addr))

#define MMA_BF16(d, a, b0, b1) \
    asm volatile("mma.sync.aligned.m16n8k16.row.col.f32.bf16.bf16.f32 " \
        "{%0,%1,%2,%3}, {%4,%5,%6,%7}, {%8,%9}, {%0,%1,%2,%3};" \
        : "+f"((d)[0]), "+f"((d)[1]), "+f"((d)[2]), "+f"((d)[3]) \
        : "r"((a)[0]), "r"((a)[1]), "r"((a)[2]), "r"((a)[3]), "r"(b0), "r"(b1))

__device__ __forceinline__ void split1(float v, __nv_bfloat16& h, __nv_bfloat16& l) {
    h = __float2bfloat16(v);
    l = __float2bfloat16(v - __bfloat162float(h));
}
__device__ __forceinline__ void pack2(float x, float y, uint32_t& hi, uint32_t& lo) {
    __nv_bfloat16 hx, lx, hy, ly;
    split1(x, hx, lx); split1(y, hy, ly);
    __nv_bfloat162 H(hx, hy), L(lx, ly);
    hi = *(uint32_t*)&H; lo = *(uint32_t*)&L;
}

// ==================== split fp32 -> bf16 hi/lo ====================
__global__ __launch_bounds__(256)
void split_bf16(const float* __restrict__ in, __nv_bfloat16* __restrict__ hi,
                __nv_bfloat16* __restrict__ lo, int n4)
{
    int i = blockIdx.x * 256 + threadIdx.x;
    if (i >= n4) return;
    float4 v = ((const float4*)in)[i];
    __nv_bfloat16 h0, h1, h2, h3, l0, l1, l2, l3;
    split1(v.x, h0, l0); split1(v.y, h1, l1);
    split1(v.z, h2, l2); split1(v.w, h3, l3);
    ((__nv_bfloat162*)hi)[i * 2 + 0] = __nv_bfloat162(h0, h1);
    ((__nv_bfloat162*)hi)[i * 2 + 1] = __nv_bfloat162(h2, h3);
    ((__nv_bfloat162*)lo)[i * 2 + 0] = __nv_bfloat162(l0, l1);
    ((__nv_bfloat162*)lo)[i * 2 + 1] = __nv_bfloat162(l2, l3);
}

// ==================== split-bf16 tensor-core GEMM, warp 64x64 ====================
// C[M,N] = A[M,K]*B[N,K]^T ~= Ah*Bh + Ah*Bl + Al*Bh, fp32 accum.
// CTA 128x128, 128 threads = 4 warps (2m x 2n), warp tile 64x64.
// K staged 32 halves, cp.async double buffer. 255-reg budget (1 CTA variant).
#define SH 40
#define TILE_HB (128 * SH * 2)
#define STG_B   (4 * TILE_HB)
#define GEMM_SMEM (2 * STG_B)

__global__ __launch_bounds__(128, 1)
void gemm_mma(const __nv_bfloat16* __restrict__ Ah, const __nv_bfloat16* __restrict__ Al,
              const __nv_bfloat16* __restrict__ Bh, const __nv_bfloat16* __restrict__ Bl,
              float* __restrict__ C, int M, int N, int K)
{
    extern __shared__ char sm[];
    const uint32_t sb = smem_u32(sm);
    const int tid  = threadIdx.x;
    const int wid  = tid >> 5, lane = tid & 31;
    const int wm   = wid & 1;
    const int wn   = wid >> 1;
    const int bm   = blockIdx.y * 128, bn = blockIdx.x * 128;

    // loader: thread = one row of each tile, 4 x 16B parts
    const __nv_bfloat16* pAh = Ah + (size_t)(bm + tid) * K;
    const __nv_bfloat16* pAl = Al + (size_t)(bm + tid) * K;
    const int brow_raw = bn + tid;
    const bool bval = brow_raw < N;
    const int brow = bval ? brow_raw : 0;
    const __nv_bfloat16* pBh = Bh + (size_t)brow * K;
    const __nv_bfloat16* pBl = Bl + (size_t)brow * K;
    const uint32_t bsz = bval ? 16u : 0u;
    const uint32_t dofs = (uint32_t)tid * (SH * 2);

    auto issue = [&](int c, int buf) {
        const int ho = c * 32;
        const uint32_t stg = sb + buf * STG_B;
        const char* sAh = (const char*)(pAh + ho);
        const char* sAl = (const char*)(pAl + ho);
        const char* sBh = (const char*)(pBh + ho);
        const char* sBl = (const char*)(pBl + ho);
        const uint32_t d0 = stg + 0 * TILE_HB + dofs;
        const uint32_t d1 = stg + 1 * TILE_HB + dofs;
        const uint32_t d2 = stg + 2 * TILE_HB + dofs;
        const uint32_t d3 = stg + 3 * TILE_HB + dofs;
#pragma unroll
        for (int p = 0; p < 4; p++) {
            CPA(d0 + p * 16, sAh + p * 16);
            CPA(d1 + p * 16, sAl + p * 16);
            CPA_SZ(d2 + p * 16, sBh + p * 16, bsz);
            CPA_SZ(d3 + p * 16, sBl + p * 16, bsz);
        }
    };

    float acc[4][8][4];
#pragma unroll
    for (int i = 0; i < 4; i++)
#pragma unroll
        for (int j = 0; j < 8; j++)
#pragma unroll
            for (int q = 0; q < 4; q++) acc[i][j][q] = 0.f;

    const int arow = wm * 64 + (lane & 15);
    const int akad = (lane >> 4) * 8;
    const int brow_l = wn * 64 + ((lane >> 4) & 1) * 8 + (lane & 7);
    const int bkad  = ((lane >> 3) & 1) * 8;

    const int NC = K / 32;
    issue(0, 0); CPA_COMMIT();
    issue(1, 1); CPA_COMMIT();

    for (int c = 0; c < NC; c++) {
        CPA_WAIT1();
        __syncthreads();
        const uint32_t stg = sb + (c & 1) * STG_B;
        const uint32_t aB_h = stg + 0 * TILE_HB;
        const uint32_t aB_l = stg + 1 * TILE_HB;
        const uint32_t bB_h = stg + 2 * TILE_HB;
        const uint32_t bB_l = stg + 3 * TILE_HB;

#pragma unroll
        for (int kh = 0; kh < 2; kh++) {
            const int kofs = kh * 16;
            uint32_t ah[4][4], al[4][4];
#pragma unroll
            for (int mi = 0; mi < 4; mi++) {
                const uint32_t ao = (uint32_t)((arow + mi * 16) * SH + kofs + akad) * 2;
                LDSM_X4(ah[mi][0], ah[mi][1], ah[mi][2], ah[mi][3], aB_h + ao);
                LDSM_X4(al[mi][0], al[mi][1], al[mi][2], al[mi][3], aB_l + ao);
            }
            uint32_t bh[4][2][2], bl[4][2][2];
#pragma unroll
            for (int bt = 0; bt < 4; bt++) {
                const uint32_t bo = (uint32_t)((brow_l + bt * 16) * SH + kofs + bkad) * 2;
                LDSM_X4(bh[bt][0][0], bh[bt][0][1], bh[bt][1][0], bh[bt][1][1], bB_h + bo);
                LDSM_X4(bl[bt][0][0], bl[bt][0][1], bl[bt][1][0], bl[bt][1][1], bB_l + bo);
            }
            // pass hh
#pragma unroll
            for (int mi = 0; mi < 4; mi++)
#pragma unroll
                for (int bt = 0; bt < 4; bt++) {
                    MMA_BF16(acc[mi][2*bt],   ah[mi], bh[bt][0][0], bh[bt][0][1]);
                    MMA_BF16(acc[mi][2*bt+1], ah[mi], bh[bt][1][0], bh[bt][1][1]);
                }
            // pass hl
#pragma unroll
            for (int mi = 0; mi < 4; mi++)
#pragma unroll
                for (int bt = 0; bt < 4; bt++) {
                    MMA_BF16(acc[mi][2*bt],   ah[mi], bl[bt][0][0], bl[bt][0][1]);
                    MMA_BF16(acc[mi][2*bt+1], ah[mi], bl[bt][1][0], bl[bt][1][1]);
                }
            // pass lh
#pragma unroll
            for (int mi = 0; mi < 4; mi++)
#pragma unroll
                for (int bt = 0; bt < 4; bt++) {
                    MMA_BF16(acc[mi][2*bt],   al[mi], bh[bt][0][0], bh[bt][0][1]);
                    MMA_BF16(acc[mi][2*bt+1], al[mi], bh[bt][1][0], bh[bt][1][1]);
                }
        }
        __syncthreads();
        if (c + 2 < NC) issue(c + 2, c & 1);
        CPA_COMMIT();
    }

    const int er = bm + wm * 64 + (lane >> 2);
    const int ec = bn + wn * 64 + (lane & 3) * 2;
#pragma unroll
    for (int mi = 0; mi < 4; mi++) {
#pragma unroll
        for (int ni = 0; ni < 8; ni++) {
            const int cc = ec + ni * 8;
            if (cc < N) {
                const int r0 = er + mi * 16;
                *(float2*)(C + (size_t)r0 * N + cc) =
                    make_float2(acc[mi][ni][0], acc[mi][ni][1]);
                *(float2*)(C + (size_t)(r0 + 8) * N + cc) =
                    make_float2(acc[mi][ni][2], acc[mi][ni][3]);
            }
        }
    }
}

// ==================== elementwise (fused hi/lo splits) ====================
__global__ __launch_bounds__(256)
void rmsnorm_split_qa(const float* __restrict__ w)
{
    __shared__ float red[256];
    __shared__ float s_inv;
    const int t = blockIdx.x;
    const float* row = g_qakvf + (size_t)t * NAB;
    float s = 0.f;
    for (int i = threadIdx.x; i < Q_LORA; i += 256) { float v = row[i]; s = fmaf(v, v, s); }
    red[threadIdx.x] = s; __syncthreads();
    for (int st = 128; st > 0; st >>= 1) {
        if (threadIdx.x < st) red[threadIdx.x] += red[threadIdx.x + st];
        __syncthreads();
    }
    if (threadIdx.x == 0) s_inv = rsqrtf(red[0] / (float)Q_LORA + EPS);
    __syncthreads();
    const float inv = s_inv;
    for (int i = threadIdx.x; i < Q_LORA; i += 256) {
        float v = row[i] * inv * w[i];
        __nv_bfloat16 h, l; split1(v, h, l);
        g_qah[(size_t)t * Q_LORA + i] = h;
        g_qal[(size_t)t * Q_LORA + i] = l;
    }
}

__global__ __launch_bounds__(256)
void kv_prep(const float* __restrict__ w, const float* __restrict__ freqs)
{
    __shared__ float red[256];
    __shared__ float s_inv;
    const int t = blockIdx.x;
    const float* row = g_qakvf + (size_t)t * NAB + Q_LORA;
    float s = 0.f;
    for (int i = threadIdx.x; i < KV_LORA; i += 256) { float v = row[i]; s = fmaf(v, v, s); }
    red[threadIdx.x] = s; __syncthreads();
    for (int st = 128; st > 0; st >>= 1) {
        if (threadIdx.x < st) red[threadIdx.x] += red[threadIdx.x + st];
        __syncthreads();
    }
    if (threadIdx.x == 0) s_inv = rsqrtf(red[0] / (float)KV_LORA + EPS);
    __syncthreads();
    const float inv = s_inv;
    for (int i = threadIdx.x; i < KV_LORA; i += 256) {
        float v = row[i] * inv * w[i];
        __nv_bfloat16 h, l; split1(v, h, l);
        g_ckvnh[(size_t)t * KV_LORA + i] = h;
        g_ckvnl[(size_t)t * KV_LORA + i] = l;
    }

    if (threadIdx.x < ROPE / 2) {
        int i = threadIdx.x;
        float x1 = row[KV_LORA + 2 * i];
        float x2 = row[KV_LORA + 2 * i + 1];
        float f = freqs[(size_t)t * (ROPE / 2) + i];
        float c = cosf(f), sn = sinf(f);
        g_kpe[(size_t)t * ROPE + 2 * i]     = x1 * c - x2 * sn;
        g_kpe[(size_t)t * ROPE + 2 * i + 1] = x1 * sn + x2 * c;
    }
}

// assemble per-head split-bf16 Q/K/V for the mma attention
__global__ __launch_bounds__(256)
void assemble(const float* __restrict__ freqs)
{
    const int t = blockIdx.x;
    const int tid = threadIdx.x;
    for (int idx = tid; idx < NH * NOPE; idx += 256) {
        int hh = idx >> 7, d = idx & 127;
        size_t qk = ((size_t)hh * T_LEN + t) * QKD + d;
        __nv_bfloat16 h, l;
        split1(g_q[(size_t)t * NH * QKD + hh * QKD + d], h, l);
        g_aqh[qk] = h; g_aql[qk] = l;
        split1(g_kv[(size_t)t * NH * 256 + hh * 256 + d], h, l);
        g_akh[qk] = h; g_akl[qk] = l;
        size_t vv = ((size_t)hh * T_LEN + t) * VDIM + d;
        split1(g_kv[(size_t)t * NH * 256 + hh * 256 + 128 + d], h, l);
        g_avh[vv] = h; g_avl[vv] = l;
    }
    for (int idx = tid; idx < NH * (ROPE / 2); idx += 256) {
        int hh = idx >> 5, i = idx & 31;
        float f = freqs[(size_t)t * (ROPE / 2) + i];
        float c = cosf(f), sn = sinf(f);
        const float* qp = g_q + (size_t)t * NH * QKD + hh * QKD + NOPE;
        float x1 = qp[2 * i], x2 = qp[2 * i + 1];
        size_t base = ((size_t)hh * T_LEN + t) * QKD + NOPE;
        __nv_bfloat16 h, l;
        split1(x1 * c - x2 * sn, h, l);  g_aqh[base + 2*i] = h;   g_aql[base + 2*i] = l;
        split1(x1 * sn + x2 * c, h, l);  g_aqh[base + 2*i+1] = h; g_aql[base + 2*i+1] = l;
        split1(g_kpe[(size_t)t * ROPE + 2*i], h, l);     g_akh[base + 2*i] = h;   g_akl[base + 2*i] = l;
        split1(g_kpe[(size_t)t * ROPE + 2*i + 1], h, l); g_akh[base + 2*i+1] = h; g_akl[base + 2*i+1] = l;
    }
}

// ==================== tensor-core flash attention ====================
#define BQ 128
#define BK 64
#define SQH 200
#define SVH 136
#define ATT_SMEM ((2 * BQ * SQH + 2 * BK * SQH + 2 * BK * SVH) * 2)

__global__ __launch_bounds__(256, 1)
void mla_attn_mma()
{
    extern __shared__ char smraw[];
    const uint32_t sb  = smem_u32(smraw);
    const uint32_t uQh = sb;
    const uint32_t uQl = uQh + BQ * SQH * 2;
    const uint32_t uKh = uQl + BQ * SQH * 2;
    const uint32_t uKl = uKh + BK * SQH * 2;
    const uint32_t uVh = uKl + BK * SQH * 2;
    const uint32_t uVl = uVh + BK * SVH * 2;

    const int h  = blockIdx.x;
    const int qi = (int)gridDim.y - 1 - (int)blockIdx.y;
    const int q0 = qi * BQ;
    const int tid = threadIdx.x, wid = tid >> 5, lane = tid & 31;
    const int mrow = wid * 16;

    const __nv_bfloat16* gQh = g_aqh + ((size_t)h * T_LEN + q0) * QKD;
    const __nv_bfloat16* gQl = g_aql + ((size_t)h * T_LEN + q0) * QKD;
    const __nv_bfloat16* gKh = g_akh + (size_t)h * T_LEN * QKD;
    const __nv_bfloat16* gKl = g_akl + (size_t)h * T_LEN * QKD;
    const __nv_bfloat16* gVh = g_avh + (size_t)h * T_LEN * VDIM;
    const __nv_bfloat16* gVl = g_avl + (size_t)h * T_LEN * VDIM;

    for (int i = tid; i < BQ * 24; i += 256) {
        int r = i / 24, c = i % 24;
        uint32_t d = (uint32_t)(r * SQH + c * 8) * 2;
        CPA(uQh + d, (const char*)(gQh + (size_t)r * QKD + c * 8));
        CPA(uQl + d, (const char*)(gQl + (size_t)r * QKD + c * 8));
    }
    CPA_COMMIT();

    float Oa[16][4];
#pragma unroll
    for (int n = 0; n < 16; n++)
#pragma unroll
        for (int j = 0; j < 4; j++) Oa[n][j] = 0.f;
    float mr0 = -1e30f, mr1 = -1e30f, lr0 = 0.f, lr1 = 0.f;

    const uint32_t qa_base = uQh + (uint32_t)((mrow + (lane & 15)) * SQH + (lane >> 4) * 8) * 2;
    const uint32_t ql_rel  = BQ * SQH * 2;
    const int kb_row = ((lane >> 4) & 1) * 8 + (lane & 7);
    const int kb_kad = ((lane >> 3) & 1) * 8;
    const int va_row = lane & 15;
    const int va_cad = (lane >> 4) * 8;

    const int nkt = 2 * qi + 2;
    for (int kt = 0; kt < nkt; kt++) {
        for (int i = tid; i < BK * 24; i += 256) {
            int r = i / 24, c = i % 24;
            const size_t go = (size_t)(kt * BK + r) * QKD + c * 8;
            uint32_t d = (uint32_t)(r * SQH + c * 8) * 2;
            CPA(uKh + d, (const char*)(gKh + go));
            CPA(uKl + d, (const char*)(gKl + go));
        }
        for (int i = tid; i < BK * 16; i += 256) {
            int r = i / 16, c = i % 16;
            const size_t go = (size_t)(kt * BK + r) * VDIM + c * 8;
            uint32_t d = (uint32_t)(r * SVH + c * 8) * 2;
            CPA(uVh + d, (const char*)(gVh + go));
            CPA(uVl + d, (const char*)(gVl + go));
        }
        CPA_COMMIT();
        CPA_WAIT0();
        __syncthreads();

        const int kbase = kt * BK;
        const bool active = kbase <= (q0 + mrow + 15);
        if (active) {
            float Sa[8][4];
#pragma unroll
            for (int n = 0; n < 8; n++)
#pragma unroll
                for (int j = 0; j < 4; j++) Sa[n][j] = 0.f;

#pragma unroll
            for (int ks = 0; ks < 12; ks++) {
                uint32_t ah[4], al[4];
                const uint32_t qo = qa_base + ks * 32;
                LDSM_X4(ah[0], ah[1], ah[2], ah[3], qo);
                LDSM_X4(al[0], al[1], al[2], al[3], qo + ql_rel);
                uint32_t bh[8][2], bl[8][2];
#pragma unroll
                for (int np = 0; np < 4; np++) {
                    const uint32_t bo = (uint32_t)((np * 16 + kb_row) * SQH + ks * 16 + kb_kad) * 2;
                    LDSM_X4(bh[2*np][0], bh[2*np][1], bh[2*np+1][0], bh[2*np+1][1], uKh + bo);
                    LDSM_X4(bl[2*np][0], bl[2*np][1], bl[2*np+1][0], bl[2*np+1][1], uKl + bo);
                }
#pragma unroll
                for (int n = 0; n < 8; n++) MMA_BF16(Sa[n], ah, bh[n][0], bh[n][1]);
#pragma unroll
                for (int n = 0; n < 8; n++) MMA_BF16(Sa[n], ah, bl[n][0], bl[n][1]);
#pragma unroll
                for (int n = 0; n < 8; n++) MMA_BF16(Sa[n], al, bh[n][0], bh[n][1]);
            }

            const int r0g = q0 + mrow + (lane >> 2);
            const int r1g = r0g + 8;
            const bool needmask = (kbase + BK - 1) > (q0 + mrow);
            float tm0 = -INFINITY, tm1 = -INFINITY;
#pragma unroll
            for (int n = 0; n < 8; n++) {
                const int c0 = kbase + n * 8 + (lane & 3) * 2;
                float v0 = Sa[n][0] * SOFTSCALE, v1 = Sa[n][1] * SOFTSCALE;
                float v2 = Sa[n][2] * SOFTSCALE, v3 = Sa[n][3] * SOFTSCALE;
                if (needmask) {
                    if (c0     > r0g) v0 = -INFINITY;
                    if (c0 + 1 > r0g) v1 = -INFINITY;
                    if (c0     > r1g) v2 = -INFINITY;
                    if (c0 + 1 > r1g) v3 = -INFINITY;
                }
                Sa[n][0] = v0; Sa[n][1] = v1; Sa[n][2] = v2; Sa[n][3] = v3;
                tm0 = fmaxf(tm0, fmaxf(v0, v1));
                tm1 = fmaxf(tm1, fmaxf(v2, v3));
            }
            tm0 = fmaxf(tm0, __shfl_xor_sync(0xffffffffu, tm0, 1));
            tm0 = fmaxf(tm0, __shfl_xor_sync(0xffffffffu, tm0, 2));
            tm1 = fmaxf(tm1, __shfl_xor_sync(0xffffffffu, tm1, 1));
            tm1 = fmaxf(tm1, __shfl_xor_sync(0xffffffffu, tm1, 2));
            const float nm0 = fmaxf(mr0, tm0), nm1 = fmaxf(mr1, tm1);
            const float sc0 = __expf(mr0 - nm0), sc1 = __expf(mr1 - nm1);
            float rs0 = 0.f, rs1 = 0.f;
#pragma unroll
            for (int n = 0; n < 8; n++) {
                Sa[n][0] = __expf(Sa[n][0] - nm0); rs0 += Sa[n][0];
                Sa[n][1] = __expf(Sa[n][1] - nm0); rs0 += Sa[n][1];
                Sa[n][2] = __expf(Sa[n][2] - nm1); rs1 += Sa[n][2];
                Sa[n][3] = __expf(Sa[n][3] - nm1); rs1 += Sa[n][3];
            }
            rs0 += __shfl_xor_sync(0xffffffffu, rs0, 1);
            rs0 += __shfl_xor_sync(0xffffffffu, rs0, 2);
            rs1 += __shfl_xor_sync(0xffffffffu, rs1, 1);
            rs1 += __shfl_xor_sync(0xffffffffu, rs1, 2);
            lr0 = lr0 * sc0 + rs0;
            lr1 = lr1 * sc1 + rs1;
            mr0 = nm0; mr1 = nm1;
#pragma unroll
            for (int n = 0; n < 16; n++) {
                Oa[n][0] *= sc0; Oa[n][1] *= sc0;
                Oa[n][2] *= sc1; Oa[n][3] *= sc1;
            }

            uint32_t ph[4][4], pl[4][4];
#pragma unroll
            for (int kf = 0; kf < 4; kf++) {
                pack2(Sa[2*kf][0],   Sa[2*kf][1],   ph[kf][0], pl[kf][0]);
                pack2(Sa[2*kf][2],   Sa[2*kf][3],   ph[kf][1], pl[kf][1]);
                pack2(Sa[2*kf+1][0], Sa[2*kf+1][1], ph[kf][2], pl[kf][2]);
                pack2(Sa[2*kf+1][2], Sa[2*kf+1][3], ph[kf][3], pl[kf][3]);
            }

#pragma unroll
            for (int kf = 0; kf < 4; kf++) {
                uint32_t vbh[16][2], vbl[16][2];
#pragma unroll
                for (int np = 0; np < 8; np++) {
                    const uint32_t vo = (uint32_t)((kf * 16 + va_row) * SVH + np * 16 + va_cad) * 2;
                    LDSM_X4_T(vbh[2*np][0], vbh[2*np][1], vbh[2*np+1][0], vbh[2*np+1][1], uVh + vo);
                    LDSM_X4_T(vbl[2*np][0], vbl[2*np][1], vbl[2*np+1][0], vbl[2*np+1][1], uVl + vo);
                }
#pragma unroll
                for (int n = 0; n < 16; n++) MMA_BF16(Oa[n], ph[kf], vbh[n][0], vbh[n][1]);
#pragma unroll
                for (int n = 0; n < 16; n++) MMA_BF16(Oa[n], ph[kf], vbl[n][0], vbl[n][1]);
#pragma unroll
                for (int n = 0; n < 16; n++) MMA_BF16(Oa[n], pl[kf], vbh[n][0], vbh[n][1]);
            }
        }
        __syncthreads();
    }

    const float inv0 = 1.f / lr0, inv1 = 1.f / lr1;
    const int r0g = q0 + mrow + (lane >> 2);
#pragma unroll
    for (int n = 0; n < 16; n++) {
        const int col = h * VDIM + n * 8 + (lane & 3) * 2;
        __nv_bfloat16 h0, l0, h1, l1;
        split1(Oa[n][0] * inv0, h0, l0);
        split1(Oa[n][1] * inv0, h1, l1);
        *(__nv_bfloat162*)(g_yh + (size_t)r0g * DIMX + col) = __nv_bfloat162(h0, h1);
        *(__nv_bfloat162*)(g_yl + (size_t)r0g * DIMX + col) = __nv_bfloat162(l0, l1);
        split1(Oa[n][2] * inv1, h0, l0);
        split1(Oa[n][3] * inv1, h1, l1);
        *(__nv_bfloat162*)(g_yh + (size_t)(r0g + 8) * DIMX + col) = __nv_bfloat162(h0, h1);
        *(__nv_bfloat162*)(g_yl + (size_t)(r0g + 8) * DIMX + col) = __nv_bfloat162(l0, l1);
    }
}

// ==================== launch ====================
extern "C" void kernel_launch(void* const* d_in, const int* in_sizes, int n_in,
                              void* d_out, int out_size)
{
    const float* x        = (const float*)d_in[0];
    const float* freqs    = (const float*)d_in[1];
    const float* wq_a     = (const float*)d_in[3];
    const float* q_norm_w = (const float*)d_in[4];
    const float* wq_b     = (const float*)d_in[5];
    const float* wkv_a    = (const float*)d_in[6];
    const float* kv_norm_w= (const float*)d_in[7];
    const float* wkv_b    = (const float*)d_in[8];
    const float* wo       = (const float*)d_in[9];
    float* out = (float*)d_out;

    float *qakvf, *q_p, *kv_p;
    cudaGetSymbolAddress((void**)&qakvf, g_qakvf);
    cudaGetSymbolAddress((void**)&q_p,   g_q);
    cudaGetSymbolAddress((void**)&kv_p,  g_kv);

    __nv_bfloat16 *xh,*xl,*wabh,*wabl,*qah,*qal,*wqbh,*wqbl,
                  *ckvnh,*ckvnl,*wkvbh,*wkvbl,*yh,*yl,*woh,*wol;
    cudaGetSymbolAddress((void**)&xh, g_xh);     cudaGetSymbolAddress((void**)&xl, g_xl);
    cudaGetSymbolAddress((void**)&wabh, g_wabh); cudaGetSymbolAddress((void**)&wabl, g_wabl);
    cudaGetSymbolAddress((void**)&qah, g_qah);   cudaGetSymbolAddress((void**)&qal, g_qal);
    cudaGetSymbolAddress((void**)&wqbh, g_wqbh); cudaGetSymbolAddress((void**)&wqbl, g_wqbl);
    cudaGetSymbolAddress((void**)&ckvnh, g_ckvnh); cudaGetSymbolAddress((void**)&ckvnl, g_ckvnl);
    cudaGetSymbolAddress((void**)&wkvbh, g_wkvbh); cudaGetSymbolAddress((void**)&wkvbl, g_wkvbl);
    cudaGetSymbolAddress((void**)&yh, g_yh);     cudaGetSymbolAddress((void**)&yl, g_yl);
    cudaGetSymbolAddress((void**)&woh, g_woh);   cudaGetSymbolAddress((void**)&wol, g_wol);

    cudaFuncSetAttribute(gemm_mma, cudaFuncAttributeMaxDynamicSharedMemorySize, GEMM_SMEM);
    cudaFuncSetAttribute(mla_attn_mma, cudaFuncAttributeMaxDynamicSharedMemorySize, ATT_SMEM);

    dim3 blk256(256), blk128(128);
    auto splits = [&](const float* src, __nv_bfloat16* h, __nv_bfloat16* l, size_t n) {
        int n4 = (int)(n / 4);
        split_bf16<<<(n4 + 255) / 256, 256>>>(src, h, l, n4);
    };

    // #1-3: x split + fused [wq_a ; wkv_a] weight split
    splits(x, xh, xl, (size_t)T_LEN * DIMX);
    splits(wq_a, wabh, wabl, (size_t)Q_LORA * DIMX);
    splits(wkv_a, wabh + (size_t)Q_LORA * DIMX, wabl + (size_t)Q_LORA * DIMX,
           (size_t)KVA_OUT * DIMX);
    // #4 <- profiled launch: fused qa|kvf GEMM, N=1344
    gemm_mma<<<dim3((NAB + 127) / 128, T_LEN / 128), blk128, GEMM_SMEM>>>(
        xh, xl, wabh, wabl, qakvf, T_LEN, NAB, DIMX);
    rmsnorm_split_qa<<<T_LEN, blk256>>>(q_norm_w);
    splits(wq_b, wqbh, wqbl, (size_t)NH * QKD * Q_LORA);
    gemm_mma<<<dim3(NH * QKD / 128, T_LEN / 128), blk128, GEMM_SMEM>>>(
        qah, qal, wqbh, wqbl, q_p, T_LEN, NH * QKD, Q_LORA);
    kv_prep<<<T_LEN, blk256>>>(kv_norm_w, freqs);
    splits(wkv_b, wkvbh, wkvbl, (size_t)4096 * KV_LORA);
    gemm_mma<<<dim3(4096 / 128, T_LEN / 128), blk128, GEMM_SMEM>>>(
        ckvnh, ckvnl, wkvbh, wkvbl, kv_p, T_LEN, 4096, KV_LORA);
    assemble<<<T_LEN, blk256>>>(freqs);
    mla_attn_mma<<<dim3(NH, T_LEN / BQ), blk256, ATT_SMEM>>>();
    splits(wo, woh, wol, (size_t)DIMX * DIMX);
    gemm_mma<<<dim3(DIMX / 128, T_LEN / 128), blk128, GEMM_SMEM>>>(
        yh, yl, woh, wol, out, T_LEN, DIMX, NH * VDIM);
}

// round 11
// speedup vs baseline: 3.5026x; 1.0946x over previous
#include <cuda_runtime.h>
#include <cuda_bf16.h>
#include <math.h>
#include <cstdint>

// Problem constants
#define T_LEN 2048
#define DIMX 2048
#define NH 16
#define NOPE 128
#define ROPE 64
#define VDIM 128
#define QKD 192
#define Q_LORA 768
#define KV_LORA 512
#define KVA_OUT 576
#define NAB (Q_LORA + KVA_OUT)   // 1344 fused qa|kvf output cols
#define SOFTSCALE (-96.0f)
#define EPS 1e-6f

// ==================== scratch ====================
__device__ float g_qakvf[(size_t)T_LEN * NAB];     // fused [qa | kvf]
__device__ float g_q   [(size_t)T_LEN * NH * QKD];
__device__ float g_kpe [(size_t)T_LEN * ROPE];
__device__ float g_kv  [(size_t)T_LEN * NH * (NOPE + VDIM)];

// bf16 split buffers (hi/lo)
__device__ __nv_bfloat16 g_xh [(size_t)T_LEN * DIMX],      g_xl [(size_t)T_LEN * DIMX];
__device__ __nv_bfloat16 g_wabh[(size_t)NAB * DIMX],       g_wabl[(size_t)NAB * DIMX];
__device__ __nv_bfloat16 g_qah[(size_t)T_LEN * Q_LORA],    g_qal[(size_t)T_LEN * Q_LORA];
__device__ __nv_bfloat16 g_wqbh[(size_t)NH * QKD * Q_LORA],g_wqbl[(size_t)NH * QKD * Q_LORA];
__device__ __nv_bfloat16 g_ckvnh[(size_t)T_LEN * KV_LORA], g_ckvnl[(size_t)T_LEN * KV_LORA];
__device__ __nv_bfloat16 g_wkvbh[(size_t)4096 * KV_LORA],  g_wkvbl[(size_t)4096 * KV_LORA];
__device__ __nv_bfloat16 g_yh [(size_t)T_LEN * DIMX],      g_yl [(size_t)T_LEN * DIMX];
__device__ __nv_bfloat16 g_woh[(size_t)DIMX * DIMX],       g_wol[(size_t)DIMX * DIMX];

// attention bf16 split operands, per-head layout
__device__ __nv_bfloat16 g_aqh[(size_t)NH * T_LEN * QKD], g_aql[(size_t)NH * T_LEN * QKD];
__device__ __nv_bfloat16 g_akh[(size_t)NH * T_LEN * QKD], g_akl[(size_t)NH * T_LEN * QKD];
__device__ __nv_bfloat16 g_avh[(size_t)NH * T_LEN * VDIM], g_avl[(size_t)NH * T_LEN * VDIM];

// ==================== PTX helpers (plain sm_103 legal) ====================
__device__ __forceinline__ uint32_t smem_u32(const void* p) {
    uint32_t a;
    asm("{ .reg .u64 t; cvta.to.shared.u64 t, %1; cvt.u32.u64 %0, t; }" : "=r"(a) : "l"(p));
    return a;
}
#define CPA(dst, src) \
    asm volatile("cp.async.cg.shared.global [%0], [%1], 16;" :: "r"(dst), "l"(src))
#define CPA_SZ(dst, src, sz) \
    asm volatile("cp.async.cg.shared.global [%0], [%1], 16, %2;" :: "r"(dst), "l"(src), "r"(sz))
#define CPA_COMMIT() asm volatile("cp.async.commit_group;" ::: "memory")
#define CPA_WAIT1()  asm volatile("cp.async.wait_group 1;" ::: "memory")
#define CPA_WAIT0()  asm volatile("cp.async.wait_group 0;" ::: "memory")

#define LDSM_X4(r0, r1, r2, r3, addr) \
    asm volatile("ldmatrix.sync.aligned.m8n8.x4.shared.b16 {%0,%1,%2,%3}, [%4];" \
        : "=r"(r0), "=r"(r1), "=r"(r2), "=r"(r3) : "r"(addr))
#define LDSM_X4_T(r0, r1, r2, r3, addr) \
    asm volatile("ldmatrix.sync.aligned.m8n8.x4.trans.shared.b16 {%0,%1,%2,%3}, [%4];" \
        : "=r"(r0), "=r"(r1), "=r"(r2), "=r"(r3) : "r"(addr))

#define MMA_BF16(d, a, b0, b1) \
    asm volatile("mma.sync.aligned.m16n8k16.row.col.f32.bf16.bf16.f32 " \
        "{%0,%1,%2,%3}, {%4,%5,%6,%7}, {%8,%9}, {%0,%1,%2,%3};" \
        : "+f"((d)[0]), "+f"((d)[1]), "+f"((d)[2]), "+f"((d)[3]) \
        : "r"((a)[0]), "r"((a)[1]), "r"((a)[2]), "r"((a)[3]), "r"(b0), "r"(b1))

__device__ __forceinline__ void split1(float v, __nv_bfloat16& h, __nv_bfloat16& l) {
    h = __float2bfloat16(v);
    l = __float2bfloat16(v - __bfloat162float(h));
}
__device__ __forceinline__ void pack2(float x, float y, uint32_t& hi, uint32_t& lo) {
    __nv_bfloat16 hx, lx, hy, ly;
    split1(x, hx, lx); split1(y, hy, ly);
    __nv_bfloat162 H(hx, hy), L(lx, ly);
    hi = *(uint32_t*)&H; lo = *(uint32_t*)&L;
}

// ==================== split fp32 -> bf16 hi/lo ====================
__global__ __launch_bounds__(256)
void split_bf16(const float* __restrict__ in, __nv_bfloat16* __restrict__ hi,
                __nv_bfloat16* __restrict__ lo, int n4)
{
    int i = blockIdx.x * 256 + threadIdx.x;
    if (i >= n4) return;
    float4 v = ((const float4*)in)[i];
    __nv_bfloat16 h0, h1, h2, h3, l0, l1, l2, l3;
    split1(v.x, h0, l0); split1(v.y, h1, l1);
    split1(v.z, h2, l2); split1(v.w, h3, l3);
    ((__nv_bfloat162*)hi)[i * 2 + 0] = __nv_bfloat162(h0, h1);
    ((__nv_bfloat162*)hi)[i * 2 + 1] = __nv_bfloat162(h2, h3);
    ((__nv_bfloat162*)lo)[i * 2 + 0] = __nv_bfloat162(l0, l1);
    ((__nv_bfloat162*)lo)[i * 2 + 1] = __nv_bfloat162(l2, l3);
}

// ==================== split-bf16 tensor-core GEMM, 8 warps x (64x32) ====================
// C[M,N] = A[M,K]*B[N,K]^T ~= Ah*Bh + Ah*Bl + Al*Bh, fp32 accum.
// CTA 128x128, 256 threads = 8 warps (2m x 4n), warp tile 64x32.
// 2 warps per SMSP -> latency hiding. K staged 32 halves, cp.async x2 buffer.
#define SH 40
#define TILE_HB (128 * SH * 2)
#define STG_B   (4 * TILE_HB)
#define GEMM_SMEM (2 * STG_B)

__global__ __launch_bounds__(256, 1)
void gemm_mma(const __nv_bfloat16* __restrict__ Ah, const __nv_bfloat16* __restrict__ Al,
              const __nv_bfloat16* __restrict__ Bh, const __nv_bfloat16* __restrict__ Bl,
              float* __restrict__ C, int M, int N, int K)
{
    extern __shared__ char sm[];
    const uint32_t sb = smem_u32(sm);
    const int tid  = threadIdx.x;
    const int wid  = tid >> 5, lane = tid & 31;
    const int wm   = wid & 1;        // 2 row groups of 64
    const int wn   = wid >> 1;       // 4 col groups of 32
    const int bm   = blockIdx.y * 128, bn = blockIdx.x * 128;

    // loader: 256 threads, row = tid>>1, part = tid&1 covers 2x16B of 64B row
    const int lrow = tid >> 1;
    const int lpart = tid & 1;
    const __nv_bfloat16* pAh = Ah + (size_t)(bm + lrow) * K;
    const __nv_bfloat16* pAl = Al + (size_t)(bm + lrow) * K;
    const int brow_raw = bn + lrow;
    const bool bval = brow_raw < N;
    const int brow = bval ? brow_raw : 0;
    const __nv_bfloat16* pBh = Bh + (size_t)brow * K;
    const __nv_bfloat16* pBl = Bl + (size_t)brow * K;
    const uint32_t bsz = bval ? 16u : 0u;
    const uint32_t dofs = (uint32_t)lrow * (SH * 2) + lpart * 32;

    auto issue = [&](int c, int buf) {
        const int ho = c * 32 + lpart * 16;
        const uint32_t stg = sb + buf * STG_B;
        const char* sAh = (const char*)(pAh + ho);
        const char* sAl = (const char*)(pAl + ho);
        const char* sBh = (const char*)(pBh + ho);
        const char* sBl = (const char*)(pBl + ho);
        const uint32_t d0 = stg + 0 * TILE_HB + dofs;
        const uint32_t d1 = stg + 1 * TILE_HB + dofs;
        const uint32_t d2 = stg + 2 * TILE_HB + dofs;
        const uint32_t d3 = stg + 3 * TILE_HB + dofs;
        CPA(d0, sAh);           CPA(d0 + 16, sAh + 16);
        CPA(d1, sAl);           CPA(d1 + 16, sAl + 16);
        CPA_SZ(d2, sBh, bsz);   CPA_SZ(d2 + 16, sBh + 16, bsz);
        CPA_SZ(d3, sBl, bsz);   CPA_SZ(d3 + 16, sBl + 16, bsz);
    };

    float acc[4][4][4];   // mi x ni x frag
#pragma unroll
    for (int i = 0; i < 4; i++)
#pragma unroll
        for (int j = 0; j < 4; j++)
#pragma unroll
            for (int q = 0; q < 4; q++) acc[i][j][q] = 0.f;

    const int arow = wm * 64 + (lane & 15);
    const int akad = (lane >> 4) * 8;
    const int brow_l = wn * 32 + ((lane >> 4) & 1) * 8 + (lane & 7);
    const int bkad  = ((lane >> 3) & 1) * 8;

    const int NC = K / 32;
    issue(0, 0); CPA_COMMIT();
    issue(1, 1); CPA_COMMIT();

    for (int c = 0; c < NC; c++) {
        CPA_WAIT1();
        __syncthreads();
        const uint32_t stg = sb + (c & 1) * STG_B;
        const uint32_t aB_h = stg + 0 * TILE_HB;
        const uint32_t aB_l = stg + 1 * TILE_HB;
        const uint32_t bB_h = stg + 2 * TILE_HB;
        const uint32_t bB_l = stg + 3 * TILE_HB;

#pragma unroll
        for (int kh = 0; kh < 2; kh++) {
            const int kofs = kh * 16;
            uint32_t ah[4][4], al[4][4];
#pragma unroll
            for (int mi = 0; mi < 4; mi++) {
                const uint32_t ao = (uint32_t)((arow + mi * 16) * SH + kofs + akad) * 2;
                LDSM_X4(ah[mi][0], ah[mi][1], ah[mi][2], ah[mi][3], aB_h + ao);
                LDSM_X4(al[mi][0], al[mi][1], al[mi][2], al[mi][3], aB_l + ao);
            }
            uint32_t bh[2][2][2], bl[2][2][2];   // bt x n8 x frag
#pragma unroll
            for (int bt = 0; bt < 2; bt++) {
                const uint32_t bo = (uint32_t)((brow_l + bt * 16) * SH + kofs + bkad) * 2;
                LDSM_X4(bh[bt][0][0], bh[bt][0][1], bh[bt][1][0], bh[bt][1][1], bB_h + bo);
                LDSM_X4(bl[bt][0][0], bl[bt][0][1], bl[bt][1][0], bl[bt][1][1], bB_l + bo);
            }
            // pass hh
#pragma unroll
            for (int mi = 0; mi < 4; mi++)
#pragma unroll
                for (int bt = 0; bt < 2; bt++) {
                    MMA_BF16(acc[mi][2*bt],   ah[mi], bh[bt][0][0], bh[bt][0][1]);
                    MMA_BF16(acc[mi][2*bt+1], ah[mi], bh[bt][1][0], bh[bt][1][1]);
                }
            // pass hl
#pragma unroll
            for (int mi = 0; mi < 4; mi++)
#pragma unroll
                for (int bt = 0; bt < 2; bt++) {
                    MMA_BF16(acc[mi][2*bt],   ah[mi], bl[bt][0][0], bl[bt][0][1]);
                    MMA_BF16(acc[mi][2*bt+1], ah[mi], bl[bt][1][0], bl[bt][1][1]);
                }
            // pass lh
#pragma unroll
            for (int mi = 0; mi < 4; mi++)
#pragma unroll
                for (int bt = 0; bt < 2; bt++) {
                    MMA_BF16(acc[mi][2*bt],   al[mi], bh[bt][0][0], bh[bt][0][1]);
                    MMA_BF16(acc[mi][2*bt+1], al[mi], bh[bt][1][0], bh[bt][1][1]);
                }
        }
        __syncthreads();
        if (c + 2 < NC) issue(c + 2, c & 1);
        CPA_COMMIT();
    }

    const int er = bm + wm * 64 + (lane >> 2);
    const int ec = bn + wn * 32 + (lane & 3) * 2;
#pragma unroll
    for (int mi = 0; mi < 4; mi++) {
#pragma unroll
        for (int ni = 0; ni < 4; ni++) {
            const int cc = ec + ni * 8;
            if (cc < N) {
                const int r0 = er + mi * 16;
                *(float2*)(C + (size_t)r0 * N + cc) =
                    make_float2(acc[mi][ni][0], acc[mi][ni][1]);
                *(float2*)(C + (size_t)(r0 + 8) * N + cc) =
                    make_float2(acc[mi][ni][2], acc[mi][ni][3]);
            }
        }
    }
}

// ==================== elementwise (fused hi/lo splits) ====================
__global__ __launch_bounds__(256)
void rmsnorm_split_qa(const float* __restrict__ w)
{
    __shared__ float red[256];
    __shared__ float s_inv;
    const int t = blockIdx.x;
    const float* row = g_qakvf + (size_t)t * NAB;
    float s = 0.f;
    for (int i = threadIdx.x; i < Q_LORA; i += 256) { float v = row[i]; s = fmaf(v, v, s); }
    red[threadIdx.x] = s; __syncthreads();
    for (int st = 128; st > 0; st >>= 1) {
        if (threadIdx.x < st) red[threadIdx.x] += red[threadIdx.x + st];
        __syncthreads();
    }
    if (threadIdx.x == 0) s_inv = rsqrtf(red[0] / (float)Q_LORA + EPS);
    __syncthreads();
    const float inv = s_inv;
    for (int i = threadIdx.x; i < Q_LORA; i += 256) {
        float v = row[i] * inv * w[i];
        __nv_bfloat16 h, l; split1(v, h, l);
        g_qah[(size_t)t * Q_LORA + i] = h;
        g_qal[(size_t)t * Q_LORA + i] = l;
    }
}

__global__ __launch_bounds__(256)
void kv_prep(const float* __restrict__ w, const float* __restrict__ freqs)
{
    __shared__ float red[256];
    __shared__ float s_inv;
    const int t = blockIdx.x;
    const float* row = g_qakvf + (size_t)t * NAB + Q_LORA;
    float s = 0.f;
    for (int i = threadIdx.x; i < KV_LORA; i += 256) { float v = row[i]; s = fmaf(v, v, s); }
    red[threadIdx.x] = s; __syncthreads();
    for (int st = 128; st > 0; st >>= 1) {
        if (threadIdx.x < st) red[threadIdx.x] += red[threadIdx.x + st];
        __syncthreads();
    }
    if (threadIdx.x == 0) s_inv = rsqrtf(red[0] / (float)KV_LORA + EPS);
    __syncthreads();
    const float inv = s_inv;
    for (int i = threadIdx.x; i < KV_LORA; i += 256) {
        float v = row[i] * inv * w[i];
        __nv_bfloat16 h, l; split1(v, h, l);
        g_ckvnh[(size_t)t * KV_LORA + i] = h;
        g_ckvnl[(size_t)t * KV_LORA + i] = l;
    }

    if (threadIdx.x < ROPE / 2) {
        int i = threadIdx.x;
        float x1 = row[KV_LORA + 2 * i];
        float x2 = row[KV_LORA + 2 * i + 1];
        float f = freqs[(size_t)t * (ROPE / 2) + i];
        float c = cosf(f), sn = sinf(f);
        g_kpe[(size_t)t * ROPE + 2 * i]     = x1 * c - x2 * sn;
        g_kpe[(size_t)t * ROPE + 2 * i + 1] = x1 * sn + x2 * c;
    }
}

// assemble per-head split-bf16 Q/K/V for the mma attention
__global__ __launch_bounds__(256)
void assemble(const float* __restrict__ freqs)
{
    const int t = blockIdx.x;
    const int tid = threadIdx.x;
    for (int idx = tid; idx < NH * NOPE; idx += 256) {
        int hh = idx >> 7, d = idx & 127;
        size_t qk = ((size_t)hh * T_LEN + t) * QKD + d;
        __nv_bfloat16 h, l;
        split1(g_q[(size_t)t * NH * QKD + hh * QKD + d], h, l);
        g_aqh[qk] = h; g_aql[qk] = l;
        split1(g_kv[(size_t)t * NH * 256 + hh * 256 + d], h, l);
        g_akh[qk] = h; g_akl[qk] = l;
        size_t vv = ((size_t)hh * T_LEN + t) * VDIM + d;
        split1(g_kv[(size_t)t * NH * 256 + hh * 256 + 128 + d], h, l);
        g_avh[vv] = h; g_avl[vv] = l;
    }
    for (int idx = tid; idx < NH * (ROPE / 2); idx += 256) {
        int hh = idx >> 5, i = idx & 31;
        float f = freqs[(size_t)t * (ROPE / 2) + i];
        float c = cosf(f), sn = sinf(f);
        const float* qp = g_q + (size_t)t * NH * QKD + hh * QKD + NOPE;
        float x1 = qp[2 * i], x2 = qp[2 * i + 1];
        size_t base = ((size_t)hh * T_LEN + t) * QKD + NOPE;
        __nv_bfloat16 h, l;
        split1(x1 * c - x2 * sn, h, l);  g_aqh[base + 2*i] = h;   g_aql[base + 2*i] = l;
        split1(x1 * sn + x2 * c, h, l);  g_aqh[base + 2*i+1] = h; g_aql[base + 2*i+1] = l;
        split1(g_kpe[(size_t)t * ROPE + 2*i], h, l);     g_akh[base + 2*i] = h;   g_akl[base + 2*i] = l;
        split1(g_kpe[(size_t)t * ROPE + 2*i + 1], h, l); g_akh[base + 2*i+1] = h; g_akl[base + 2*i+1] = l;
    }
}

// ==================== tensor-core flash attention ====================
#define BQ 128
#define BK 64
#define SQH 200
#define SVH 136
#define ATT_SMEM ((2 * BQ * SQH + 2 * BK * SQH + 2 * BK * SVH) * 2)

__global__ __launch_bounds__(256, 1)
void mla_attn_mma()
{
    extern __shared__ char smraw[];
    const uint32_t sb  = smem_u32(smraw);
    const uint32_t uQh = sb;
    const uint32_t uQl = uQh + BQ * SQH * 2;
    const uint32_t uKh = uQl + BQ * SQH * 2;
    const uint32_t uKl = uKh + BK * SQH * 2;
    const uint32_t uVh = uKl + BK * SQH * 2;
    const uint32_t uVl = uVh + BK * SVH * 2;

    const int h  = blockIdx.x;
    const int qi = (int)gridDim.y - 1 - (int)blockIdx.y;
    const int q0 = qi * BQ;
    const int tid = threadIdx.x, wid = tid >> 5, lane = tid & 31;
    const int mrow = wid * 16;

    const __nv_bfloat16* gQh = g_aqh + ((size_t)h * T_LEN + q0) * QKD;
    const __nv_bfloat16* gQl = g_aql + ((size_t)h * T_LEN + q0) * QKD;
    const __nv_bfloat16* gKh = g_akh + (size_t)h * T_LEN * QKD;
    const __nv_bfloat16* gKl = g_akl + (size_t)h * T_LEN * QKD;
    const __nv_bfloat16* gVh = g_avh + (size_t)h * T_LEN * VDIM;
    const __nv_bfloat16* gVl = g_avl + (size_t)h * T_LEN * VDIM;

    for (int i = tid; i < BQ * 24; i += 256) {
        int r = i / 24, c = i % 24;
        uint32_t d = (uint32_t)(r * SQH + c * 8) * 2;
        CPA(uQh + d, (const char*)(gQh + (size_t)r * QKD + c * 8));
        CPA(uQl + d, (const char*)(gQl + (size_t)r * QKD + c * 8));
    }
    CPA_COMMIT();

    float Oa[16][4];
#pragma unroll
    for (int n = 0; n < 16; n++)
#pragma unroll
        for (int j = 0; j < 4; j++) Oa[n][j] = 0.f;
    float mr0 = -1e30f, mr1 = -1e30f, lr0 = 0.f, lr1 = 0.f;

    const uint32_t qa_base = uQh + (uint32_t)((mrow + (lane & 15)) * SQH + (lane >> 4) * 8) * 2;
    const uint32_t ql_rel  = BQ * SQH * 2;
    const int kb_row = ((lane >> 4) & 1) * 8 + (lane & 7);
    const int kb_kad = ((lane >> 3) & 1) * 8;
    const int va_row = lane & 15;
    const int va_cad = (lane >> 4) * 8;

    const int nkt = 2 * qi + 2;
    for (int kt = 0; kt < nkt; kt++) {
        for (int i = tid; i < BK * 24; i += 256) {
            int r = i / 24, c = i % 24;
            const size_t go = (size_t)(kt * BK + r) * QKD + c * 8;
            uint32_t d = (uint32_t)(r * SQH + c * 8) * 2;
            CPA(uKh + d, (const char*)(gKh + go));
            CPA(uKl + d, (const char*)(gKl + go));
        }
        for (int i = tid; i < BK * 16; i += 256) {
            int r = i / 16, c = i % 16;
            const size_t go = (size_t)(kt * BK + r) * VDIM + c * 8;
            uint32_t d = (uint32_t)(r * SVH + c * 8) * 2;
            CPA(uVh + d, (const char*)(gVh + go));
            CPA(uVl + d, (const char*)(gVl + go));
        }
        CPA_COMMIT();
        CPA_WAIT0();
        __syncthreads();

        const int kbase = kt * BK;
        const bool active = kbase <= (q0 + mrow + 15);
        if (active) {
            float Sa[8][4];
#pragma unroll
            for (int n = 0; n < 8; n++)
#pragma unroll
                for (int j = 0; j < 4; j++) Sa[n][j] = 0.f;

#pragma unroll
            for (int ks = 0; ks < 12; ks++) {
                uint32_t ah[4], al[4];
                const uint32_t qo = qa_base + ks * 32;
                LDSM_X4(ah[0], ah[1], ah[2], ah[3], qo);
                LDSM_X4(al[0], al[1], al[2], al[3], qo + ql_rel);
                uint32_t bh[8][2], bl[8][2];
#pragma unroll
                for (int np = 0; np < 4; np++) {
                    const uint32_t bo = (uint32_t)((np * 16 + kb_row) * SQH + ks * 16 + kb_kad) * 2;
                    LDSM_X4(bh[2*np][0], bh[2*np][1], bh[2*np+1][0], bh[2*np+1][1], uKh + bo);
                    LDSM_X4(bl[2*np][0], bl[2*np][1], bl[2*np+1][0], bl[2*np+1][1], uKl + bo);
                }
#pragma unroll
                for (int n = 0; n < 8; n++) MMA_BF16(Sa[n], ah, bh[n][0], bh[n][1]);
#pragma unroll
                for (int n = 0; n < 8; n++) MMA_BF16(Sa[n], ah, bl[n][0], bl[n][1]);
#pragma unroll
                for (int n = 0; n < 8; n++) MMA_BF16(Sa[n], al, bh[n][0], bh[n][1]);
            }

            const int r0g = q0 + mrow + (lane >> 2);
            const int r1g = r0g + 8;
            const bool needmask = (kbase + BK - 1) > (q0 + mrow);
            float tm0 = -INFINITY, tm1 = -INFINITY;
#pragma unroll
            for (int n = 0; n < 8; n++) {
                const int c0 = kbase + n * 8 + (lane & 3) * 2;
                float v0 = Sa[n][0] * SOFTSCALE, v1 = Sa[n][1] * SOFTSCALE;
                float v2 = Sa[n][2] * SOFTSCALE, v3 = Sa[n][3] * SOFTSCALE;
                if (needmask) {
                    if (c0     > r0g) v0 = -INFINITY;
                    if (c0 + 1 > r0g) v1 = -INFINITY;
                    if (c0     > r1g) v2 = -INFINITY;
                    if (c0 + 1 > r1g) v3 = -INFINITY;
                }
                Sa[n][0] = v0; Sa[n][1] = v1; Sa[n][2] = v2; Sa[n][3] = v3;
                tm0 = fmaxf(tm0, fmaxf(v0, v1));
                tm1 = fmaxf(tm1, fmaxf(v2, v3));
            }
            tm0 = fmaxf(tm0, __shfl_xor_sync(0xffffffffu, tm0, 1));
            tm0 = fmaxf(tm0, __shfl_xor_sync(0xffffffffu, tm0, 2));
            tm1 = fmaxf(tm1, __shfl_xor_sync(0xffffffffu, tm1, 1));
            tm1 = fmaxf(tm1, __shfl_xor_sync(0xffffffffu, tm1, 2));
            const float nm0 = fmaxf(mr0, tm0), nm1 = fmaxf(mr1, tm1);
            const float sc0 = __expf(mr0 - nm0), sc1 = __expf(mr1 - nm1);
            float rs0 = 0.f, rs1 = 0.f;
#pragma unroll
            for (int n = 0; n < 8; n++) {
                Sa[n][0] = __expf(Sa[n][0] - nm0); rs0 += Sa[n][0];
                Sa[n][1] = __expf(Sa[n][1] - nm0); rs0 += Sa[n][1];
                Sa[n][2] = __expf(Sa[n][2] - nm1); rs1 += Sa[n][2];
                Sa[n][3] = __expf(Sa[n][3] - nm1); rs1 += Sa[n][3];
            }
            rs0 += __shfl_xor_sync(0xffffffffu, rs0, 1);
            rs0 += __shfl_xor_sync(0xffffffffu, rs0, 2);
            rs1 += __shfl_xor_sync(0xffffffffu, rs1, 1);
            rs1 += __shfl_xor_sync(0xffffffffu, rs1, 2);
            lr0 = lr0 * sc0 + rs0;
            lr1 = lr1 * sc1 + rs1;
            mr0 = nm0; mr1 = nm1;
#pragma unroll
            for (int n = 0; n < 16; n++) {
                Oa[n][0] *= sc0; Oa[n][1] *= sc0;
                Oa[n][2] *= sc1; Oa[n][3] *= sc1;
            }

            uint32_t ph[4][4], pl[4][4];
#pragma unroll
            for (int kf = 0; kf < 4; kf++) {
                pack2(Sa[2*kf][0],   Sa[2*kf][1],   ph[kf][0], pl[kf][0]);
                pack2(Sa[2*kf][2],   Sa[2*kf][3],   ph[kf][1], pl[kf][1]);
                pack2(Sa[2*kf+1][0], Sa[2*kf+1][1], ph[kf][2], pl[kf][2]);
                pack2(Sa[2*kf+1][2], Sa[2*kf+1][3], ph[kf][3], pl[kf][3]);
            }

#pragma unroll
            for (int kf = 0; kf < 4; kf++) {
                uint32_t vbh[16][2], vbl[16][2];
#pragma unroll
                for (int np = 0; np < 8; np++) {
                    const uint32_t vo = (uint32_t)((kf * 16 + va_row) * SVH + np * 16 + va_cad) * 2;
                    LDSM_X4_T(vbh[2*np][0], vbh[2*np][1], vbh[2*np+1][0], vbh[2*np+1][1], uVh + vo);
                    LDSM_X4_T(vbl[2*np][0], vbl[2*np][1], vbl[2*np+1][0], vbl[2*np+1][1], uVl + vo);
                }
#pragma unroll
                for (int n = 0; n < 16; n++) MMA_BF16(Oa[n], ph[kf], vbh[n][0], vbh[n][1]);
#pragma unroll
                for (int n = 0; n < 16; n++) MMA_BF16(Oa[n], ph[kf], vbl[n][0], vbl[n][1]);
#pragma unroll
                for (int n = 0; n < 16; n++) MMA_BF16(Oa[n], pl[kf], vbh[n][0], vbh[n][1]);
            }
        }
        __syncthreads();
    }

    const float inv0 = 1.f / lr0, inv1 = 1.f / lr1;
    const int r0g = q0 + mrow + (lane >> 2);
#pragma unroll
    for (int n = 0; n < 16; n++) {
        const int col = h * VDIM + n * 8 + (lane & 3) * 2;
        __nv_bfloat16 h0, l0, h1, l1;
        split1(Oa[n][0] * inv0, h0, l0);
        split1(Oa[n][1] * inv0, h1, l1);
        *(__nv_bfloat162*)(g_yh + (size_t)r0g * DIMX + col) = __nv_bfloat162(h0, h1);
        *(__nv_bfloat162*)(g_yl + (size_t)r0g * DIMX + col) = __nv_bfloat162(l0, l1);
        split1(Oa[n][2] * inv1, h0, l0);
        split1(Oa[n][3] * inv1, h1, l1);
        *(__nv_bfloat162*)(g_yh + (size_t)(r0g + 8) * DIMX + col) = __nv_bfloat162(h0, h1);
        *(__nv_bfloat162*)(g_yl + (size_t)(r0g + 8) * DIMX + col) = __nv_bfloat162(l0, l1);
    }
}

// ==================== launch ====================
extern "C" void kernel_launch(void* const* d_in, const int* in_sizes, int n_in,
                              void* d_out, int out_size)
{
    const float* x        = (const float*)d_in[0];
    const float* freqs    = (const float*)d_in[1];
    const float* wq_a     = (const float*)d_in[3];
    const float* q_norm_w = (const float*)d_in[4];
    const float* wq_b     = (const float*)d_in[5];
    const float* wkv_a    = (const float*)d_in[6];
    const float* kv_norm_w= (const float*)d_in[7];
    const float* wkv_b    = (const float*)d_in[8];
    const float* wo       = (const float*)d_in[9];
    float* out = (float*)d_out;

    float *qakvf, *q_p, *kv_p;
    cudaGetSymbolAddress((void**)&qakvf, g_qakvf);
    cudaGetSymbolAddress((void**)&q_p,   g_q);
    cudaGetSymbolAddress((void**)&kv_p,  g_kv);

    __nv_bfloat16 *xh,*xl,*wabh,*wabl,*qah,*qal,*wqbh,*wqbl,
                  *ckvnh,*ckvnl,*wkvbh,*wkvbl,*yh,*yl,*woh,*wol;
    cudaGetSymbolAddress((void**)&xh, g_xh);     cudaGetSymbolAddress((void**)&xl, g_xl);
    cudaGetSymbolAddress((void**)&wabh, g_wabh); cudaGetSymbolAddress((void**)&wabl, g_wabl);
    cudaGetSymbolAddress((void**)&qah, g_qah);   cudaGetSymbolAddress((void**)&qal, g_qal);
    cudaGetSymbolAddress((void**)&wqbh, g_wqbh); cudaGetSymbolAddress((void**)&wqbl, g_wqbl);
    cudaGetSymbolAddress((void**)&ckvnh, g_ckvnh); cudaGetSymbolAddress((void**)&ckvnl, g_ckvnl);
    cudaGetSymbolAddress((void**)&wkvbh, g_wkvbh); cudaGetSymbolAddress((void**)&wkvbl, g_wkvbl);
    cudaGetSymbolAddress((void**)&yh, g_yh);     cudaGetSymbolAddress((void**)&yl, g_yl);
    cudaGetSymbolAddress((void**)&woh, g_woh);   cudaGetSymbolAddress((void**)&wol, g_wol);

    cudaFuncSetAttribute(gemm_mma, cudaFuncAttributeMaxDynamicSharedMemorySize, GEMM_SMEM);
    cudaFuncSetAttribute(mla_attn_mma, cudaFuncAttributeMaxDynamicSharedMemorySize, ATT_SMEM);

    dim3 blk256(256);
    auto splits = [&](const float* src, __nv_bfloat16* h, __nv_bfloat16* l, size_t n) {
        int n4 = (int)(n / 4);
        split_bf16<<<(n4 + 255) / 256, 256>>>(src, h, l, n4);
    };

    // #1-3: x split + fused [wq_a ; wkv_a] weight split
    splits(x, xh, xl, (size_t)T_LEN * DIMX);
    splits(wq_a, wabh, wabl, (size_t)Q_LORA * DIMX);
    splits(wkv_a, wabh + (size_t)Q_LORA * DIMX, wabl + (size_t)Q_LORA * DIMX,
           (size_t)KVA_OUT * DIMX);
    // #4 <- profiled launch: fused qa|kvf GEMM, N=1344
    gemm_mma<<<dim3((NAB + 127) / 128, T_LEN / 128), blk256, GEMM_SMEM>>>(
        xh, xl, wabh, wabl, qakvf, T_LEN, NAB, DIMX);
    rmsnorm_split_qa<<<T_LEN, blk256>>>(q_norm_w);
    splits(wq_b, wqbh, wqbl, (size_t)NH * QKD * Q_LORA);
    gemm_mma<<<dim3(NH * QKD / 128, T_LEN / 128), blk256, GEMM_SMEM>>>(
        qah, qal, wqbh, wqbl, q_p, T_LEN, NH * QKD, Q_LORA);
    kv_prep<<<T_LEN, blk256>>>(kv_norm_w, freqs);
    splits(wkv_b, wkvbh, wkvbl, (size_t)4096 * KV_LORA);
    gemm_mma<<<dim3(4096 / 128, T_LEN / 128), blk256, GEMM_SMEM>>>(
        ckvnh, ckvnl, wkvbh, wkvbl, kv_p, T_LEN, 4096, KV_LORA);
    assemble<<<T_LEN, blk256>>>(freqs);
    mla_attn_mma<<<dim3(NH, T_LEN / BQ), blk256, ATT_SMEM>>>();
    splits(wo, woh, wol, (size_t)DIMX * DIMX);
    gemm_mma<<<dim3(DIMX / 128, T_LEN / 128), blk256, GEMM_SMEM>>>(
        yh, yl, woh, wol, out, T_LEN, DIMX, NH * VDIM);
}

// round 12
// speedup vs baseline: 3.6860x; 1.0524x over previous
#include <cuda_runtime.h>
#include <cuda_bf16.h>
#include <math.h>
#include <cstdint>

// Problem constants
#define T_LEN 2048
#define DIMX 2048
#define NH 16
#define NOPE 128
#define ROPE 64
#define VDIM 128
#define QKD 192
#define Q_LORA 768
#define KV_LORA 512
#define KVA_OUT 576
#define NAB (Q_LORA + KVA_OUT)   // 1344 fused qa|kvf output cols
#define SOFTSCALE (-96.0f)
#define EPS 1e-6f

// ==================== scratch ====================
__device__ float g_qakvf[(size_t)T_LEN * NAB];     // fused [qa | kvf]
__device__ float g_q   [(size_t)T_LEN * NH * QKD];
__device__ float g_kpe [(size_t)T_LEN * ROPE];
__device__ float g_kv  [(size_t)T_LEN * NH * (NOPE + VDIM)];

// bf16 split buffers (hi/lo)
__device__ __nv_bfloat16 g_xh [(size_t)T_LEN * DIMX],      g_xl [(size_t)T_LEN * DIMX];
__device__ __nv_bfloat16 g_wabh[(size_t)NAB * DIMX],       g_wabl[(size_t)NAB * DIMX];
__device__ __nv_bfloat16 g_qah[(size_t)T_LEN * Q_LORA],    g_qal[(size_t)T_LEN * Q_LORA];
__device__ __nv_bfloat16 g_wqbh[(size_t)NH * QKD * Q_LORA],g_wqbl[(size_t)NH * QKD * Q_LORA];
__device__ __nv_bfloat16 g_ckvnh[(size_t)T_LEN * KV_LORA], g_ckvnl[(size_t)T_LEN * KV_LORA];
__device__ __nv_bfloat16 g_wkvbh[(size_t)4096 * KV_LORA],  g_wkvbl[(size_t)4096 * KV_LORA];
__device__ __nv_bfloat16 g_yh [(size_t)T_LEN * DIMX],      g_yl [(size_t)T_LEN * DIMX];
__device__ __nv_bfloat16 g_woh[(size_t)DIMX * DIMX],       g_wol[(size_t)DIMX * DIMX];

// attention bf16 split operands, per-head layout
__device__ __nv_bfloat16 g_aqh[(size_t)NH * T_LEN * QKD], g_aql[(size_t)NH * T_LEN * QKD];
__device__ __nv_bfloat16 g_akh[(size_t)NH * T_LEN * QKD], g_akl[(size_t)NH * T_LEN * QKD];
__device__ __nv_bfloat16 g_avh[(size_t)NH * T_LEN * VDIM], g_avl[(size_t)NH * T_LEN * VDIM];

// ==================== PTX helpers (plain sm_103 legal) ====================
__device__ __forceinline__ uint32_t smem_u32(const void* p) {
    uint32_t a;
    asm("{ .reg .u64 t; cvta.to.shared.u64 t, %1; cvt.u32.u64 %0, t; }" : "=r"(a) : "l"(p));
    return a;
}
#define CPA(dst, src) \
    asm volatile("cp.async.cg.shared.global [%0], [%1], 16;" :: "r"(dst), "l"(src))
#define CPA_SZ(dst, src, sz) \
    asm volatile("cp.async.cg.shared.global [%0], [%1], 16, %2;" :: "r"(dst), "l"(src), "r"(sz))
#define CPA_COMMIT() asm volatile("cp.async.commit_group;" ::: "memory")
#define CPA_WAIT1()  asm volatile("cp.async.wait_group 1;" ::: "memory")
#define CPA_WAIT0()  asm volatile("cp.async.wait_group 0;" ::: "memory")

#define LDSM_X4(r0, r1, r2, r3, addr) \
    asm volatile("ldmatrix.sync.aligned.m8n8.x4.shared.b16 {%0,%1,%2,%3}, [%4];" \
        : "=r"(r0), "=r"(r1), "=r"(r2), "=r"(r3) : "r"(addr))
#define LDSM_X4_T(r0, r1, r2, r3, addr) \
    asm volatile("ldmatrix.sync.aligned.m8n8.x4.trans.shared.b16 {%0,%1,%2,%3}, [%4];" \
        : "=r"(r0), "=r"(r1), "=r"(r2), "=r"(r3) : "r"(addr))

#define MMA_BF16(d, a, b0, b1) \
    asm volatile("mma.sync.aligned.m16n8k16.row.col.f32.bf16.bf16.f32 " \
        "{%0,%1,%2,%3}, {%4,%5,%6,%7}, {%8,%9}, {%0,%1,%2,%3};" \
        : "+f"((d)[0]), "+f"((d)[1]), "+f"((d)[2]), "+f"((d)[3]) \
        : "r"((a)[0]), "r"((a)[1]), "r"((a)[2]), "r"((a)[3]), "r"(b0), "r"(b1))

__device__ __forceinline__ void split1(float v, __nv_bfloat16& h, __nv_bfloat16& l) {
    h = __float2bfloat16(v);
    l = __float2bfloat16(v - __bfloat162float(h));
}
__device__ __forceinline__ void pack2(float x, float y, uint32_t& hi, uint32_t& lo) {
    __nv_bfloat16 hx, lx, hy, ly;
    split1(x, hx, lx); split1(y, hy, ly);
    __nv_bfloat162 H(hx, hy), L(lx, ly);
    hi = *(uint32_t*)&H; lo = *(uint32_t*)&L;
}

// ==================== split fp32 -> bf16 hi/lo ====================
__global__ __launch_bounds__(256)
void split_bf16(const float* __restrict__ in, __nv_bfloat16* __restrict__ hi,
                __nv_bfloat16* __restrict__ lo, int n4)
{
    int i = blockIdx.x * 256 + threadIdx.x;
    if (i >= n4) return;
    float4 v = ((const float4*)in)[i];
    __nv_bfloat16 h0, h1, h2, h3, l0, l1, l2, l3;
    split1(v.x, h0, l0); split1(v.y, h1, l1);
    split1(v.z, h2, l2); split1(v.w, h3, l3);
    ((__nv_bfloat162*)hi)[i * 2 + 0] = __nv_bfloat162(h0, h1);
    ((__nv_bfloat162*)hi)[i * 2 + 1] = __nv_bfloat162(h2, h3);
    ((__nv_bfloat162*)lo)[i * 2 + 0] = __nv_bfloat162(l0, l1);
    ((__nv_bfloat162*)lo)[i * 2 + 1] = __nv_bfloat162(l2, l3);
}

// ==================== split-bf16 tensor-core GEMM, 8 warps x (64x32) ====================
#define SH 40
#define TILE_HB (128 * SH * 2)
#define STG_B   (4 * TILE_HB)
#define GEMM_SMEM (2 * STG_B)

__global__ __launch_bounds__(256, 1)
void gemm_mma(const __nv_bfloat16* __restrict__ Ah, const __nv_bfloat16* __restrict__ Al,
              const __nv_bfloat16* __restrict__ Bh, const __nv_bfloat16* __restrict__ Bl,
              float* __restrict__ C, int M, int N, int K)
{
    extern __shared__ char sm[];
    const uint32_t sb = smem_u32(sm);
    const int tid  = threadIdx.x;
    const int wid  = tid >> 5, lane = tid & 31;
    const int wm   = wid & 1;
    const int wn   = wid >> 1;
    const int bm   = blockIdx.y * 128, bn = blockIdx.x * 128;

    const int lrow = tid >> 1;
    const int lpart = tid & 1;
    const __nv_bfloat16* pAh = Ah + (size_t)(bm + lrow) * K;
    const __nv_bfloat16* pAl = Al + (size_t)(bm + lrow) * K;
    const int brow_raw = bn + lrow;
    const bool bval = brow_raw < N;
    const int brow = bval ? brow_raw : 0;
    const __nv_bfloat16* pBh = Bh + (size_t)brow * K;
    const __nv_bfloat16* pBl = Bl + (size_t)brow * K;
    const uint32_t bsz = bval ? 16u : 0u;
    const uint32_t dofs = (uint32_t)lrow * (SH * 2) + lpart * 32;

    auto issue = [&](int c, int buf) {
        const int ho = c * 32 + lpart * 16;
        const uint32_t stg = sb + buf * STG_B;
        const char* sAh = (const char*)(pAh + ho);
        const char* sAl = (const char*)(pAl + ho);
        const char* sBh = (const char*)(pBh + ho);
        const char* sBl = (const char*)(pBl + ho);
        const uint32_t d0 = stg + 0 * TILE_HB + dofs;
        const uint32_t d1 = stg + 1 * TILE_HB + dofs;
        const uint32_t d2 = stg + 2 * TILE_HB + dofs;
        const uint32_t d3 = stg + 3 * TILE_HB + dofs;
        CPA(d0, sAh);           CPA(d0 + 16, sAh + 16);
        CPA(d1, sAl);           CPA(d1 + 16, sAl + 16);
        CPA_SZ(d2, sBh, bsz);   CPA_SZ(d2 + 16, sBh + 16, bsz);
        CPA_SZ(d3, sBl, bsz);   CPA_SZ(d3 + 16, sBl + 16, bsz);
    };

    float acc[4][4][4];
#pragma unroll
    for (int i = 0; i < 4; i++)
#pragma unroll
        for (int j = 0; j < 4; j++)
#pragma unroll
            for (int q = 0; q < 4; q++) acc[i][j][q] = 0.f;

    const int arow = wm * 64 + (lane & 15);
    const int akad = (lane >> 4) * 8;
    const int brow_l = wn * 32 + ((lane >> 4) & 1) * 8 + (lane & 7);
    const int bkad  = ((lane >> 3) & 1) * 8;

    const int NC = K / 32;
    issue(0, 0); CPA_COMMIT();
    issue(1, 1); CPA_COMMIT();

    for (int c = 0; c < NC; c++) {
        CPA_WAIT1();
        __syncthreads();
        const uint32_t stg = sb + (c & 1) * STG_B;
        const uint32_t aB_h = stg + 0 * TILE_HB;
        const uint32_t aB_l = stg + 1 * TILE_HB;
        const uint32_t bB_h = stg + 2 * TILE_HB;
        const uint32_t bB_l = stg + 3 * TILE_HB;

#pragma unroll
        for (int kh = 0; kh < 2; kh++) {
            const int kofs = kh * 16;
            uint32_t ah[4][4], al[4][4];
#pragma unroll
            for (int mi = 0; mi < 4; mi++) {
                const uint32_t ao = (uint32_t)((arow + mi * 16) * SH + kofs + akad) * 2;
                LDSM_X4(ah[mi][0], ah[mi][1], ah[mi][2], ah[mi][3], aB_h + ao);
                LDSM_X4(al[mi][0], al[mi][1], al[mi][2], al[mi][3], aB_l + ao);
            }
            uint32_t bh[2][2][2], bl[2][2][2];
#pragma unroll
            for (int bt = 0; bt < 2; bt++) {
                const uint32_t bo = (uint32_t)((brow_l + bt * 16) * SH + kofs + bkad) * 2;
                LDSM_X4(bh[bt][0][0], bh[bt][0][1], bh[bt][1][0], bh[bt][1][1], bB_h + bo);
                LDSM_X4(bl[bt][0][0], bl[bt][0][1], bl[bt][1][0], bl[bt][1][1], bB_l + bo);
            }
#pragma unroll
            for (int mi = 0; mi < 4; mi++)
#pragma unroll
                for (int bt = 0; bt < 2; bt++) {
                    MMA_BF16(acc[mi][2*bt],   ah[mi], bh[bt][0][0], bh[bt][0][1]);
                    MMA_BF16(acc[mi][2*bt+1], ah[mi], bh[bt][1][0], bh[bt][1][1]);
                }
#pragma unroll
            for (int mi = 0; mi < 4; mi++)
#pragma unroll
                for (int bt = 0; bt < 2; bt++) {
                    MMA_BF16(acc[mi][2*bt],   ah[mi], bl[bt][0][0], bl[bt][0][1]);
                    MMA_BF16(acc[mi][2*bt+1], ah[mi], bl[bt][1][0], bl[bt][1][1]);
                }
#pragma unroll
            for (int mi = 0; mi < 4; mi++)
#pragma unroll
                for (int bt = 0; bt < 2; bt++) {
                    MMA_BF16(acc[mi][2*bt],   al[mi], bh[bt][0][0], bh[bt][0][1]);
                    MMA_BF16(acc[mi][2*bt+1], al[mi], bh[bt][1][0], bh[bt][1][1]);
                }
        }
        __syncthreads();
        if (c + 2 < NC) issue(c + 2, c & 1);
        CPA_COMMIT();
    }

    const int er = bm + wm * 64 + (lane >> 2);
    const int ec = bn + wn * 32 + (lane & 3) * 2;
#pragma unroll
    for (int mi = 0; mi < 4; mi++) {
#pragma unroll
        for (int ni = 0; ni < 4; ni++) {
            const int cc = ec + ni * 8;
            if (cc < N) {
                const int r0 = er + mi * 16;
                *(float2*)(C + (size_t)r0 * N + cc) =
                    make_float2(acc[mi][ni][0], acc[mi][ni][1]);
                *(float2*)(C + (size_t)(r0 + 8) * N + cc) =
                    make_float2(acc[mi][ni][2], acc[mi][ni][3]);
            }
        }
    }
}

// ==================== elementwise (fused hi/lo splits) ====================
__global__ __launch_bounds__(256)
void rmsnorm_split_qa(const float* __restrict__ w)
{
    __shared__ float red[256];
    __shared__ float s_inv;
    const int t = blockIdx.x;
    const float* row = g_qakvf + (size_t)t * NAB;
    float s = 0.f;
    for (int i = threadIdx.x; i < Q_LORA; i += 256) { float v = row[i]; s = fmaf(v, v, s); }
    red[threadIdx.x] = s; __syncthreads();
    for (int st = 128; st > 0; st >>= 1) {
        if (threadIdx.x < st) red[threadIdx.x] += red[threadIdx.x + st];
        __syncthreads();
    }
    if (threadIdx.x == 0) s_inv = rsqrtf(red[0] / (float)Q_LORA + EPS);
    __syncthreads();
    const float inv = s_inv;
    for (int i = threadIdx.x; i < Q_LORA; i += 256) {
        float v = row[i] * inv * w[i];
        __nv_bfloat16 h, l; split1(v, h, l);
        g_qah[(size_t)t * Q_LORA + i] = h;
        g_qal[(size_t)t * Q_LORA + i] = l;
    }
}

__global__ __launch_bounds__(256)
void kv_prep(const float* __restrict__ w, const float* __restrict__ freqs)
{
    __shared__ float red[256];
    __shared__ float s_inv;
    const int t = blockIdx.x;
    const float* row = g_qakvf + (size_t)t * NAB + Q_LORA;
    float s = 0.f;
    for (int i = threadIdx.x; i < KV_LORA; i += 256) { float v = row[i]; s = fmaf(v, v, s); }
    red[threadIdx.x] = s; __syncthreads();
    for (int st = 128; st > 0; st >>= 1) {
        if (threadIdx.x < st) red[threadIdx.x] += red[threadIdx.x + st];
        __syncthreads();
    }
    if (threadIdx.x == 0) s_inv = rsqrtf(red[0] / (float)KV_LORA + EPS);
    __syncthreads();
    const float inv = s_inv;
    for (int i = threadIdx.x; i < KV_LORA; i += 256) {
        float v = row[i] * inv * w[i];
        __nv_bfloat16 h, l; split1(v, h, l);
        g_ckvnh[(size_t)t * KV_LORA + i] = h;
        g_ckvnl[(size_t)t * KV_LORA + i] = l;
    }

    if (threadIdx.x < ROPE / 2) {
        int i = threadIdx.x;
        float x1 = row[KV_LORA + 2 * i];
        float x2 = row[KV_LORA + 2 * i + 1];
        float f = freqs[(size_t)t * (ROPE / 2) + i];
        float c = cosf(f), sn = sinf(f);
        g_kpe[(size_t)t * ROPE + 2 * i]     = x1 * c - x2 * sn;
        g_kpe[(size_t)t * ROPE + 2 * i + 1] = x1 * sn + x2 * c;
    }
}

// assemble per-head split-bf16 Q/K/V for the mma attention
__global__ __launch_bounds__(256)
void assemble(const float* __restrict__ freqs)
{
    const int t = blockIdx.x;
    const int tid = threadIdx.x;
    for (int idx = tid; idx < NH * NOPE; idx += 256) {
        int hh = idx >> 7, d = idx & 127;
        size_t qk = ((size_t)hh * T_LEN + t) * QKD + d;
        __nv_bfloat16 h, l;
        split1(g_q[(size_t)t * NH * QKD + hh * QKD + d], h, l);
        g_aqh[qk] = h; g_aql[qk] = l;
        split1(g_kv[(size_t)t * NH * 256 + hh * 256 + d], h, l);
        g_akh[qk] = h; g_akl[qk] = l;
        size_t vv = ((size_t)hh * T_LEN + t) * VDIM + d;
        split1(g_kv[(size_t)t * NH * 256 + hh * 256 + 128 + d], h, l);
        g_avh[vv] = h; g_avl[vv] = l;
    }
    for (int idx = tid; idx < NH * (ROPE / 2); idx += 256) {
        int hh = idx >> 5, i = idx & 31;
        float f = freqs[(size_t)t * (ROPE / 2) + i];
        float c = cosf(f), sn = sinf(f);
        const float* qp = g_q + (size_t)t * NH * QKD + hh * QKD + NOPE;
        float x1 = qp[2 * i], x2 = qp[2 * i + 1];
        size_t base = ((size_t)hh * T_LEN + t) * QKD + NOPE;
        __nv_bfloat16 h, l;
        split1(x1 * c - x2 * sn, h, l);  g_aqh[base + 2*i] = h;   g_aql[base + 2*i] = l;
        split1(x1 * sn + x2 * c, h, l);  g_aqh[base + 2*i+1] = h; g_aql[base + 2*i+1] = l;
        split1(g_kpe[(size_t)t * ROPE + 2*i], h, l);     g_akh[base + 2*i] = h;   g_akl[base + 2*i] = l;
        split1(g_kpe[(size_t)t * ROPE + 2*i + 1], h, l); g_akh[base + 2*i+1] = h; g_akl[base + 2*i+1] = l;
    }
}

// ==================== tensor-core flash attention ====================
#define BQ 128
#define BK 64
#define SQH 200
#define SVH 136
#define ATT_SMEM ((2 * BQ * SQH + 2 * BK * SQH + 2 * BK * SVH) * 2)

__global__ __launch_bounds__(256, 1)
void mla_attn_mma()
{
    extern __shared__ char smraw[];
    const uint32_t sb  = smem_u32(smraw);
    const uint32_t uQh = sb;
    const uint32_t uQl = uQh + BQ * SQH * 2;
    const uint32_t uKh = uQl + BQ * SQH * 2;
    const uint32_t uKl = uKh + BK * SQH * 2;
    const uint32_t uVh = uKl + BK * SQH * 2;
    const uint32_t uVl = uVh + BK * SVH * 2;

    const int h  = blockIdx.x;
    const int qi = (int)gridDim.y - 1 - (int)blockIdx.y;
    const int q0 = qi * BQ;
    const int tid = threadIdx.x, wid = tid >> 5, lane = tid & 31;
    const int mrow = wid * 16;

    const __nv_bfloat16* gQh = g_aqh + ((size_t)h * T_LEN + q0) * QKD;
    const __nv_bfloat16* gQl = g_aql + ((size_t)h * T_LEN + q0) * QKD;
    const __nv_bfloat16* gKh = g_akh + (size_t)h * T_LEN * QKD;
    const __nv_bfloat16* gKl = g_akl + (size_t)h * T_LEN * QKD;
    const __nv_bfloat16* gVh = g_avh + (size_t)h * T_LEN * VDIM;
    const __nv_bfloat16* gVl = g_avl + (size_t)h * T_LEN * VDIM;

    for (int i = tid; i < BQ * 24; i += 256) {
        int r = i / 24, c = i % 24;
        uint32_t d = (uint32_t)(r * SQH + c * 8) * 2;
        CPA(uQh + d, (const char*)(gQh + (size_t)r * QKD + c * 8));
        CPA(uQl + d, (const char*)(gQl + (size_t)r * QKD + c * 8));
    }
    CPA_COMMIT();

    float Oa[16][4];
#pragma unroll
    for (int n = 0; n < 16; n++)
#pragma unroll
        for (int j = 0; j < 4; j++) Oa[n][j] = 0.f;
    float mr0 = -1e30f, mr1 = -1e30f, lr0 = 0.f, lr1 = 0.f;

    const uint32_t qa_base = uQh + (uint32_t)((mrow + (lane & 15)) * SQH + (lane >> 4) * 8) * 2;
    const uint32_t ql_rel  = BQ * SQH * 2;
    const int kb_row = ((lane >> 4) & 1) * 8 + (lane & 7);
    const int kb_kad = ((lane >> 3) & 1) * 8;
    const int va_row = lane & 15;
    const int va_cad = (lane >> 4) * 8;

    const int nkt = 2 * qi + 2;
    for (int kt = 0; kt < nkt; kt++) {
        for (int i = tid; i < BK * 24; i += 256) {
            int r = i / 24, c = i % 24;
            const size_t go = (size_t)(kt * BK + r) * QKD + c * 8;
            uint32_t d = (uint32_t)(r * SQH + c * 8) * 2;
            CPA(uKh + d, (const char*)(gKh + go));
            CPA(uKl + d, (const char*)(gKl + go));
        }
        for (int i = tid; i < BK * 16; i += 256) {
            int r = i / 16, c = i % 16;
            const size_t go = (size_t)(kt * BK + r) * VDIM + c * 8;
            uint32_t d = (uint32_t)(r * SVH + c * 8) * 2;
            CPA(uVh + d, (const char*)(gVh + go));
            CPA(uVl + d, (const char*)(gVl + go));
        }
        CPA_COMMIT();
        CPA_WAIT0();
        __syncthreads();

        const int kbase = kt * BK;
        const bool active = kbase <= (q0 + mrow + 15);
        if (active) {
            float Sa[8][4];
#pragma unroll
            for (int n = 0; n < 8; n++)
#pragma unroll
                for (int j = 0; j < 4; j++) Sa[n][j] = 0.f;

#pragma unroll
            for (int ks = 0; ks < 12; ks++) {
                uint32_t ah[4], al[4];
                const uint32_t qo = qa_base + ks * 32;
                LDSM_X4(ah[0], ah[1], ah[2], ah[3], qo);
                LDSM_X4(al[0], al[1], al[2], al[3], qo + ql_rel);
                uint32_t bh[8][2], bl[8][2];
#pragma unroll
                for (int np = 0; np < 4; np++) {
                    const uint32_t bo = (uint32_t)((np * 16 + kb_row) * SQH + ks * 16 + kb_kad) * 2;
                    LDSM_X4(bh[2*np][0], bh[2*np][1], bh[2*np+1][0], bh[2*np+1][1], uKh + bo);
                    LDSM_X4(bl[2*np][0], bl[2*np][1], bl[2*np+1][0], bl[2*np+1][1], uKl + bo);
                }
#pragma unroll
                for (int n = 0; n < 8; n++) MMA_BF16(Sa[n], ah, bh[n][0], bh[n][1]);
#pragma unroll
                for (int n = 0; n < 8; n++) MMA_BF16(Sa[n], ah, bl[n][0], bl[n][1]);
#pragma unroll
                for (int n = 0; n < 8; n++) MMA_BF16(Sa[n], al, bh[n][0], bh[n][1]);
            }

            const int r0g = q0 + mrow + (lane >> 2);
            const int r1g = r0g + 8;
            const bool needmask = (kbase + BK - 1) > (q0 + mrow);
            float tm0 = -INFINITY, tm1 = -INFINITY;
#pragma unroll
            for (int n = 0; n < 8; n++) {
                const int c0 = kbase + n * 8 + (lane & 3) * 2;
                float v0 = Sa[n][0] * SOFTSCALE, v1 = Sa[n][1] * SOFTSCALE;
                float v2 = Sa[n][2] * SOFTSCALE, v3 = Sa[n][3] * SOFTSCALE;
                if (needmask) {
                    if (c0     > r0g) v0 = -INFINITY;
                    if (c0 + 1 > r0g) v1 = -INFINITY;
                    if (c0     > r1g) v2 = -INFINITY;
                    if (c0 + 1 > r1g) v3 = -INFINITY;
                }
                Sa[n][0] = v0; Sa[n][1] = v1; Sa[n][2] = v2; Sa[n][3] = v3;
                tm0 = fmaxf(tm0, fmaxf(v0, v1));
                tm1 = fmaxf(tm1, fmaxf(v2, v3));
            }
            tm0 = fmaxf(tm0, __shfl_xor_sync(0xffffffffu, tm0, 1));
            tm0 = fmaxf(tm0, __shfl_xor_sync(0xffffffffu, tm0, 2));
            tm1 = fmaxf(tm1, __shfl_xor_sync(0xffffffffu, tm1, 1));
            tm1 = fmaxf(tm1, __shfl_xor_sync(0xffffffffu, tm1, 2));
            const float nm0 = fmaxf(mr0, tm0), nm1 = fmaxf(mr1, tm1);
            const float sc0 = __expf(mr0 - nm0), sc1 = __expf(mr1 - nm1);
            float rs0 = 0.f, rs1 = 0.f;
#pragma unroll
            for (int n = 0; n < 8; n++) {
                Sa[n][0] = __expf(Sa[n][0] - nm0); rs0 += Sa[n][0];
                Sa[n][1] = __expf(Sa[n][1] - nm0); rs0 += Sa[n][1];
                Sa[n][2] = __expf(Sa[n][2] - nm1); rs1 += Sa[n][2];
                Sa[n][3] = __expf(Sa[n][3] - nm1); rs1 += Sa[n][3];
            }
            rs0 += __shfl_xor_sync(0xffffffffu, rs0, 1);
            rs0 += __shfl_xor_sync(0xffffffffu, rs0, 2);
            rs1 += __shfl_xor_sync(0xffffffffu, rs1, 1);
            rs1 += __shfl_xor_sync(0xffffffffu, rs1, 2);
            lr0 = lr0 * sc0 + rs0;
            lr1 = lr1 * sc1 + rs1;
            mr0 = nm0; mr1 = nm1;
#pragma unroll
            for (int n = 0; n < 16; n++) {
                Oa[n][0] *= sc0; Oa[n][1] *= sc0;
                Oa[n][2] *= sc1; Oa[n][3] *= sc1;
            }

            uint32_t ph[4][4], pl[4][4];
#pragma unroll
            for (int kf = 0; kf < 4; kf++) {
                pack2(Sa[2*kf][0],   Sa[2*kf][1],   ph[kf][0], pl[kf][0]);
                pack2(Sa[2*kf][2],   Sa[2*kf][3],   ph[kf][1], pl[kf][1]);
                pack2(Sa[2*kf+1][0], Sa[2*kf+1][1], ph[kf][2], pl[kf][2]);
                pack2(Sa[2*kf+1][2], Sa[2*kf+1][3], ph[kf][3], pl[kf][3]);
            }

#pragma unroll
            for (int kf = 0; kf < 4; kf++) {
                uint32_t vbh[16][2], vbl[16][2];
#pragma unroll
                for (int np = 0; np < 8; np++) {
                    const uint32_t vo = (uint32_t)((kf * 16 + va_row) * SVH + np * 16 + va_cad) * 2;
                    LDSM_X4_T(vbh[2*np][0], vbh[2*np][1], vbh[2*np+1][0], vbh[2*np+1][1], uVh + vo);
                    LDSM_X4_T(vbl[2*np][0], vbl[2*np][1], vbl[2*np+1][0], vbl[2*np+1][1], uVl + vo);
                }
#pragma unroll
                for (int n = 0; n < 16; n++) MMA_BF16(Oa[n], ph[kf], vbh[n][0], vbh[n][1]);
#pragma unroll
                for (int n = 0; n < 16; n++) MMA_BF16(Oa[n], ph[kf], vbl[n][0], vbl[n][1]);
#pragma unroll
                for (int n = 0; n < 16; n++) MMA_BF16(Oa[n], pl[kf], vbh[n][0], vbh[n][1]);
            }
        }
        __syncthreads();
    }

    const float inv0 = 1.f / lr0, inv1 = 1.f / lr1;
    const int r0g = q0 + mrow + (lane >> 2);
#pragma unroll
    for (int n = 0; n < 16; n++) {
        const int col = h * VDIM + n * 8 + (lane & 3) * 2;
        __nv_bfloat16 h0, l0, h1, l1;
        split1(Oa[n][0] * inv0, h0, l0);
        split1(Oa[n][1] * inv0, h1, l1);
        *(__nv_bfloat162*)(g_yh + (size_t)r0g * DIMX + col) = __nv_bfloat162(h0, h1);
        *(__nv_bfloat162*)(g_yl + (size_t)r0g * DIMX + col) = __nv_bfloat162(l0, l1);
        split1(Oa[n][2] * inv1, h0, l0);
        split1(Oa[n][3] * inv1, h1, l1);
        *(__nv_bfloat162*)(g_yh + (size_t)(r0g + 8) * DIMX + col) = __nv_bfloat162(h0, h1);
        *(__nv_bfloat162*)(g_yl + (size_t)(r0g + 8) * DIMX + col) = __nv_bfloat162(l0, l1);
    }
}

// ==================== launch (multi-stream DAG inside graph capture) ====================
extern "C" void kernel_launch(void* const* d_in, const int* in_sizes, int n_in,
                              void* d_out, int out_size)
{
    const float* x        = (const float*)d_in[0];
    const float* freqs    = (const float*)d_in[1];
    const float* wq_a     = (const float*)d_in[3];
    const float* q_norm_w = (const float*)d_in[4];
    const float* wq_b     = (const float*)d_in[5];
    const float* wkv_a    = (const float*)d_in[6];
    const float* kv_norm_w= (const float*)d_in[7];
    const float* wkv_b    = (const float*)d_in[8];
    const float* wo       = (const float*)d_in[9];
    float* out = (float*)d_out;

    float *qakvf, *q_p, *kv_p;
    cudaGetSymbolAddress((void**)&qakvf, g_qakvf);
    cudaGetSymbolAddress((void**)&q_p,   g_q);
    cudaGetSymbolAddress((void**)&kv_p,  g_kv);

    __nv_bfloat16 *xh,*xl,*wabh,*wabl,*qah,*qal,*wqbh,*wqbl,
                  *ckvnh,*ckvnl,*wkvbh,*wkvbl,*yh,*yl,*woh,*wol;
    cudaGetSymbolAddress((void**)&xh, g_xh);     cudaGetSymbolAddress((void**)&xl, g_xl);
    cudaGetSymbolAddress((void**)&wabh, g_wabh); cudaGetSymbolAddress((void**)&wabl, g_wabl);
    cudaGetSymbolAddress((void**)&qah, g_qah);   cudaGetSymbolAddress((void**)&qal, g_qal);
    cudaGetSymbolAddress((void**)&wqbh, g_wqbh); cudaGetSymbolAddress((void**)&wqbl, g_wqbl);
    cudaGetSymbolAddress((void**)&ckvnh, g_ckvnh); cudaGetSymbolAddress((void**)&ckvnl, g_ckvnl);
    cudaGetSymbolAddress((void**)&wkvbh, g_wkvbh); cudaGetSymbolAddress((void**)&wkvbl, g_wkvbl);
    cudaGetSymbolAddress((void**)&yh, g_yh);     cudaGetSymbolAddress((void**)&yl, g_yl);
    cudaGetSymbolAddress((void**)&woh, g_woh);   cudaGetSymbolAddress((void**)&wol, g_wol);

    cudaFuncSetAttribute(gemm_mma, cudaFuncAttributeMaxDynamicSharedMemorySize, GEMM_SMEM);
    cudaFuncSetAttribute(mla_attn_mma, cudaFuncAttributeMaxDynamicSharedMemorySize, ATT_SMEM);

    // streams/events created once on first (non-captured correctness) call;
    // reused identically on every subsequent call -> deterministic captured DAG.
    static cudaStream_t s1 = nullptr, s2 = nullptr;
    static cudaEvent_t eFork, eWab, eWqb, eWkvb, eWo, eG1, eG3;
    if (!s1) {
        cudaStreamCreateWithFlags(&s1, cudaStreamNonBlocking);
        cudaStreamCreateWithFlags(&s2, cudaStreamNonBlocking);
        cudaEventCreateWithFlags(&eFork, cudaEventDisableTiming);
        cudaEventCreateWithFlags(&eWab,  cudaEventDisableTiming);
        cudaEventCreateWithFlags(&eWqb,  cudaEventDisableTiming);
        cudaEventCreateWithFlags(&eWkvb, cudaEventDisableTiming);
        cudaEventCreateWithFlags(&eWo,   cudaEventDisableTiming);
        cudaEventCreateWithFlags(&eG1,   cudaEventDisableTiming);
        cudaEventCreateWithFlags(&eG3,   cudaEventDisableTiming);
    }

    dim3 blk256(256);
    auto splits = [&](cudaStream_t st, const float* src, __nv_bfloat16* h,
                      __nv_bfloat16* l, size_t n) {
        int n4 = (int)(n / 4);
        split_bf16<<<(n4 + 255) / 256, 256, 0, st>>>(src, h, l, n4);
    };

    // fork side streams from the capture (default) stream
    cudaEventRecord(eFork, 0);
    cudaStreamWaitEvent(s1, eFork, 0);
    cudaStreamWaitEvent(s2, eFork, 0);

    // s1: all weight splits (independent of compute chain)
    splits(s1, wq_a, wabh, wabl, (size_t)Q_LORA * DIMX);
    splits(s1, wkv_a, wabh + (size_t)Q_LORA * DIMX, wabl + (size_t)Q_LORA * DIMX,
           (size_t)KVA_OUT * DIMX);
    cudaEventRecord(eWab, s1);
    splits(s1, wq_b, wqbh, wqbl, (size_t)NH * QKD * Q_LORA);
    cudaEventRecord(eWqb, s1);
    splits(s1, wkv_b, wkvbh, wkvbl, (size_t)4096 * KV_LORA);
    cudaEventRecord(eWkvb, s1);
    splits(s1, wo, woh, wol, (size_t)DIMX * DIMX);
    cudaEventRecord(eWo, s1);

    // s0: x split, then fused qa|kvf GEMM
    splits(0, x, xh, xl, (size_t)T_LEN * DIMX);
    cudaStreamWaitEvent(0, eWab, 0);
    gemm_mma<<<dim3((NAB + 127) / 128, T_LEN / 128), blk256, GEMM_SMEM>>>(
        xh, xl, wabh, wabl, qakvf, T_LEN, NAB, DIMX);
    cudaEventRecord(eG1, 0);

    // s0: q path
    rmsnorm_split_qa<<<T_LEN, blk256>>>(q_norm_w);
    cudaStreamWaitEvent(0, eWqb, 0);
    gemm_mma<<<dim3(NH * QKD / 128, T_LEN / 128), blk256, GEMM_SMEM>>>(
        qah, qal, wqbh, wqbl, q_p, T_LEN, NH * QKD, Q_LORA);

    // s2: kv path (concurrent with q path)
    cudaStreamWaitEvent(s2, eG1, 0);
    kv_prep<<<T_LEN, blk256, 0, s2>>>(kv_norm_w, freqs);
    cudaStreamWaitEvent(s2, eWkvb, 0);
    gemm_mma<<<dim3(4096 / 128, T_LEN / 128), blk256, GEMM_SMEM, s2>>>(
        ckvnh, ckvnl, wkvbh, wkvbl, kv_p, T_LEN, 4096, KV_LORA);
    cudaEventRecord(eG3, s2);

    // s0: join kv path, assemble, attention, output GEMM
    cudaStreamWaitEvent(0, eG3, 0);
    assemble<<<T_LEN, blk256>>>(freqs);
    mla_attn_mma<<<dim3(NH, T_LEN / BQ), blk256, ATT_SMEM>>>();
    cudaStreamWaitEvent(0, eWo, 0);
    gemm_mma<<<dim3(DIMX / 128, T_LEN / 128), blk256, GEMM_SMEM>>>(
        yh, yl, woh, wol, out, T_LEN, DIMX, NH * VDIM);
}

// round 13
// speedup vs baseline: 3.7055x; 1.0053x over previous
#include <cuda_runtime.h>
#include <cuda_bf16.h>
#include <math.h>
#include <cstdint>

// Problem constants
#define T_LEN 2048
#define DIMX 2048
#define NH 16
#define NOPE 128
#define ROPE 64
#define VDIM 128
#define QKD 192
#define Q_LORA 768
#define KV_LORA 512
#define KVA_OUT 576
#define NAB (Q_LORA + KVA_OUT)   // 1344 fused qa|kvf output cols
#define SOFTSCALE (-96.0f)
#define EPS 1e-6f

// ==================== scratch ====================
__device__ float g_qakvf[(size_t)T_LEN * NAB];     // fused [qa | kvf]
__device__ float g_q   [(size_t)T_LEN * NH * QKD];
__device__ float g_kpe [(size_t)T_LEN * ROPE];
__device__ float g_kv  [(size_t)T_LEN * NH * (NOPE + VDIM)];

// bf16 split buffers (hi/lo)
__device__ __nv_bfloat16 g_xh [(size_t)T_LEN * DIMX],      g_xl [(size_t)T_LEN * DIMX];
__device__ __nv_bfloat16 g_wabh[(size_t)NAB * DIMX],       g_wabl[(size_t)NAB * DIMX];
__device__ __nv_bfloat16 g_qah[(size_t)T_LEN * Q_LORA],    g_qal[(size_t)T_LEN * Q_LORA];
__device__ __nv_bfloat16 g_wqbh[(size_t)NH * QKD * Q_LORA],g_wqbl[(size_t)NH * QKD * Q_LORA];
__device__ __nv_bfloat16 g_ckvnh[(size_t)T_LEN * KV_LORA], g_ckvnl[(size_t)T_LEN * KV_LORA];
__device__ __nv_bfloat16 g_wkvbh[(size_t)4096 * KV_LORA],  g_wkvbl[(size_t)4096 * KV_LORA];
__device__ __nv_bfloat16 g_yh [(size_t)T_LEN * DIMX],      g_yl [(size_t)T_LEN * DIMX];
__device__ __nv_bfloat16 g_woh[(size_t)DIMX * DIMX],       g_wol[(size_t)DIMX * DIMX];

// attention bf16 split operands, per-head layout
__device__ __nv_bfloat16 g_aqh[(size_t)NH * T_LEN * QKD], g_aql[(size_t)NH * T_LEN * QKD];
__device__ __nv_bfloat16 g_akh[(size_t)NH * T_LEN * QKD], g_akl[(size_t)NH * T_LEN * QKD];
__device__ __nv_bfloat16 g_avh[(size_t)NH * T_LEN * VDIM], g_avl[(size_t)NH * T_LEN * VDIM];

// ==================== PTX helpers (plain sm_103 legal) ====================
__device__ __forceinline__ uint32_t smem_u32(const void* p) {
    uint32_t a;
    asm("{ .reg .u64 t; cvta.to.shared.u64 t, %1; cvt.u32.u64 %0, t; }" : "=r"(a) : "l"(p));
    return a;
}
#define CPA(dst, src) \
    asm volatile("cp.async.cg.shared.global [%0], [%1], 16;" :: "r"(dst), "l"(src))
#define CPA_SZ(dst, src, sz) \
    asm volatile("cp.async.cg.shared.global [%0], [%1], 16, %2;" :: "r"(dst), "l"(src), "r"(sz))
#define CPA_COMMIT() asm volatile("cp.async.commit_group;" ::: "memory")
#define CPA_WAIT1()  asm volatile("cp.async.wait_group 1;" ::: "memory")
#define CPA_WAIT0()  asm volatile("cp.async.wait_group 0;" ::: "memory")

#define LDSM_X4(r0, r1, r2, r3, addr) \
    asm volatile("ldmatrix.sync.aligned.m8n8.x4.shared.b16 {%0,%1,%2,%3}, [%4];" \
        : "=r"(r0), "=r"(r1), "=r"(r2), "=r"(r3) : "r"(addr))
#define LDSM_X4_T(r0, r1, r2, r3, addr) \
    asm volatile("ldmatrix.sync.aligned.m8n8.x4.trans.shared.b16 {%0,%1,%2,%3}, [%4];" \
        : "=r"(r0), "=r"(r1), "=r"(r2), "=r"(r3) : "r"(addr))

#define MMA_BF16(d, a, b0, b1) \
    asm volatile("mma.sync.aligned.m16n8k16.row.col.f32.bf16.bf16.f32 " \
        "{%0,%1,%2,%3}, {%4,%5,%6,%7}, {%8,%9}, {%0,%1,%2,%3};" \
        : "+f"((d)[0]), "+f"((d)[1]), "+f"((d)[2]), "+f"((d)[3]) \
        : "r"((a)[0]), "r"((a)[1]), "r"((a)[2]), "r"((a)[3]), "r"(b0), "r"(b1))

__device__ __forceinline__ void split1(float v, __nv_bfloat16& h, __nv_bfloat16& l) {
    h = __float2bfloat16(v);
    l = __float2bfloat16(v - __bfloat162float(h));
}
__device__ __forceinline__ void pack2(float x, float y, uint32_t& hi, uint32_t& lo) {
    __nv_bfloat16 hx, lx, hy, ly;
    split1(x, hx, lx); split1(y, hy, ly);
    __nv_bfloat162 H(hx, hy), L(lx, ly);
    hi = *(uint32_t*)&H; lo = *(uint32_t*)&L;
}

// ==================== split fp32 -> bf16 hi/lo ====================
__global__ __launch_bounds__(256)
void split_bf16(const float* __restrict__ in, __nv_bfloat16* __restrict__ hi,
                __nv_bfloat16* __restrict__ lo, int n4)
{
    int i = blockIdx.x * 256 + threadIdx.x;
    if (i >= n4) return;
    float4 v = ((const float4*)in)[i];
    __nv_bfloat16 h0, h1, h2, h3, l0, l1, l2, l3;
    split1(v.x, h0, l0); split1(v.y, h1, l1);
    split1(v.z, h2, l2); split1(v.w, h3, l3);
    ((__nv_bfloat162*)hi)[i * 2 + 0] = __nv_bfloat162(h0, h1);
    ((__nv_bfloat162*)hi)[i * 2 + 1] = __nv_bfloat162(h2, h3);
    ((__nv_bfloat162*)lo)[i * 2 + 0] = __nv_bfloat162(l0, l1);
    ((__nv_bfloat162*)lo)[i * 2 + 1] = __nv_bfloat162(l2, l3);
}

// ==================== split-bf16 tensor-core GEMM, 8 warps x (64x32) ====================
#define SH 40
#define TILE_HB (128 * SH * 2)
#define STG_B   (4 * TILE_HB)
#define GEMM_SMEM (2 * STG_B)

__global__ __launch_bounds__(256, 1)
void gemm_mma(const __nv_bfloat16* __restrict__ Ah, const __nv_bfloat16* __restrict__ Al,
              const __nv_bfloat16* __restrict__ Bh, const __nv_bfloat16* __restrict__ Bl,
              float* __restrict__ C, int M, int N, int K)
{
    extern __shared__ char sm[];
    const uint32_t sb = smem_u32(sm);
    const int tid  = threadIdx.x;
    const int wid  = tid >> 5, lane = tid & 31;
    const int wm   = wid & 1;
    const int wn   = wid >> 1;
    const int bm   = blockIdx.y * 128, bn = blockIdx.x * 128;

    const int lrow = tid >> 1;
    const int lpart = tid & 1;
    const __nv_bfloat16* pAh = Ah + (size_t)(bm + lrow) * K;
    const __nv_bfloat16* pAl = Al + (size_t)(bm + lrow) * K;
    const int brow_raw = bn + lrow;
    const bool bval = brow_raw < N;
    const int brow = bval ? brow_raw : 0;
    const __nv_bfloat16* pBh = Bh + (size_t)brow * K;
    const __nv_bfloat16* pBl = Bl + (size_t)brow * K;
    const uint32_t bsz = bval ? 16u : 0u;
    const uint32_t dofs = (uint32_t)lrow * (SH * 2) + lpart * 32;

    auto issue = [&](int c, int buf) {
        const int ho = c * 32 + lpart * 16;
        const uint32_t stg = sb + buf * STG_B;
        const char* sAh = (const char*)(pAh + ho);
        const char* sAl = (const char*)(pAl + ho);
        const char* sBh = (const char*)(pBh + ho);
        const char* sBl = (const char*)(pBl + ho);
        const uint32_t d0 = stg + 0 * TILE_HB + dofs;
        const uint32_t d1 = stg + 1 * TILE_HB + dofs;
        const uint32_t d2 = stg + 2 * TILE_HB + dofs;
        const uint32_t d3 = stg + 3 * TILE_HB + dofs;
        CPA(d0, sAh);           CPA(d0 + 16, sAh + 16);
        CPA(d1, sAl);           CPA(d1 + 16, sAl + 16);
        CPA_SZ(d2, sBh, bsz);   CPA_SZ(d2 + 16, sBh + 16, bsz);
        CPA_SZ(d3, sBl, bsz);   CPA_SZ(d3 + 16, sBl + 16, bsz);
    };

    float acc[4][4][4];
#pragma unroll
    for (int i = 0; i < 4; i++)
#pragma unroll
        for (int j = 0; j < 4; j++)
#pragma unroll
            for (int q = 0; q < 4; q++) acc[i][j][q] = 0.f;

    const int arow = wm * 64 + (lane & 15);
    const int akad = (lane >> 4) * 8;
    const int brow_l = wn * 32 + ((lane >> 4) & 1) * 8 + (lane & 7);
    const int bkad  = ((lane >> 3) & 1) * 8;

    const int NC = K / 32;
    issue(0, 0); CPA_COMMIT();
    issue(1, 1); CPA_COMMIT();

    for (int c = 0; c < NC; c++) {
        CPA_WAIT1();
        __syncthreads();
        const uint32_t stg = sb + (c & 1) * STG_B;
        const uint32_t aB_h = stg + 0 * TILE_HB;
        const uint32_t aB_l = stg + 1 * TILE_HB;
        const uint32_t bB_h = stg + 2 * TILE_HB;
        const uint32_t bB_l = stg + 3 * TILE_HB;

#pragma unroll
        for (int kh = 0; kh < 2; kh++) {
            const int kofs = kh * 16;
            uint32_t ah[4][4], al[4][4];
#pragma unroll
            for (int mi = 0; mi < 4; mi++) {
                const uint32_t ao = (uint32_t)((arow + mi * 16) * SH + kofs + akad) * 2;
                LDSM_X4(ah[mi][0], ah[mi][1], ah[mi][2], ah[mi][3], aB_h + ao);
                LDSM_X4(al[mi][0], al[mi][1], al[mi][2], al[mi][3], aB_l + ao);
            }
            uint32_t bh[2][2][2], bl[2][2][2];
#pragma unroll
            for (int bt = 0; bt < 2; bt++) {
                const uint32_t bo = (uint32_t)((brow_l + bt * 16) * SH + kofs + bkad) * 2;
                LDSM_X4(bh[bt][0][0], bh[bt][0][1], bh[bt][1][0], bh[bt][1][1], bB_h + bo);
                LDSM_X4(bl[bt][0][0], bl[bt][0][1], bl[bt][1][0], bl[bt][1][1], bB_l + bo);
            }
#pragma unroll
            for (int mi = 0; mi < 4; mi++)
#pragma unroll
                for (int bt = 0; bt < 2; bt++) {
                    MMA_BF16(acc[mi][2*bt],   ah[mi], bh[bt][0][0], bh[bt][0][1]);
                    MMA_BF16(acc[mi][2*bt+1], ah[mi], bh[bt][1][0], bh[bt][1][1]);
                }
#pragma unroll
            for (int mi = 0; mi < 4; mi++)
#pragma unroll
                for (int bt = 0; bt < 2; bt++) {
                    MMA_BF16(acc[mi][2*bt],   ah[mi], bl[bt][0][0], bl[bt][0][1]);
                    MMA_BF16(acc[mi][2*bt+1], ah[mi], bl[bt][1][0], bl[bt][1][1]);
                }
#pragma unroll
            for (int mi = 0; mi < 4; mi++)
#pragma unroll
                for (int bt = 0; bt < 2; bt++) {
                    MMA_BF16(acc[mi][2*bt],   al[mi], bh[bt][0][0], bh[bt][0][1]);
                    MMA_BF16(acc[mi][2*bt+1], al[mi], bh[bt][1][0], bh[bt][1][1]);
                }
        }
        __syncthreads();
        if (c + 2 < NC) issue(c + 2, c & 1);
        CPA_COMMIT();
    }

    const int er = bm + wm * 64 + (lane >> 2);
    const int ec = bn + wn * 32 + (lane & 3) * 2;
#pragma unroll
    for (int mi = 0; mi < 4; mi++) {
#pragma unroll
        for (int ni = 0; ni < 4; ni++) {
            const int cc = ec + ni * 8;
            if (cc < N) {
                const int r0 = er + mi * 16;
                *(float2*)(C + (size_t)r0 * N + cc) =
                    make_float2(acc[mi][ni][0], acc[mi][ni][1]);
                *(float2*)(C + (size_t)(r0 + 8) * N + cc) =
                    make_float2(acc[mi][ni][2], acc[mi][ni][3]);
            }
        }
    }
}

// ==================== elementwise (fused hi/lo splits) ====================
__global__ __launch_bounds__(256)
void rmsnorm_split_qa(const float* __restrict__ w)
{
    __shared__ float red[256];
    __shared__ float s_inv;
    const int t = blockIdx.x;
    const float* row = g_qakvf + (size_t)t * NAB;
    float s = 0.f;
    for (int i = threadIdx.x; i < Q_LORA; i += 256) { float v = row[i]; s = fmaf(v, v, s); }
    red[threadIdx.x] = s; __syncthreads();
    for (int st = 128; st > 0; st >>= 1) {
        if (threadIdx.x < st) red[threadIdx.x] += red[threadIdx.x + st];
        __syncthreads();
    }
    if (threadIdx.x == 0) s_inv = rsqrtf(red[0] / (float)Q_LORA + EPS);
    __syncthreads();
    const float inv = s_inv;
    for (int i = threadIdx.x; i < Q_LORA; i += 256) {
        float v = row[i] * inv * w[i];
        __nv_bfloat16 h, l; split1(v, h, l);
        g_qah[(size_t)t * Q_LORA + i] = h;
        g_qal[(size_t)t * Q_LORA + i] = l;
    }
}

__global__ __launch_bounds__(256)
void kv_prep(const float* __restrict__ w, const float* __restrict__ freqs)
{
    __shared__ float red[256];
    __shared__ float s_inv;
    const int t = blockIdx.x;
    const float* row = g_qakvf + (size_t)t * NAB + Q_LORA;
    float s = 0.f;
    for (int i = threadIdx.x; i < KV_LORA; i += 256) { float v = row[i]; s = fmaf(v, v, s); }
    red[threadIdx.x] = s; __syncthreads();
    for (int st = 128; st > 0; st >>= 1) {
        if (threadIdx.x < st) red[threadIdx.x] += red[threadIdx.x + st];
        __syncthreads();
    }
    if (threadIdx.x == 0) s_inv = rsqrtf(red[0] / (float)KV_LORA + EPS);
    __syncthreads();
    const float inv = s_inv;
    for (int i = threadIdx.x; i < KV_LORA; i += 256) {
        float v = row[i] * inv * w[i];
        __nv_bfloat16 h, l; split1(v, h, l);
        g_ckvnh[(size_t)t * KV_LORA + i] = h;
        g_ckvnl[(size_t)t * KV_LORA + i] = l;
    }

    if (threadIdx.x < ROPE / 2) {
        int i = threadIdx.x;
        float x1 = row[KV_LORA + 2 * i];
        float x2 = row[KV_LORA + 2 * i + 1];
        float f = freqs[(size_t)t * (ROPE / 2) + i];
        float c = cosf(f), sn = sinf(f);
        g_kpe[(size_t)t * ROPE + 2 * i]     = x1 * c - x2 * sn;
        g_kpe[(size_t)t * ROPE + 2 * i + 1] = x1 * sn + x2 * c;
    }
}

// assemble per-head split-bf16 Q/K/V for the mma attention (token range [t0, t0+grid))
__global__ __launch_bounds__(256)
void assemble(const float* __restrict__ freqs, int t0)
{
    const int t = t0 + blockIdx.x;
    const int tid = threadIdx.x;
    for (int idx = tid; idx < NH * NOPE; idx += 256) {
        int hh = idx >> 7, d = idx & 127;
        size_t qk = ((size_t)hh * T_LEN + t) * QKD + d;
        __nv_bfloat16 h, l;
        split1(g_q[(size_t)t * NH * QKD + hh * QKD + d], h, l);
        g_aqh[qk] = h; g_aql[qk] = l;
        split1(g_kv[(size_t)t * NH * 256 + hh * 256 + d], h, l);
        g_akh[qk] = h; g_akl[qk] = l;
        size_t vv = ((size_t)hh * T_LEN + t) * VDIM + d;
        split1(g_kv[(size_t)t * NH * 256 + hh * 256 + 128 + d], h, l);
        g_avh[vv] = h; g_avl[vv] = l;
    }
    for (int idx = tid; idx < NH * (ROPE / 2); idx += 256) {
        int hh = idx >> 5, i = idx & 31;
        float f = freqs[(size_t)t * (ROPE / 2) + i];
        float c = cosf(f), sn = sinf(f);
        const float* qp = g_q + (size_t)t * NH * QKD + hh * QKD + NOPE;
        float x1 = qp[2 * i], x2 = qp[2 * i + 1];
        size_t base = ((size_t)hh * T_LEN + t) * QKD + NOPE;
        __nv_bfloat16 h, l;
        split1(x1 * c - x2 * sn, h, l);  g_aqh[base + 2*i] = h;   g_aql[base + 2*i] = l;
        split1(x1 * sn + x2 * c, h, l);  g_aqh[base + 2*i+1] = h; g_aql[base + 2*i+1] = l;
        split1(g_kpe[(size_t)t * ROPE + 2*i], h, l);     g_akh[base + 2*i] = h;   g_akl[base + 2*i] = l;
        split1(g_kpe[(size_t)t * ROPE + 2*i + 1], h, l); g_akh[base + 2*i+1] = h; g_akl[base + 2*i+1] = l;
    }
}

// ==================== tensor-core flash attention (q-block range param) ====================
#define BQ 128
#define BK 64
#define SQH 200
#define SVH 136
#define ATT_SMEM ((2 * BQ * SQH + 2 * BK * SQH + 2 * BK * SVH) * 2)

__global__ __launch_bounds__(256, 1)
void mla_attn_mma(int qstart)
{
    extern __shared__ char smraw[];
    const uint32_t sb  = smem_u32(smraw);
    const uint32_t uQh = sb;
    const uint32_t uQl = uQh + BQ * SQH * 2;
    const uint32_t uKh = uQl + BQ * SQH * 2;
    const uint32_t uKl = uKh + BK * SQH * 2;
    const uint32_t uVh = uKl + BK * SQH * 2;
    const uint32_t uVl = uVh + BK * SVH * 2;

    const int h  = blockIdx.x;
    const int qi = qstart + (int)gridDim.y - 1 - (int)blockIdx.y;  // heavy first
    const int q0 = qi * BQ;
    const int tid = threadIdx.x, wid = tid >> 5, lane = tid & 31;
    const int mrow = wid * 16;

    const __nv_bfloat16* gQh = g_aqh + ((size_t)h * T_LEN + q0) * QKD;
    const __nv_bfloat16* gQl = g_aql + ((size_t)h * T_LEN + q0) * QKD;
    const __nv_bfloat16* gKh = g_akh + (size_t)h * T_LEN * QKD;
    const __nv_bfloat16* gKl = g_akl + (size_t)h * T_LEN * QKD;
    const __nv_bfloat16* gVh = g_avh + (size_t)h * T_LEN * VDIM;
    const __nv_bfloat16* gVl = g_avl + (size_t)h * T_LEN * VDIM;

    for (int i = tid; i < BQ * 24; i += 256) {
        int r = i / 24, c = i % 24;
        uint32_t d = (uint32_t)(r * SQH + c * 8) * 2;
        CPA(uQh + d, (const char*)(gQh + (size_t)r * QKD + c * 8));
        CPA(uQl + d, (const char*)(gQl + (size_t)r * QKD + c * 8));
    }
    CPA_COMMIT();

    float Oa[16][4];
#pragma unroll
    for (int n = 0; n < 16; n++)
#pragma unroll
        for (int j = 0; j < 4; j++) Oa[n][j] = 0.f;
    float mr0 = -1e30f, mr1 = -1e30f, lr0 = 0.f, lr1 = 0.f;

    const uint32_t qa_base = uQh + (uint32_t)((mrow + (lane & 15)) * SQH + (lane >> 4) * 8) * 2;
    const uint32_t ql_rel  = BQ * SQH * 2;
    const int kb_row = ((lane >> 4) & 1) * 8 + (lane & 7);
    const int kb_kad = ((lane >> 3) & 1) * 8;
    const int va_row = lane & 15;
    const int va_cad = (lane >> 4) * 8;

    const int nkt = 2 * qi + 2;
    for (int kt = 0; kt < nkt; kt++) {
        for (int i = tid; i < BK * 24; i += 256) {
            int r = i / 24, c = i % 24;
            const size_t go = (size_t)(kt * BK + r) * QKD + c * 8;
            uint32_t d = (uint32_t)(r * SQH + c * 8) * 2;
            CPA(uKh + d, (const char*)(gKh + go));
            CPA(uKl + d, (const char*)(gKl + go));
        }
        for (int i = tid; i < BK * 16; i += 256) {
            int r = i / 16, c = i % 16;
            const size_t go = (size_t)(kt * BK + r) * VDIM + c * 8;
            uint32_t d = (uint32_t)(r * SVH + c * 8) * 2;
            CPA(uVh + d, (const char*)(gVh + go));
            CPA(uVl + d, (const char*)(gVl + go));
        }
        CPA_COMMIT();
        CPA_WAIT0();
        __syncthreads();

        const int kbase = kt * BK;
        const bool active = kbase <= (q0 + mrow + 15);
        if (active) {
            float Sa[8][4];
#pragma unroll
            for (int n = 0; n < 8; n++)
#pragma unroll
                for (int j = 0; j < 4; j++) Sa[n][j] = 0.f;

#pragma unroll
            for (int ks = 0; ks < 12; ks++) {
                uint32_t ah[4], al[4];
                const uint32_t qo = qa_base + ks * 32;
                LDSM_X4(ah[0], ah[1], ah[2], ah[3], qo);
                LDSM_X4(al[0], al[1], al[2], al[3], qo + ql_rel);
                uint32_t bh[8][2], bl[8][2];
#pragma unroll
                for (int np = 0; np < 4; np++) {
                    const uint32_t bo = (uint32_t)((np * 16 + kb_row) * SQH + ks * 16 + kb_kad) * 2;
                    LDSM_X4(bh[2*np][0], bh[2*np][1], bh[2*np+1][0], bh[2*np+1][1], uKh + bo);
                    LDSM_X4(bl[2*np][0], bl[2*np][1], bl[2*np+1][0], bl[2*np+1][1], uKl + bo);
                }
#pragma unroll
                for (int n = 0; n < 8; n++) MMA_BF16(Sa[n], ah, bh[n][0], bh[n][1]);
#pragma unroll
                for (int n = 0; n < 8; n++) MMA_BF16(Sa[n], ah, bl[n][0], bl[n][1]);
#pragma unroll
                for (int n = 0; n < 8; n++) MMA_BF16(Sa[n], al, bh[n][0], bh[n][1]);
            }

            const int r0g = q0 + mrow + (lane >> 2);
            const int r1g = r0g + 8;
            const bool needmask = (kbase + BK - 1) > (q0 + mrow);
            float tm0 = -INFINITY, tm1 = -INFINITY;
#pragma unroll
            for (int n = 0; n < 8; n++) {
                const int c0 = kbase + n * 8 + (lane & 3) * 2;
                float v0 = Sa[n][0] * SOFTSCALE, v1 = Sa[n][1] * SOFTSCALE;
                float v2 = Sa[n][2] * SOFTSCALE, v3 = Sa[n][3] * SOFTSCALE;
                if (needmask) {
                    if (c0     > r0g) v0 = -INFINITY;
                    if (c0 + 1 > r0g) v1 = -INFINITY;
                    if (c0     > r1g) v2 = -INFINITY;
                    if (c0 + 1 > r1g) v3 = -INFINITY;
                }
                Sa[n][0] = v0; Sa[n][1] = v1; Sa[n][2] = v2; Sa[n][3] = v3;
                tm0 = fmaxf(tm0, fmaxf(v0, v1));
                tm1 = fmaxf(tm1, fmaxf(v2, v3));
            }
            tm0 = fmaxf(tm0, __shfl_xor_sync(0xffffffffu, tm0, 1));
            tm0 = fmaxf(tm0, __shfl_xor_sync(0xffffffffu, tm0, 2));
            tm1 = fmaxf(tm1, __shfl_xor_sync(0xffffffffu, tm1, 1));
            tm1 = fmaxf(tm1, __shfl_xor_sync(0xffffffffu, tm1, 2));
            const float nm0 = fmaxf(mr0, tm0), nm1 = fmaxf(mr1, tm1);
            const float sc0 = __expf(mr0 - nm0), sc1 = __expf(mr1 - nm1);
            float rs0 = 0.f, rs1 = 0.f;
#pragma unroll
            for (int n = 0; n < 8; n++) {
                Sa[n][0] = __expf(Sa[n][0] - nm0); rs0 += Sa[n][0];
                Sa[n][1] = __expf(Sa[n][1] - nm0); rs0 += Sa[n][1];
                Sa[n][2] = __expf(Sa[n][2] - nm1); rs1 += Sa[n][2];
                Sa[n][3] = __expf(Sa[n][3] - nm1); rs1 += Sa[n][3];
            }
            rs0 += __shfl_xor_sync(0xffffffffu, rs0, 1);
            rs0 += __shfl_xor_sync(0xffffffffu, rs0, 2);
            rs1 += __shfl_xor_sync(0xffffffffu, rs1, 1);
            rs1 += __shfl_xor_sync(0xffffffffu, rs1, 2);
            lr0 = lr0 * sc0 + rs0;
            lr1 = lr1 * sc1 + rs1;
            mr0 = nm0; mr1 = nm1;
#pragma unroll
            for (int n = 0; n < 16; n++) {
                Oa[n][0] *= sc0; Oa[n][1] *= sc0;
                Oa[n][2] *= sc1; Oa[n][3] *= sc1;
            }

            uint32_t ph[4][4], pl[4][4];
#pragma unroll
            for (int kf = 0; kf < 4; kf++) {
                pack2(Sa[2*kf][0],   Sa[2*kf][1],   ph[kf][0], pl[kf][0]);
                pack2(Sa[2*kf][2],   Sa[2*kf][3],   ph[kf][1], pl[kf][1]);
                pack2(Sa[2*kf+1][0], Sa[2*kf+1][1], ph[kf][2], pl[kf][2]);
                pack2(Sa[2*kf+1][2], Sa[2*kf+1][3], ph[kf][3], pl[kf][3]);
            }

#pragma unroll
            for (int kf = 0; kf < 4; kf++) {
                uint32_t vbh[16][2], vbl[16][2];
#pragma unroll
                for (int np = 0; np < 8; np++) {
                    const uint32_t vo = (uint32_t)((kf * 16 + va_row) * SVH + np * 16 + va_cad) * 2;
                    LDSM_X4_T(vbh[2*np][0], vbh[2*np][1], vbh[2*np+1][0], vbh[2*np+1][1], uVh + vo);
                    LDSM_X4_T(vbl[2*np][0], vbl[2*np][1], vbl[2*np+1][0], vbl[2*np+1][1], uVl + vo);
                }
#pragma unroll
                for (int n = 0; n < 16; n++) MMA_BF16(Oa[n], ph[kf], vbh[n][0], vbh[n][1]);
#pragma unroll
                for (int n = 0; n < 16; n++) MMA_BF16(Oa[n], ph[kf], vbl[n][0], vbl[n][1]);
#pragma unroll
                for (int n = 0; n < 16; n++) MMA_BF16(Oa[n], pl[kf], vbh[n][0], vbh[n][1]);
            }
        }
        __syncthreads();
    }

    const float inv0 = 1.f / lr0, inv1 = 1.f / lr1;
    const int r0g = q0 + mrow + (lane >> 2);
#pragma unroll
    for (int n = 0; n < 16; n++) {
        const int col = h * VDIM + n * 8 + (lane & 3) * 2;
        __nv_bfloat16 h0, l0, h1, l1;
        split1(Oa[n][0] * inv0, h0, l0);
        split1(Oa[n][1] * inv0, h1, l1);
        *(__nv_bfloat162*)(g_yh + (size_t)r0g * DIMX + col) = __nv_bfloat162(h0, h1);
        *(__nv_bfloat162*)(g_yl + (size_t)r0g * DIMX + col) = __nv_bfloat162(l0, l1);
        split1(Oa[n][2] * inv1, h0, l0);
        split1(Oa[n][3] * inv1, h1, l1);
        *(__nv_bfloat162*)(g_yh + (size_t)(r0g + 8) * DIMX + col) = __nv_bfloat162(h0, h1);
        *(__nv_bfloat162*)(g_yl + (size_t)(r0g + 8) * DIMX + col) = __nv_bfloat162(l0, l1);
    }
}

// ==================== launch (multi-stream DAG inside graph capture) ====================
extern "C" void kernel_launch(void* const* d_in, const int* in_sizes, int n_in,
                              void* d_out, int out_size)
{
    const float* x        = (const float*)d_in[0];
    const float* freqs    = (const float*)d_in[1];
    const float* wq_a     = (const float*)d_in[3];
    const float* q_norm_w = (const float*)d_in[4];
    const float* wq_b     = (const float*)d_in[5];
    const float* wkv_a    = (const float*)d_in[6];
    const float* kv_norm_w= (const float*)d_in[7];
    const float* wkv_b    = (const float*)d_in[8];
    const float* wo       = (const float*)d_in[9];
    float* out = (float*)d_out;

    float *qakvf, *q_p, *kv_p;
    cudaGetSymbolAddress((void**)&qakvf, g_qakvf);
    cudaGetSymbolAddress((void**)&q_p,   g_q);
    cudaGetSymbolAddress((void**)&kv_p,  g_kv);

    __nv_bfloat16 *xh,*xl,*wabh,*wabl,*qah,*qal,*wqbh,*wqbl,
                  *ckvnh,*ckvnl,*wkvbh,*wkvbl,*yh,*yl,*woh,*wol;
    cudaGetSymbolAddress((void**)&xh, g_xh);     cudaGetSymbolAddress((void**)&xl, g_xl);
    cudaGetSymbolAddress((void**)&wabh, g_wabh); cudaGetSymbolAddress((void**)&wabl, g_wabl);
    cudaGetSymbolAddress((void**)&qah, g_qah);   cudaGetSymbolAddress((void**)&qal, g_qal);
    cudaGetSymbolAddress((void**)&wqbh, g_wqbh); cudaGetSymbolAddress((void**)&wqbl, g_wqbl);
    cudaGetSymbolAddress((void**)&ckvnh, g_ckvnh); cudaGetSymbolAddress((void**)&ckvnl, g_ckvnl);
    cudaGetSymbolAddress((void**)&wkvbh, g_wkvbh); cudaGetSymbolAddress((void**)&wkvbl, g_wkvbl);
    cudaGetSymbolAddress((void**)&yh, g_yh);     cudaGetSymbolAddress((void**)&yl, g_yl);
    cudaGetSymbolAddress((void**)&woh, g_woh);   cudaGetSymbolAddress((void**)&wol, g_wol);

    cudaFuncSetAttribute(gemm_mma, cudaFuncAttributeMaxDynamicSharedMemorySize, GEMM_SMEM);
    cudaFuncSetAttribute(mla_attn_mma, cudaFuncAttributeMaxDynamicSharedMemorySize, ATT_SMEM);

    static cudaStream_t s1 = nullptr, s2 = nullptr;
    static cudaEvent_t eFork, eWab, eWqb, eWkvb, eWo, eG1, eG2, eG3, eAsmL, eAL, eAH;
    if (!s1) {
        cudaStreamCreateWithFlags(&s1, cudaStreamNonBlocking);
        cudaStreamCreateWithFlags(&s2, cudaStreamNonBlocking);
        cudaEventCreateWithFlags(&eFork, cudaEventDisableTiming);
        cudaEventCreateWithFlags(&eWab,  cudaEventDisableTiming);
        cudaEventCreateWithFlags(&eWqb,  cudaEventDisableTiming);
        cudaEventCreateWithFlags(&eWkvb, cudaEventDisableTiming);
        cudaEventCreateWithFlags(&eWo,   cudaEventDisableTiming);
        cudaEventCreateWithFlags(&eG1,   cudaEventDisableTiming);
        cudaEventCreateWithFlags(&eG2,   cudaEventDisableTiming);
        cudaEventCreateWithFlags(&eG3,   cudaEventDisableTiming);
        cudaEventCreateWithFlags(&eAsmL, cudaEventDisableTiming);
        cudaEventCreateWithFlags(&eAL,   cudaEventDisableTiming);
        cudaEventCreateWithFlags(&eAH,   cudaEventDisableTiming);
    }

    dim3 blk256(256);
    auto splits = [&](cudaStream_t st, const float* src, __nv_bfloat16* h,
                      __nv_bfloat16* l, size_t n) {
        int n4 = (int)(n / 4);
        split_bf16<<<(n4 + 255) / 256, 256, 0, st>>>(src, h, l, n4);
    };

    // fork side streams
    cudaEventRecord(eFork, 0);
    cudaStreamWaitEvent(s1, eFork, 0);
    cudaStreamWaitEvent(s2, eFork, 0);

    // s1: weight splits
    splits(s1, wq_a, wabh, wabl, (size_t)Q_LORA * DIMX);
    splits(s1, wkv_a, wabh + (size_t)Q_LORA * DIMX, wabl + (size_t)Q_LORA * DIMX,
           (size_t)KVA_OUT * DIMX);
    cudaEventRecord(eWab, s1);
    splits(s1, wq_b, wqbh, wqbl, (size_t)NH * QKD * Q_LORA);
    cudaEventRecord(eWqb, s1);
    splits(s1, wkv_b, wkvbh, wkvbl, (size_t)4096 * KV_LORA);
    cudaEventRecord(eWkvb, s1);
    splits(s1, wo, woh, wol, (size_t)DIMX * DIMX);
    cudaEventRecord(eWo, s1);

    // s0: x split -> fused qa|kvf GEMM
    splits(0, x, xh, xl, (size_t)T_LEN * DIMX);
    cudaStreamWaitEvent(0, eWab, 0);
    gemm_mma<<<dim3((NAB + 127) / 128, T_LEN / 128), blk256, GEMM_SMEM>>>(
        xh, xl, wabh, wabl, qakvf, T_LEN, NAB, DIMX);
    cudaEventRecord(eG1, 0);

    // s0: q path
    rmsnorm_split_qa<<<T_LEN, blk256>>>(q_norm_w);
    cudaStreamWaitEvent(0, eWqb, 0);
    gemm_mma<<<dim3(NH * QKD / 128, T_LEN / 128), blk256, GEMM_SMEM>>>(
        qah, qal, wqbh, wqbl, q_p, T_LEN, NH * QKD, Q_LORA);
    cudaEventRecord(eG2, 0);

    // s2: kv path (concurrent with q path)
    cudaStreamWaitEvent(s2, eG1, 0);
    kv_prep<<<T_LEN, blk256, 0, s2>>>(kv_norm_w, freqs);
    cudaStreamWaitEvent(s2, eWkvb, 0);
    gemm_mma<<<dim3(4096 / 128, T_LEN / 128), blk256, GEMM_SMEM, s2>>>(
        ckvnh, ckvnl, wkvbh, wkvbl, kv_p, T_LEN, 4096, KV_LORA);
    cudaEventRecord(eG3, s2);

    // s0: assemble low half (needs gemm2 on s0 + gemm3 via eG3)
    cudaStreamWaitEvent(0, eG3, 0);
    assemble<<<T_LEN / 2, blk256>>>(freqs, 0);
    cudaEventRecord(eAsmL, 0);
    // s2: assemble high half (needs gemm3 on s2 + gemm2 via eG2)
    cudaStreamWaitEvent(s2, eG2, 0);
    assemble<<<T_LEN / 2, blk256, 0, s2>>>(freqs, T_LEN / 2);

    // s0: attention low (q blocks 0..7) right after assembleLow
    mla_attn_mma<<<dim3(NH, 8), blk256, ATT_SMEM>>>(0);
    cudaEventRecord(eAL, 0);

    // s2: attention high (q blocks 8..15) needs assembleLow too (K/V rows < 1024)
    cudaStreamWaitEvent(s2, eAsmL, 0);
    mla_attn_mma<<<dim3(NH, 8), blk256, ATT_SMEM, s2>>>(8);
    cudaEventRecord(eAH, s2);

    // s0: gemm4 low rows (fills attention-high tail), then gemm4 high rows
    cudaStreamWaitEvent(0, eWo, 0);
    gemm_mma<<<dim3(DIMX / 128, (T_LEN / 2) / 128), blk256, GEMM_SMEM>>>(
        yh, yl, woh, wol, out, T_LEN / 2, DIMX, NH * VDIM);
    cudaStreamWaitEvent(0, eAH, 0);
    gemm_mma<<<dim3(DIMX / 128, (T_LEN / 2) / 128), blk256, GEMM_SMEM>>>(
        yh + (size_t)(T_LEN / 2) * DIMX, yl + (size_t)(T_LEN / 2) * DIMX,
        woh, wol, out + (size_t)(T_LEN / 2) * DIMX, T_LEN / 2, DIMX, NH * VDIM);
}

// round 14
// speedup vs baseline: 3.8392x; 1.0361x over previous
#include <cuda_runtime.h>
#include <cuda_bf16.h>
#include <cuda_fp16.h>
#include <math.h>
#include <cstdint>

// Problem constants
#define T_LEN 2048
#define DIMX 2048
#define NH 16
#define NOPE 128
#define ROPE 64
#define VDIM 128
#define QKD 192
#define Q_LORA 768
#define KV_LORA 512
#define KVA_OUT 576
#define NAB (Q_LORA + KVA_OUT)
#define SOFTSCALE (-96.0f)
#define EPS 1e-6f

// ==================== scratch ====================
__device__ float g_qakvf[(size_t)T_LEN * NAB];
__device__ float g_q   [(size_t)T_LEN * NH * QKD];
__device__ float g_kpe [(size_t)T_LEN * ROPE];
__device__ float g_kv  [(size_t)T_LEN * NH * (NOPE + VDIM)];

// bf16 split buffers (hi/lo)
__device__ __nv_bfloat16 g_xh [(size_t)T_LEN * DIMX],      g_xl [(size_t)T_LEN * DIMX];
__device__ __nv_bfloat16 g_wabh[(size_t)NAB * DIMX],       g_wabl[(size_t)NAB * DIMX];
__device__ __nv_bfloat16 g_qah[(size_t)T_LEN * Q_LORA],    g_qal[(size_t)T_LEN * Q_LORA];
__device__ __nv_bfloat16 g_wqbh[(size_t)NH * QKD * Q_LORA],g_wqbl[(size_t)NH * QKD * Q_LORA];
__device__ __nv_bfloat16 g_ckvnh[(size_t)T_LEN * KV_LORA], g_ckvnl[(size_t)T_LEN * KV_LORA];
__device__ __nv_bfloat16 g_wkvbh[(size_t)4096 * KV_LORA],  g_wkvbl[(size_t)4096 * KV_LORA];

// fp16 buffers for the terminal GEMM (2-pass scheme)
__device__ __half g_yhH[(size_t)T_LEN * DIMX], g_ylH[(size_t)T_LEN * DIMX];
__device__ __half g_woF[(size_t)DIMX * DIMX];

// attention bf16 split operands, per-head layout
__device__ __nv_bfloat16 g_aqh[(size_t)NH * T_LEN * QKD], g_aql[(size_t)NH * T_LEN * QKD];
__device__ __nv_bfloat16 g_akh[(size_t)NH * T_LEN * QKD], g_akl[(size_t)NH * T_LEN * QKD];
__device__ __nv_bfloat16 g_avh[(size_t)NH * T_LEN * VDIM], g_avl[(size_t)NH * T_LEN * VDIM];

// ==================== PTX helpers ====================
__device__ __forceinline__ uint32_t smem_u32(const void* p) {
    uint32_t a;
    asm("{ .reg .u64 t; cvta.to.shared.u64 t, %1; cvt.u32.u64 %0, t; }" : "=r"(a) : "l"(p));
    return a;
}
#define CPA(dst, src) \
    asm volatile("cp.async.cg.shared.global [%0], [%1], 16;" :: "r"(dst), "l"(src))
#define CPA_SZ(dst, src, sz) \
    asm volatile("cp.async.cg.shared.global [%0], [%1], 16, %2;" :: "r"(dst), "l"(src), "r"(sz))
#define CPA_COMMIT() asm volatile("cp.async.commit_group;" ::: "memory")
#define CPA_WAIT1()  asm volatile("cp.async.wait_group 1;" ::: "memory")
#define CPA_WAIT0()  asm volatile("cp.async.wait_group 0;" ::: "memory")

#define LDSM_X4(r0, r1, r2, r3, addr) \
    asm volatile("ldmatrix.sync.aligned.m8n8.x4.shared.b16 {%0,%1,%2,%3}, [%4];" \
        : "=r"(r0), "=r"(r1), "=r"(r2), "=r"(r3) : "r"(addr))
#define LDSM_X4_T(r0, r1, r2, r3, addr) \
    asm volatile("ldmatrix.sync.aligned.m8n8.x4.trans.shared.b16 {%0,%1,%2,%3}, [%4];" \
        : "=r"(r0), "=r"(r1), "=r"(r2), "=r"(r3) : "r"(addr))

#define MMA_BF16(d, a, b0, b1) \
    asm volatile("mma.sync.aligned.m16n8k16.row.col.f32.bf16.bf16.f32 " \
        "{%0,%1,%2,%3}, {%4,%5,%6,%7}, {%8,%9}, {%0,%1,%2,%3};" \
        : "+f"((d)[0]), "+f"((d)[1]), "+f"((d)[2]), "+f"((d)[3]) \
        : "r"((a)[0]), "r"((a)[1]), "r"((a)[2]), "r"((a)[3]), "r"(b0), "r"(b1))
#define MMA_F16(d, a, b0, b1) \
    asm volatile("mma.sync.aligned.m16n8k16.row.col.f32.f16.f16.f32 " \
        "{%0,%1,%2,%3}, {%4,%5,%6,%7}, {%8,%9}, {%0,%1,%2,%3};" \
        : "+f"((d)[0]), "+f"((d)[1]), "+f"((d)[2]), "+f"((d)[3]) \
        : "r"((a)[0]), "r"((a)[1]), "r"((a)[2]), "r"((a)[3]), "r"(b0), "r"(b1))

__device__ __forceinline__ void split1(float v, __nv_bfloat16& h, __nv_bfloat16& l) {
    h = __float2bfloat16(v);
    l = __float2bfloat16(v - __bfloat162float(h));
}
__device__ __forceinline__ void split1h(float v, __half& h, __half& l) {
    h = __float2half(v);
    l = __float2half(v - __half2float(h));
}
__device__ __forceinline__ void pack2(float x, float y, uint32_t& hi, uint32_t& lo) {
    __nv_bfloat16 hx, lx, hy, ly;
    split1(x, hx, lx); split1(y, hy, ly);
    __nv_bfloat162 H(hx, hy), L(lx, ly);
    hi = *(uint32_t*)&H; lo = *(uint32_t*)&L;
}

// ==================== split fp32 -> bf16 hi/lo ====================
__global__ __launch_bounds__(256)
void split_bf16(const float* __restrict__ in, __nv_bfloat16* __restrict__ hi,
                __nv_bfloat16* __restrict__ lo, int n4)
{
    int i = blockIdx.x * 256 + threadIdx.x;
    if (i >= n4) return;
    float4 v = ((const float4*)in)[i];
    __nv_bfloat16 h0, h1, h2, h3, l0, l1, l2, l3;
    split1(v.x, h0, l0); split1(v.y, h1, l1);
    split1(v.z, h2, l2); split1(v.w, h3, l3);
    ((__nv_bfloat162*)hi)[i * 2 + 0] = __nv_bfloat162(h0, h1);
    ((__nv_bfloat162*)hi)[i * 2 + 1] = __nv_bfloat162(h2, h3);
    ((__nv_bfloat162*)lo)[i * 2 + 0] = __nv_bfloat162(l0, l1);
    ((__nv_bfloat162*)lo)[i * 2 + 1] = __nv_bfloat162(l2, l3);
}

// convert fp32 -> single fp16
__global__ __launch_bounds__(256)
void conv_fp16(const float* __restrict__ in, __half* __restrict__ o, int n4)
{
    int i = blockIdx.x * 256 + threadIdx.x;
    if (i >= n4) return;
    float4 v = ((const float4*)in)[i];
    ((__half2*)o)[i * 2 + 0] = __half2(__float2half(v.x), __float2half(v.y));
    ((__half2*)o)[i * 2 + 1] = __half2(__float2half(v.z), __float2half(v.w));
}

// ==================== split-bf16 GEMM (3-pass), 8 warps x (64x32) ====================
#define SH 40
#define TILE_HB (128 * SH * 2)
#define STG_B   (4 * TILE_HB)
#define GEMM_SMEM (2 * STG_B)

__global__ __launch_bounds__(256, 1)
void gemm_mma(const __nv_bfloat16* __restrict__ Ah, const __nv_bfloat16* __restrict__ Al,
              const __nv_bfloat16* __restrict__ Bh, const __nv_bfloat16* __restrict__ Bl,
              float* __restrict__ C, int M, int N, int K)
{
    extern __shared__ char sm[];
    const uint32_t sb = smem_u32(sm);
    const int tid  = threadIdx.x;
    const int wid  = tid >> 5, lane = tid & 31;
    const int wm   = wid & 1;
    const int wn   = wid >> 1;
    const int bm   = blockIdx.y * 128, bn = blockIdx.x * 128;

    const int lrow = tid >> 1;
    const int lpart = tid & 1;
    const __nv_bfloat16* pAh = Ah + (size_t)(bm + lrow) * K;
    const __nv_bfloat16* pAl = Al + (size_t)(bm + lrow) * K;
    const int brow_raw = bn + lrow;
    const bool bval = brow_raw < N;
    const int brow = bval ? brow_raw : 0;
    const __nv_bfloat16* pBh = Bh + (size_t)brow * K;
    const __nv_bfloat16* pBl = Bl + (size_t)brow * K;
    const uint32_t bsz = bval ? 16u : 0u;
    const uint32_t dofs = (uint32_t)lrow * (SH * 2) + lpart * 32;

    auto issue = [&](int c, int buf) {
        const int ho = c * 32 + lpart * 16;
        const uint32_t stg = sb + buf * STG_B;
        const char* sAh = (const char*)(pAh + ho);
        const char* sAl = (const char*)(pAl + ho);
        const char* sBh = (const char*)(pBh + ho);
        const char* sBl = (const char*)(pBl + ho);
        const uint32_t d0 = stg + 0 * TILE_HB + dofs;
        const uint32_t d1 = stg + 1 * TILE_HB + dofs;
        const uint32_t d2 = stg + 2 * TILE_HB + dofs;
        const uint32_t d3 = stg + 3 * TILE_HB + dofs;
        CPA(d0, sAh);           CPA(d0 + 16, sAh + 16);
        CPA(d1, sAl);           CPA(d1 + 16, sAl + 16);
        CPA_SZ(d2, sBh, bsz);   CPA_SZ(d2 + 16, sBh + 16, bsz);
        CPA_SZ(d3, sBl, bsz);   CPA_SZ(d3 + 16, sBl + 16, bsz);
    };

    float acc[4][4][4];
#pragma unroll
    for (int i = 0; i < 4; i++)
#pragma unroll
        for (int j = 0; j < 4; j++)
#pragma unroll
            for (int q = 0; q < 4; q++) acc[i][j][q] = 0.f;

    const int arow = wm * 64 + (lane & 15);
    const int akad = (lane >> 4) * 8;
    const int brow_l = wn * 32 + ((lane >> 4) & 1) * 8 + (lane & 7);
    const int bkad  = ((lane >> 3) & 1) * 8;

    const int NC = K / 32;
    issue(0, 0); CPA_COMMIT();
    issue(1, 1); CPA_COMMIT();

    for (int c = 0; c < NC; c++) {
        CPA_WAIT1();
        __syncthreads();
        const uint32_t stg = sb + (c & 1) * STG_B;
        const uint32_t aB_h = stg + 0 * TILE_HB;
        const uint32_t aB_l = stg + 1 * TILE_HB;
        const uint32_t bB_h = stg + 2 * TILE_HB;
        const uint32_t bB_l = stg + 3 * TILE_HB;

#pragma unroll
        for (int kh = 0; kh < 2; kh++) {
            const int kofs = kh * 16;
            uint32_t ah[4][4], al[4][4];
#pragma unroll
            for (int mi = 0; mi < 4; mi++) {
                const uint32_t ao = (uint32_t)((arow + mi * 16) * SH + kofs + akad) * 2;
                LDSM_X4(ah[mi][0], ah[mi][1], ah[mi][2], ah[mi][3], aB_h + ao);
                LDSM_X4(al[mi][0], al[mi][1], al[mi][2], al[mi][3], aB_l + ao);
            }
            uint32_t bh[2][2][2], bl[2][2][2];
#pragma unroll
            for (int bt = 0; bt < 2; bt++) {
                const uint32_t bo = (uint32_t)((brow_l + bt * 16) * SH + kofs + bkad) * 2;
                LDSM_X4(bh[bt][0][0], bh[bt][0][1], bh[bt][1][0], bh[bt][1][1], bB_h + bo);
                LDSM_X4(bl[bt][0][0], bl[bt][0][1], bl[bt][1][0], bl[bt][1][1], bB_l + bo);
            }
#pragma unroll
            for (int mi = 0; mi < 4; mi++)
#pragma unroll
                for (int bt = 0; bt < 2; bt++) {
                    MMA_BF16(acc[mi][2*bt],   ah[mi], bh[bt][0][0], bh[bt][0][1]);
                    MMA_BF16(acc[mi][2*bt+1], ah[mi], bh[bt][1][0], bh[bt][1][1]);
                }
#pragma unroll
            for (int mi = 0; mi < 4; mi++)
#pragma unroll
                for (int bt = 0; bt < 2; bt++) {
                    MMA_BF16(acc[mi][2*bt],   ah[mi], bl[bt][0][0], bl[bt][0][1]);
                    MMA_BF16(acc[mi][2*bt+1], ah[mi], bl[bt][1][0], bl[bt][1][1]);
                }
#pragma unroll
            for (int mi = 0; mi < 4; mi++)
#pragma unroll
                for (int bt = 0; bt < 2; bt++) {
                    MMA_BF16(acc[mi][2*bt],   al[mi], bh[bt][0][0], bh[bt][0][1]);
                    MMA_BF16(acc[mi][2*bt+1], al[mi], bh[bt][1][0], bh[bt][1][1]);
                }
        }
        __syncthreads();
        if (c + 2 < NC) issue(c + 2, c & 1);
        CPA_COMMIT();
    }

    const int er = bm + wm * 64 + (lane >> 2);
    const int ec = bn + wn * 32 + (lane & 3) * 2;
#pragma unroll
    for (int mi = 0; mi < 4; mi++) {
#pragma unroll
        for (int ni = 0; ni < 4; ni++) {
            const int cc = ec + ni * 8;
            if (cc < N) {
                const int r0 = er + mi * 16;
                *(float2*)(C + (size_t)r0 * N + cc) =
                    make_float2(acc[mi][ni][0], acc[mi][ni][1]);
                *(float2*)(C + (size_t)(r0 + 8) * N + cc) =
                    make_float2(acc[mi][ni][2], acc[mi][ni][3]);
            }
        }
    }
}

// ==================== fp16 2-pass GEMM (terminal): C = (Ah+Al) * B^T ====================
#define STG2_B   (3 * TILE_HB)
#define GEMM2_SMEM (2 * STG2_B)

__global__ __launch_bounds__(256, 1)
void gemm_mma2(const __half* __restrict__ Ah, const __half* __restrict__ Al,
               const __half* __restrict__ B, float* __restrict__ C,
               int M, int N, int K)
{
    extern __shared__ char sm[];
    const uint32_t sb = smem_u32(sm);
    const int tid  = threadIdx.x;
    const int wid  = tid >> 5, lane = tid & 31;
    const int wm   = wid & 1;
    const int wn   = wid >> 1;
    const int bm   = blockIdx.y * 128, bn = blockIdx.x * 128;

    const int lrow = tid >> 1;
    const int lpart = tid & 1;
    const __half* pAh = Ah + (size_t)(bm + lrow) * K;
    const __half* pAl = Al + (size_t)(bm + lrow) * K;
    const __half* pB  = B  + (size_t)(bn + lrow) * K;
    const uint32_t dofs = (uint32_t)lrow * (SH * 2) + lpart * 32;

    auto issue = [&](int c, int buf) {
        const int ho = c * 32 + lpart * 16;
        const uint32_t stg = sb + buf * STG2_B;
        const char* sAh = (const char*)(pAh + ho);
        const char* sAl = (const char*)(pAl + ho);
        const char* sB  = (const char*)(pB + ho);
        const uint32_t d0 = stg + 0 * TILE_HB + dofs;
        const uint32_t d1 = stg + 1 * TILE_HB + dofs;
        const uint32_t d2 = stg + 2 * TILE_HB + dofs;
        CPA(d0, sAh);  CPA(d0 + 16, sAh + 16);
        CPA(d1, sAl);  CPA(d1 + 16, sAl + 16);
        CPA(d2, sB);   CPA(d2 + 16, sB + 16);
    };

    float acc[4][4][4];
#pragma unroll
    for (int i = 0; i < 4; i++)
#pragma unroll
        for (int j = 0; j < 4; j++)
#pragma unroll
            for (int q = 0; q < 4; q++) acc[i][j][q] = 0.f;

    const int arow = wm * 64 + (lane & 15);
    const int akad = (lane >> 4) * 8;
    const int brow_l = wn * 32 + ((lane >> 4) & 1) * 8 + (lane & 7);
    const int bkad  = ((lane >> 3) & 1) * 8;

    const int NC = K / 32;
    issue(0, 0); CPA_COMMIT();
    issue(1, 1); CPA_COMMIT();

    for (int c = 0; c < NC; c++) {
        CPA_WAIT1();
        __syncthreads();
        const uint32_t stg = sb + (c & 1) * STG2_B;
        const uint32_t aB_h = stg + 0 * TILE_HB;
        const uint32_t aB_l = stg + 1 * TILE_HB;
        const uint32_t bB   = stg + 2 * TILE_HB;

#pragma unroll
        for (int kh = 0; kh < 2; kh++) {
            const int kofs = kh * 16;
            uint32_t ah[4][4], al[4][4];
#pragma unroll
            for (int mi = 0; mi < 4; mi++) {
                const uint32_t ao = (uint32_t)((arow + mi * 16) * SH + kofs + akad) * 2;
                LDSM_X4(ah[mi][0], ah[mi][1], ah[mi][2], ah[mi][3], aB_h + ao);
                LDSM_X4(al[mi][0], al[mi][1], al[mi][2], al[mi][3], aB_l + ao);
            }
            uint32_t bb[2][2][2];
#pragma unroll
            for (int bt = 0; bt < 2; bt++) {
                const uint32_t bo = (uint32_t)((brow_l + bt * 16) * SH + kofs + bkad) * 2;
                LDSM_X4(bb[bt][0][0], bb[bt][0][1], bb[bt][1][0], bb[bt][1][1], bB + bo);
            }
#pragma unroll
            for (int mi = 0; mi < 4; mi++)
#pragma unroll
                for (int bt = 0; bt < 2; bt++) {
                    MMA_F16(acc[mi][2*bt],   ah[mi], bb[bt][0][0], bb[bt][0][1]);
                    MMA_F16(acc[mi][2*bt+1], ah[mi], bb[bt][1][0], bb[bt][1][1]);
                }
#pragma unroll
            for (int mi = 0; mi < 4; mi++)
#pragma unroll
                for (int bt = 0; bt < 2; bt++) {
                    MMA_F16(acc[mi][2*bt],   al[mi], bb[bt][0][0], bb[bt][0][1]);
                    MMA_F16(acc[mi][2*bt+1], al[mi], bb[bt][1][0], bb[bt][1][1]);
                }
        }
        __syncthreads();
        if (c + 2 < NC) issue(c + 2, c & 1);
        CPA_COMMIT();
    }

    const int er = bm + wm * 64 + (lane >> 2);
    const int ec = bn + wn * 32 + (lane & 3) * 2;
#pragma unroll
    for (int mi = 0; mi < 4; mi++) {
#pragma unroll
        for (int ni = 0; ni < 4; ni++) {
            const int cc = ec + ni * 8;
            const int r0 = er + mi * 16;
            *(float2*)(C + (size_t)r0 * N + cc) =
                make_float2(acc[mi][ni][0], acc[mi][ni][1]);
            *(float2*)(C + (size_t)(r0 + 8) * N + cc) =
                make_float2(acc[mi][ni][2], acc[mi][ni][3]);
        }
    }
}

// ==================== elementwise ====================
__global__ __launch_bounds__(256)
void rmsnorm_split_qa(const float* __restrict__ w)
{
    __shared__ float red[256];
    __shared__ float s_inv;
    const int t = blockIdx.x;
    const float* row = g_qakvf + (size_t)t * NAB;
    float s = 0.f;
    for (int i = threadIdx.x; i < Q_LORA; i += 256) { float v = row[i]; s = fmaf(v, v, s); }
    red[threadIdx.x] = s; __syncthreads();
    for (int st = 128; st > 0; st >>= 1) {
        if (threadIdx.x < st) red[threadIdx.x] += red[threadIdx.x + st];
        __syncthreads();
    }
    if (threadIdx.x == 0) s_inv = rsqrtf(red[0] / (float)Q_LORA + EPS);
    __syncthreads();
    const float inv = s_inv;
    for (int i = threadIdx.x; i < Q_LORA; i += 256) {
        float v = row[i] * inv * w[i];
        __nv_bfloat16 h, l; split1(v, h, l);
        g_qah[(size_t)t * Q_LORA + i] = h;
        g_qal[(size_t)t * Q_LORA + i] = l;
    }
}

__global__ __launch_bounds__(256)
void kv_prep(const float* __restrict__ w, const float* __restrict__ freqs)
{
    __shared__ float red[256];
    __shared__ float s_inv;
    const int t = blockIdx.x;
    const float* row = g_qakvf + (size_t)t * NAB + Q_LORA;
    float s = 0.f;
    for (int i = threadIdx.x; i < KV_LORA; i += 256) { float v = row[i]; s = fmaf(v, v, s); }
    red[threadIdx.x] = s; __syncthreads();
    for (int st = 128; st > 0; st >>= 1) {
        if (threadIdx.x < st) red[threadIdx.x] += red[threadIdx.x + st];
        __syncthreads();
    }
    if (threadIdx.x == 0) s_inv = rsqrtf(red[0] / (float)KV_LORA + EPS);
    __syncthreads();
    const float inv = s_inv;
    for (int i = threadIdx.x; i < KV_LORA; i += 256) {
        float v = row[i] * inv * w[i];
        __nv_bfloat16 h, l; split1(v, h, l);
        g_ckvnh[(size_t)t * KV_LORA + i] = h;
        g_ckvnl[(size_t)t * KV_LORA + i] = l;
    }

    if (threadIdx.x < ROPE / 2) {
        int i = threadIdx.x;
        float x1 = row[KV_LORA + 2 * i];
        float x2 = row[KV_LORA + 2 * i + 1];
        float f = freqs[(size_t)t * (ROPE / 2) + i];
        float c = cosf(f), sn = sinf(f);
        g_kpe[(size_t)t * ROPE + 2 * i]     = x1 * c - x2 * sn;
        g_kpe[(size_t)t * ROPE + 2 * i + 1] = x1 * sn + x2 * c;
    }
}

__global__ __launch_bounds__(256)
void assemble(const float* __restrict__ freqs, int t0)
{
    const int t = t0 + blockIdx.x;
    const int tid = threadIdx.x;
    for (int idx = tid; idx < NH * NOPE; idx += 256) {
        int hh = idx >> 7, d = idx & 127;
        size_t qk = ((size_t)hh * T_LEN + t) * QKD + d;
        __nv_bfloat16 h, l;
        split1(g_q[(size_t)t * NH * QKD + hh * QKD + d], h, l);
        g_aqh[qk] = h; g_aql[qk] = l;
        split1(g_kv[(size_t)t * NH * 256 + hh * 256 + d], h, l);
        g_akh[qk] = h; g_akl[qk] = l;
        size_t vv = ((size_t)hh * T_LEN + t) * VDIM + d;
        split1(g_kv[(size_t)t * NH * 256 + hh * 256 + 128 + d], h, l);
        g_avh[vv] = h; g_avl[vv] = l;
    }
    for (int idx = tid; idx < NH * (ROPE / 2); idx += 256) {
        int hh = idx >> 5, i = idx & 31;
        float f = freqs[(size_t)t * (ROPE / 2) + i];
        float c = cosf(f), sn = sinf(f);
        const float* qp = g_q + (size_t)t * NH * QKD + hh * QKD + NOPE;
        float x1 = qp[2 * i], x2 = qp[2 * i + 1];
        size_t base = ((size_t)hh * T_LEN + t) * QKD + NOPE;
        __nv_bfloat16 h, l;
        split1(x1 * c - x2 * sn, h, l);  g_aqh[base + 2*i] = h;   g_aql[base + 2*i] = l;
        split1(x1 * sn + x2 * c, h, l);  g_aqh[base + 2*i+1] = h; g_aql[base + 2*i+1] = l;
        split1(g_kpe[(size_t)t * ROPE + 2*i], h, l);     g_akh[base + 2*i] = h;   g_akl[base + 2*i] = l;
        split1(g_kpe[(size_t)t * ROPE + 2*i + 1], h, l); g_akh[base + 2*i+1] = h; g_akl[base + 2*i+1] = l;
    }
}

// ==================== tensor-core flash attention ====================
#define BQ 128
#define BK 64
#define SQH 200
#define SVH 136
#define ATT_SMEM ((2 * BQ * SQH + 2 * BK * SQH + 2 * BK * SVH) * 2)

__global__ __launch_bounds__(256, 1)
void mla_attn_mma(int qstart)
{
    extern __shared__ char smraw[];
    const uint32_t sb  = smem_u32(smraw);
    const uint32_t uQh = sb;
    const uint32_t uQl = uQh + BQ * SQH * 2;
    const uint32_t uKh = uQl + BQ * SQH * 2;
    const uint32_t uKl = uKh + BK * SQH * 2;
    const uint32_t uVh = uKl + BK * SQH * 2;
    const uint32_t uVl = uVh + BK * SVH * 2;

    const int h  = blockIdx.x;
    const int qi = qstart + (int)gridDim.y - 1 - (int)blockIdx.y;
    const int q0 = qi * BQ;
    const int tid = threadIdx.x, wid = tid >> 5, lane = tid & 31;
    const int mrow = wid * 16;

    const __nv_bfloat16* gQh = g_aqh + ((size_t)h * T_LEN + q0) * QKD;
    const __nv_bfloat16* gQl = g_aql + ((size_t)h * T_LEN + q0) * QKD;
    const __nv_bfloat16* gKh = g_akh + (size_t)h * T_LEN * QKD;
    const __nv_bfloat16* gKl = g_akl + (size_t)h * T_LEN * QKD;
    const __nv_bfloat16* gVh = g_avh + (size_t)h * T_LEN * VDIM;
    const __nv_bfloat16* gVl = g_avl + (size_t)h * T_LEN * VDIM;

    for (int i = tid; i < BQ * 24; i += 256) {
        int r = i / 24, c = i % 24;
        uint32_t d = (uint32_t)(r * SQH + c * 8) * 2;
        CPA(uQh + d, (const char*)(gQh + (size_t)r * QKD + c * 8));
        CPA(uQl + d, (const char*)(gQl + (size_t)r * QKD + c * 8));
    }
    CPA_COMMIT();

    float Oa[16][4];
#pragma unroll
    for (int n = 0; n < 16; n++)
#pragma unroll
        for (int j = 0; j < 4; j++) Oa[n][j] = 0.f;
    float mr0 = -1e30f, mr1 = -1e30f, lr0 = 0.f, lr1 = 0.f;

    const uint32_t qa_base = uQh + (uint32_t)((mrow + (lane & 15)) * SQH + (lane >> 4) * 8) * 2;
    const uint32_t ql_rel  = BQ * SQH * 2;
    const int kb_row = ((lane >> 4) & 1) * 8 + (lane & 7);
    const int kb_kad = ((lane >> 3) & 1) * 8;
    const int va_row = lane & 15;
    const int va_cad = (lane >> 4) * 8;

    const int nkt = 2 * qi + 2;
    for (int kt = 0; kt < nkt; kt++) {
        for (int i = tid; i < BK * 24; i += 256) {
            int r = i / 24, c = i % 24;
            const size_t go = (size_t)(kt * BK + r) * QKD + c * 8;
            uint32_t d = (uint32_t)(r * SQH + c * 8) * 2;
            CPA(uKh + d, (const char*)(gKh + go));
            CPA(uKl + d, (const char*)(gKl + go));
        }
        for (int i = tid; i < BK * 16; i += 256) {
            int r = i / 16, c = i % 16;
            const size_t go = (size_t)(kt * BK + r) * VDIM + c * 8;
            uint32_t d = (uint32_t)(r * SVH + c * 8) * 2;
            CPA(uVh + d, (const char*)(gVh + go));
            CPA(uVl + d, (const char*)(gVl + go));
        }
        CPA_COMMIT();
        CPA_WAIT0();
        __syncthreads();

        const int kbase = kt * BK;
        const bool active = kbase <= (q0 + mrow + 15);
        if (active) {
            float Sa[8][4];
#pragma unroll
            for (int n = 0; n < 8; n++)
#pragma unroll
                for (int j = 0; j < 4; j++) Sa[n][j] = 0.f;

#pragma unroll
            for (int ks = 0; ks < 12; ks++) {
                uint32_t ah[4], al[4];
                const uint32_t qo = qa_base + ks * 32;
                LDSM_X4(ah[0], ah[1], ah[2], ah[3], qo);
                LDSM_X4(al[0], al[1], al[2], al[3], qo + ql_rel);
                uint32_t bh[8][2], bl[8][2];
#pragma unroll
                for (int np = 0; np < 4; np++) {
                    const uint32_t bo = (uint32_t)((np * 16 + kb_row) * SQH + ks * 16 + kb_kad) * 2;
                    LDSM_X4(bh[2*np][0], bh[2*np][1], bh[2*np+1][0], bh[2*np+1][1], uKh + bo);
                    LDSM_X4(bl[2*np][0], bl[2*np][1], bl[2*np+1][0], bl[2*np+1][1], uKl + bo);
                }
#pragma unroll
                for (int n = 0; n < 8; n++) MMA_BF16(Sa[n], ah, bh[n][0], bh[n][1]);
#pragma unroll
                for (int n = 0; n < 8; n++) MMA_BF16(Sa[n], ah, bl[n][0], bl[n][1]);
#pragma unroll
                for (int n = 0; n < 8; n++) MMA_BF16(Sa[n], al, bh[n][0], bh[n][1]);
            }

            const int r0g = q0 + mrow + (lane >> 2);
            const int r1g = r0g + 8;
            const bool needmask = (kbase + BK - 1) > (q0 + mrow);
            float tm0 = -INFINITY, tm1 = -INFINITY;
#pragma unroll
            for (int n = 0; n < 8; n++) {
                const int c0 = kbase + n * 8 + (lane & 3) * 2;
                float v0 = Sa[n][0] * SOFTSCALE, v1 = Sa[n][1] * SOFTSCALE;
                float v2 = Sa[n][2] * SOFTSCALE, v3 = Sa[n][3] * SOFTSCALE;
                if (needmask) {
                    if (c0     > r0g) v0 = -INFINITY;
                    if (c0 + 1 > r0g) v1 = -INFINITY;
                    if (c0     > r1g) v2 = -INFINITY;
                    if (c0 + 1 > r1g) v3 = -INFINITY;
                }
                Sa[n][0] = v0; Sa[n][1] = v1; Sa[n][2] = v2; Sa[n][3] = v3;
                tm0 = fmaxf(tm0, fmaxf(v0, v1));
                tm1 = fmaxf(tm1, fmaxf(v2, v3));
            }
            tm0 = fmaxf(tm0, __shfl_xor_sync(0xffffffffu, tm0, 1));
            tm0 = fmaxf(tm0, __shfl_xor_sync(0xffffffffu, tm0, 2));
            tm1 = fmaxf(tm1, __shfl_xor_sync(0xffffffffu, tm1, 1));
            tm1 = fmaxf(tm1, __shfl_xor_sync(0xffffffffu, tm1, 2));
            const float nm0 = fmaxf(mr0, tm0), nm1 = fmaxf(mr1, tm1);
            const float sc0 = __expf(mr0 - nm0), sc1 = __expf(mr1 - nm1);
            float rs0 = 0.f, rs1 = 0.f;
#pragma unroll
            for (int n = 0; n < 8; n++) {
                Sa[n][0] = __expf(Sa[n][0] - nm0); rs0 += Sa[n][0];
                Sa[n][1] = __expf(Sa[n][1] - nm0); rs0 += Sa[n][1];
                Sa[n][2] = __expf(Sa[n][2] - nm1); rs1 += Sa[n][2];
                Sa[n][3] = __expf(Sa[n][3] - nm1); rs1 += Sa[n][3];
            }
            rs0 += __shfl_xor_sync(0xffffffffu, rs0, 1);
            rs0 += __shfl_xor_sync(0xffffffffu, rs0, 2);
            rs1 += __shfl_xor_sync(0xffffffffu, rs1, 1);
            rs1 += __shfl_xor_sync(0xffffffffu, rs1, 2);
            lr0 = lr0 * sc0 + rs0;
            lr1 = lr1 * sc1 + rs1;
            mr0 = nm0; mr1 = nm1;
#pragma unroll
            for (int n = 0; n < 16; n++) {
                Oa[n][0] *= sc0; Oa[n][1] *= sc0;
                Oa[n][2] *= sc1; Oa[n][3] *= sc1;
            }

            uint32_t ph[4][4], pl[4][4];
#pragma unroll
            for (int kf = 0; kf < 4; kf++) {
                pack2(Sa[2*kf][0],   Sa[2*kf][1],   ph[kf][0], pl[kf][0]);
                pack2(Sa[2*kf][2],   Sa[2*kf][3],   ph[kf][1], pl[kf][1]);
                pack2(Sa[2*kf+1][0], Sa[2*kf+1][1], ph[kf][2], pl[kf][2]);
                pack2(Sa[2*kf+1][2], Sa[2*kf+1][3], ph[kf][3], pl[kf][3]);
            }

#pragma unroll
            for (int kf = 0; kf < 4; kf++) {
                uint32_t vbh[16][2], vbl[16][2];
#pragma unroll
                for (int np = 0; np < 8; np++) {
                    const uint32_t vo = (uint32_t)((kf * 16 + va_row) * SVH + np * 16 + va_cad) * 2;
                    LDSM_X4_T(vbh[2*np][0], vbh[2*np][1], vbh[2*np+1][0], vbh[2*np+1][1], uVh + vo);
                    LDSM_X4_T(vbl[2*np][0], vbl[2*np][1], vbl[2*np+1][0], vbl[2*np+1][1], uVl + vo);
                }
#pragma unroll
                for (int n = 0; n < 16; n++) MMA_BF16(Oa[n], ph[kf], vbh[n][0], vbh[n][1]);
#pragma unroll
                for (int n = 0; n < 16; n++) MMA_BF16(Oa[n], ph[kf], vbl[n][0], vbl[n][1]);
#pragma unroll
                for (int n = 0; n < 16; n++) MMA_BF16(Oa[n], pl[kf], vbh[n][0], vbh[n][1]);
            }
        }
        __syncthreads();
    }

    // epilogue: normalize + fp16 hi/lo write for terminal GEMM
    const float inv0 = 1.f / lr0, inv1 = 1.f / lr1;
    const int r0g = q0 + mrow + (lane >> 2);
#pragma unroll
    for (int n = 0; n < 16; n++) {
        const int col = h * VDIM + n * 8 + (lane & 3) * 2;
        __half h0, l0, h1, l1;
        split1h(Oa[n][0] * inv0, h0, l0);
        split1h(Oa[n][1] * inv0, h1, l1);
        *(__half2*)(g_yhH + (size_t)r0g * DIMX + col) = __half2(h0, h1);
        *(__half2*)(g_ylH + (size_t)r0g * DIMX + col) = __half2(l0, l1);
        split1h(Oa[n][2] * inv1, h0, l0);
        split1h(Oa[n][3] * inv1, h1, l1);
        *(__half2*)(g_yhH + (size_t)(r0g + 8) * DIMX + col) = __half2(h0, h1);
        *(__half2*)(g_ylH + (size_t)(r0g + 8) * DIMX + col) = __half2(l0, l1);
    }
}

// ==================== launch (multi-stream DAG) ====================
extern "C" void kernel_launch(void* const* d_in, const int* in_sizes, int n_in,
                              void* d_out, int out_size)
{
    const float* x        = (const float*)d_in[0];
    const float* freqs    = (const float*)d_in[1];
    const float* wq_a     = (const float*)d_in[3];
    const float* q_norm_w = (const float*)d_in[4];
    const float* wq_b     = (const float*)d_in[5];
    const float* wkv_a    = (const float*)d_in[6];
    const float* kv_norm_w= (const float*)d_in[7];
    const float* wkv_b    = (const float*)d_in[8];
    const float* wo       = (const float*)d_in[9];
    float* out = (float*)d_out;

    float *qakvf, *q_p, *kv_p;
    cudaGetSymbolAddress((void**)&qakvf, g_qakvf);
    cudaGetSymbolAddress((void**)&q_p,   g_q);
    cudaGetSymbolAddress((void**)&kv_p,  g_kv);

    __nv_bfloat16 *xh,*xl,*wabh,*wabl,*qah,*qal,*wqbh,*wqbl,*ckvnh,*ckvnl,*wkvbh,*wkvbl;
    __half *yhH,*ylH,*woF;
    cudaGetSymbolAddress((void**)&xh, g_xh);     cudaGetSymbolAddress((void**)&xl, g_xl);
    cudaGetSymbolAddress((void**)&wabh, g_wabh); cudaGetSymbolAddress((void**)&wabl, g_wabl);
    cudaGetSymbolAddress((void**)&qah, g_qah);   cudaGetSymbolAddress((void**)&qal, g_qal);
    cudaGetSymbolAddress((void**)&wqbh, g_wqbh); cudaGetSymbolAddress((void**)&wqbl, g_wqbl);
    cudaGetSymbolAddress((void**)&ckvnh, g_ckvnh); cudaGetSymbolAddress((void**)&ckvnl, g_ckvnl);
    cudaGetSymbolAddress((void**)&wkvbh, g_wkvbh); cudaGetSymbolAddress((void**)&wkvbl, g_wkvbl);
    cudaGetSymbolAddress((void**)&yhH, g_yhH);   cudaGetSymbolAddress((void**)&ylH, g_ylH);
    cudaGetSymbolAddress((void**)&woF, g_woF);

    cudaFuncSetAttribute(gemm_mma, cudaFuncAttributeMaxDynamicSharedMemorySize, GEMM_SMEM);
    cudaFuncSetAttribute(gemm_mma2, cudaFuncAttributeMaxDynamicSharedMemorySize, GEMM2_SMEM);
    cudaFuncSetAttribute(mla_attn_mma, cudaFuncAttributeMaxDynamicSharedMemorySize, ATT_SMEM);

    static cudaStream_t s1 = nullptr, s2 = nullptr;
    static cudaEvent_t eFork, eWab, eWqb, eWkvb, eWo, eG1, eG2, eG3, eAsmL, eAH;
    if (!s1) {
        cudaStreamCreateWithFlags(&s1, cudaStreamNonBlocking);
        cudaStreamCreateWithFlags(&s2, cudaStreamNonBlocking);
        cudaEventCreateWithFlags(&eFork, cudaEventDisableTiming);
        cudaEventCreateWithFlags(&eWab,  cudaEventDisableTiming);
        cudaEventCreateWithFlags(&eWqb,  cudaEventDisableTiming);
        cudaEventCreateWithFlags(&eWkvb, cudaEventDisableTiming);
        cudaEventCreateWithFlags(&eWo,   cudaEventDisableTiming);
        cudaEventCreateWithFlags(&eG1,   cudaEventDisableTiming);
        cudaEventCreateWithFlags(&eG2,   cudaEventDisableTiming);
        cudaEventCreateWithFlags(&eG3,   cudaEventDisableTiming);
        cudaEventCreateWithFlags(&eAsmL, cudaEventDisableTiming);
        cudaEventCreateWithFlags(&eAH,   cudaEventDisableTiming);
    }

    dim3 blk256(256);
    auto splits = [&](cudaStream_t st, const float* src, __nv_bfloat16* h,
                      __nv_bfloat16* l, size_t n) {
        int n4 = (int)(n / 4);
        split_bf16<<<(n4 + 255) / 256, 256, 0, st>>>(src, h, l, n4);
    };

    cudaEventRecord(eFork, 0);
    cudaStreamWaitEvent(s1, eFork, 0);
    cudaStreamWaitEvent(s2, eFork, 0);

    // s1: weight splits/conversions
    splits(s1, wq_a, wabh, wabl, (size_t)Q_LORA * DIMX);
    splits(s1, wkv_a, wabh + (size_t)Q_LORA * DIMX, wabl + (size_t)Q_LORA * DIMX,
           (size_t)KVA_OUT * DIMX);
    cudaEventRecord(eWab, s1);
    splits(s1, wq_b, wqbh, wqbl, (size_t)NH * QKD * Q_LORA);
    cudaEventRecord(eWqb, s1);
    splits(s1, wkv_b, wkvbh, wkvbl, (size_t)4096 * KV_LORA);
    cudaEventRecord(eWkvb, s1);
    {
        int n4 = (int)((size_t)DIMX * DIMX / 4);
        conv_fp16<<<(n4 + 255) / 256, 256, 0, s1>>>(wo, woF, n4);
    }
    cudaEventRecord(eWo, s1);

    // s0: x split -> fused qa|kvf GEMM
    splits(0, x, xh, xl, (size_t)T_LEN * DIMX);
    cudaStreamWaitEvent(0, eWab, 0);
    gemm_mma<<<dim3((NAB + 127) / 128, T_LEN / 128), blk256, GEMM_SMEM>>>(
        xh, xl, wabh, wabl, qakvf, T_LEN, NAB, DIMX);
    cudaEventRecord(eG1, 0);

    // s0: q path
    rmsnorm_split_qa<<<T_LEN, blk256>>>(q_norm_w);
    cudaStreamWaitEvent(0, eWqb, 0);
    gemm_mma<<<dim3(NH * QKD / 128, T_LEN / 128), blk256, GEMM_SMEM>>>(
        qah, qal, wqbh, wqbl, q_p, T_LEN, NH * QKD, Q_LORA);
    cudaEventRecord(eG2, 0);

    // s2: kv path
    cudaStreamWaitEvent(s2, eG1, 0);
    kv_prep<<<T_LEN, blk256, 0, s2>>>(kv_norm_w, freqs);
    cudaStreamWaitEvent(s2, eWkvb, 0);
    gemm_mma<<<dim3(4096 / 128, T_LEN / 128), blk256, GEMM_SMEM, s2>>>(
        ckvnh, ckvnl, wkvbh, wkvbl, kv_p, T_LEN, 4096, KV_LORA);
    cudaEventRecord(eG3, s2);

    // assemble halves
    cudaStreamWaitEvent(0, eG3, 0);
    assemble<<<T_LEN / 2, blk256>>>(freqs, 0);
    cudaEventRecord(eAsmL, 0);
    cudaStreamWaitEvent(s2, eG2, 0);
    assemble<<<T_LEN / 2, blk256, 0, s2>>>(freqs, T_LEN / 2);

    // attention low on s0; attention high on s2
    mla_attn_mma<<<dim3(NH, 8), blk256, ATT_SMEM>>>(0);
    cudaStreamWaitEvent(s2, eAsmL, 0);
    mla_attn_mma<<<dim3(NH, 8), blk256, ATT_SMEM, s2>>>(8);
    cudaEventRecord(eAH, s2);

    // terminal fp16 2-pass GEMM, split rows
    cudaStreamWaitEvent(0, eWo, 0);
    gemm_mma2<<<dim3(DIMX / 128, (T_LEN / 2) / 128), blk256, GEMM2_SMEM>>>(
        yhH, ylH, woF, out, T_LEN / 2, DIMX, NH * VDIM);
    cudaStreamWaitEvent(0, eAH, 0);
    gemm_mma2<<<dim3(DIMX / 128, (T_LEN / 2) / 128), blk256, GEMM2_SMEM>>>(
        yhH + (size_t)(T_LEN / 2) * DIMX, ylH + (size_t)(T_LEN / 2) * DIMX,
        woF, out + (size_t)(T_LEN / 2) * DIMX, T_LEN / 2, DIMX, NH * VDIM);
}

// round 15
// speedup vs baseline: 3.9414x; 1.0266x over previous
#include <cuda_runtime.h>
#include <cuda_bf16.h>
#include <cuda_fp16.h>
#include <math.h>
#include <cstdint>

// Problem constants
#define T_LEN 2048
#define DIMX 2048
#define NH 16
#define NOPE 128
#define ROPE 64
#define VDIM 128
#define QKD 192
#define Q_LORA 768
#define KV_LORA 512
#define KVA_OUT 576
#define NAB (Q_LORA + KVA_OUT)
#define SOFTSCALE (-96.0f)
#define EPS 1e-6f

// ==================== scratch ====================
__device__ float g_qakvf[(size_t)T_LEN * NAB];
__device__ float g_q   [(size_t)T_LEN * NH * QKD];
__device__ float g_kpe [(size_t)T_LEN * ROPE];
__device__ float g_kv  [(size_t)T_LEN * NH * (NOPE + VDIM)];

// bf16 split buffers (hi/lo)
__device__ __nv_bfloat16 g_xh [(size_t)T_LEN * DIMX],      g_xl [(size_t)T_LEN * DIMX];
__device__ __nv_bfloat16 g_wabh[(size_t)NAB * DIMX],       g_wabl[(size_t)NAB * DIMX];
__device__ __nv_bfloat16 g_qah[(size_t)T_LEN * Q_LORA],    g_qal[(size_t)T_LEN * Q_LORA];
__device__ __nv_bfloat16 g_wqbh[(size_t)NH * QKD * Q_LORA],g_wqbl[(size_t)NH * QKD * Q_LORA];
__device__ __nv_bfloat16 g_ckvnh[(size_t)T_LEN * KV_LORA], g_ckvnl[(size_t)T_LEN * KV_LORA];
__device__ __nv_bfloat16 g_wkvbh[(size_t)4096 * KV_LORA],  g_wkvbl[(size_t)4096 * KV_LORA];

// fp16 buffers for the terminal GEMM (2-pass scheme)
__device__ __half g_yhH[(size_t)T_LEN * DIMX], g_ylH[(size_t)T_LEN * DIMX];
__device__ __half g_woF[(size_t)DIMX * DIMX];

// attention operands: Q/K bf16 split (logit path), V single fp16 (benign path)
__device__ __nv_bfloat16 g_aqh[(size_t)NH * T_LEN * QKD], g_aql[(size_t)NH * T_LEN * QKD];
__device__ __nv_bfloat16 g_akh[(size_t)NH * T_LEN * QKD], g_akl[(size_t)NH * T_LEN * QKD];
__device__ __half        g_avF[(size_t)NH * T_LEN * VDIM];

// ==================== PTX helpers ====================
__device__ __forceinline__ uint32_t smem_u32(const void* p) {
    uint32_t a;
    asm("{ .reg .u64 t; cvta.to.shared.u64 t, %1; cvt.u32.u64 %0, t; }" : "=r"(a) : "l"(p));
    return a;
}
#define CPA(dst, src) \
    asm volatile("cp.async.cg.shared.global [%0], [%1], 16;" :: "r"(dst), "l"(src))
#define CPA_SZ(dst, src, sz) \
    asm volatile("cp.async.cg.shared.global [%0], [%1], 16, %2;" :: "r"(dst), "l"(src), "r"(sz))
#define CPA_COMMIT() asm volatile("cp.async.commit_group;" ::: "memory")
#define CPA_WAIT1()  asm volatile("cp.async.wait_group 1;" ::: "memory")
#define CPA_WAIT0()  asm volatile("cp.async.wait_group 0;" ::: "memory")

#define LDSM_X4(r0, r1, r2, r3, addr) \
    asm volatile("ldmatrix.sync.aligned.m8n8.x4.shared.b16 {%0,%1,%2,%3}, [%4];" \
        : "=r"(r0), "=r"(r1), "=r"(r2), "=r"(r3) : "r"(addr))
#define LDSM_X4_T(r0, r1, r2, r3, addr) \
    asm volatile("ldmatrix.sync.aligned.m8n8.x4.trans.shared.b16 {%0,%1,%2,%3}, [%4];" \
        : "=r"(r0), "=r"(r1), "=r"(r2), "=r"(r3) : "r"(addr))

#define MMA_BF16(d, a, b0, b1) \
    asm volatile("mma.sync.aligned.m16n8k16.row.col.f32.bf16.bf16.f32 " \
        "{%0,%1,%2,%3}, {%4,%5,%6,%7}, {%8,%9}, {%0,%1,%2,%3};" \
        : "+f"((d)[0]), "+f"((d)[1]), "+f"((d)[2]), "+f"((d)[3]) \
        : "r"((a)[0]), "r"((a)[1]), "r"((a)[2]), "r"((a)[3]), "r"(b0), "r"(b1))
#define MMA_F16(d, a, b0, b1) \
    asm volatile("mma.sync.aligned.m16n8k16.row.col.f32.f16.f16.f32 " \
        "{%0,%1,%2,%3}, {%4,%5,%6,%7}, {%8,%9}, {%0,%1,%2,%3};" \
        : "+f"((d)[0]), "+f"((d)[1]), "+f"((d)[2]), "+f"((d)[3]) \
        : "r"((a)[0]), "r"((a)[1]), "r"((a)[2]), "r"((a)[3]), "r"(b0), "r"(b1))

__device__ __forceinline__ void split1(float v, __nv_bfloat16& h, __nv_bfloat16& l) {
    h = __float2bfloat16(v);
    l = __float2bfloat16(v - __bfloat162float(h));
}
__device__ __forceinline__ void split1h(float v, __half& h, __half& l) {
    h = __float2half(v);
    l = __float2half(v - __half2float(h));
}
__device__ __forceinline__ void pack2h(float x, float y, uint32_t& hi, uint32_t& lo) {
    __half hx, lx, hy, ly;
    split1h(x, hx, lx); split1h(y, hy, ly);
    __half2 H(hx, hy), L(lx, ly);
    hi = *(uint32_t*)&H; lo = *(uint32_t*)&L;
}

// ==================== split fp32 -> bf16 hi/lo ====================
__global__ __launch_bounds__(256)
void split_bf16(const float* __restrict__ in, __nv_bfloat16* __restrict__ hi,
                __nv_bfloat16* __restrict__ lo, int n4)
{
    int i = blockIdx.x * 256 + threadIdx.x;
    if (i >= n4) return;
    float4 v = ((const float4*)in)[i];
    __nv_bfloat16 h0, h1, h2, h3, l0, l1, l2, l3;
    split1(v.x, h0, l0); split1(v.y, h1, l1);
    split1(v.z, h2, l2); split1(v.w, h3, l3);
    ((__nv_bfloat162*)hi)[i * 2 + 0] = __nv_bfloat162(h0, h1);
    ((__nv_bfloat162*)hi)[i * 2 + 1] = __nv_bfloat162(h2, h3);
    ((__nv_bfloat162*)lo)[i * 2 + 0] = __nv_bfloat162(l0, l1);
    ((__nv_bfloat162*)lo)[i * 2 + 1] = __nv_bfloat162(l2, l3);
}

// convert fp32 -> single fp16
__global__ __launch_bounds__(256)
void conv_fp16(const float* __restrict__ in, __half* __restrict__ o, int n4)
{
    int i = blockIdx.x * 256 + threadIdx.x;
    if (i >= n4) return;
    float4 v = ((const float4*)in)[i];
    ((__half2*)o)[i * 2 + 0] = __half2(__float2half(v.x), __float2half(v.y));
    ((__half2*)o)[i * 2 + 1] = __half2(__float2half(v.z), __float2half(v.w));
}

// ==================== split-bf16 GEMM (3-pass), 8 warps x (64x32) ====================
#define SH 40
#define TILE_HB (128 * SH * 2)
#define STG_B   (4 * TILE_HB)
#define GEMM_SMEM (2 * STG_B)

__global__ __launch_bounds__(256, 1)
void gemm_mma(const __nv_bfloat16* __restrict__ Ah, const __nv_bfloat16* __restrict__ Al,
              const __nv_bfloat16* __restrict__ Bh, const __nv_bfloat16* __restrict__ Bl,
              float* __restrict__ C, int M, int N, int K)
{
    extern __shared__ char sm[];
    const uint32_t sb = smem_u32(sm);
    const int tid  = threadIdx.x;
    const int wid  = tid >> 5, lane = tid & 31;
    const int wm   = wid & 1;
    const int wn   = wid >> 1;
    const int bm   = blockIdx.y * 128, bn = blockIdx.x * 128;

    const int lrow = tid >> 1;
    const int lpart = tid & 1;
    const __nv_bfloat16* pAh = Ah + (size_t)(bm + lrow) * K;
    const __nv_bfloat16* pAl = Al + (size_t)(bm + lrow) * K;
    const int brow_raw = bn + lrow;
    const bool bval = brow_raw < N;
    const int brow = bval ? brow_raw : 0;
    const __nv_bfloat16* pBh = Bh + (size_t)brow * K;
    const __nv_bfloat16* pBl = Bl + (size_t)brow * K;
    const uint32_t bsz = bval ? 16u : 0u;
    const uint32_t dofs = (uint32_t)lrow * (SH * 2) + lpart * 32;

    auto issue = [&](int c, int buf) {
        const int ho = c * 32 + lpart * 16;
        const uint32_t stg = sb + buf * STG_B;
        const char* sAh = (const char*)(pAh + ho);
        const char* sAl = (const char*)(pAl + ho);
        const char* sBh = (const char*)(pBh + ho);
        const char* sBl = (const char*)(pBl + ho);
        const uint32_t d0 = stg + 0 * TILE_HB + dofs;
        const uint32_t d1 = stg + 1 * TILE_HB + dofs;
        const uint32_t d2 = stg + 2 * TILE_HB + dofs;
        const uint32_t d3 = stg + 3 * TILE_HB + dofs;
        CPA(d0, sAh);           CPA(d0 + 16, sAh + 16);
        CPA(d1, sAl);           CPA(d1 + 16, sAl + 16);
        CPA_SZ(d2, sBh, bsz);   CPA_SZ(d2 + 16, sBh + 16, bsz);
        CPA_SZ(d3, sBl, bsz);   CPA_SZ(d3 + 16, sBl + 16, bsz);
    };

    float acc[4][4][4];
#pragma unroll
    for (int i = 0; i < 4; i++)
#pragma unroll
        for (int j = 0; j < 4; j++)
#pragma unroll
            for (int q = 0; q < 4; q++) acc[i][j][q] = 0.f;

    const int arow = wm * 64 + (lane & 15);
    const int akad = (lane >> 4) * 8;
    const int brow_l = wn * 32 + ((lane >> 4) & 1) * 8 + (lane & 7);
    const int bkad  = ((lane >> 3) & 1) * 8;

    const int NC = K / 32;
    issue(0, 0); CPA_COMMIT();
    issue(1, 1); CPA_COMMIT();

    for (int c = 0; c < NC; c++) {
        CPA_WAIT1();
        __syncthreads();
        const uint32_t stg = sb + (c & 1) * STG_B;
        const uint32_t aB_h = stg + 0 * TILE_HB;
        const uint32_t aB_l = stg + 1 * TILE_HB;
        const uint32_t bB_h = stg + 2 * TILE_HB;
        const uint32_t bB_l = stg + 3 * TILE_HB;

#pragma unroll
        for (int kh = 0; kh < 2; kh++) {
            const int kofs = kh * 16;
            uint32_t ah[4][4], al[4][4];
#pragma unroll
            for (int mi = 0; mi < 4; mi++) {
                const uint32_t ao = (uint32_t)((arow + mi * 16) * SH + kofs + akad) * 2;
                LDSM_X4(ah[mi][0], ah[mi][1], ah[mi][2], ah[mi][3], aB_h + ao);
                LDSM_X4(al[mi][0], al[mi][1], al[mi][2], al[mi][3], aB_l + ao);
            }
            uint32_t bh[2][2][2], bl[2][2][2];
#pragma unroll
            for (int bt = 0; bt < 2; bt++) {
                const uint32_t bo = (uint32_t)((brow_l + bt * 16) * SH + kofs + bkad) * 2;
                LDSM_X4(bh[bt][0][0], bh[bt][0][1], bh[bt][1][0], bh[bt][1][1], bB_h + bo);
                LDSM_X4(bl[bt][0][0], bl[bt][0][1], bl[bt][1][0], bl[bt][1][1], bB_l + bo);
            }
#pragma unroll
            for (int mi = 0; mi < 4; mi++)
#pragma unroll
                for (int bt = 0; bt < 2; bt++) {
                    MMA_BF16(acc[mi][2*bt],   ah[mi], bh[bt][0][0], bh[bt][0][1]);
                    MMA_BF16(acc[mi][2*bt+1], ah[mi], bh[bt][1][0], bh[bt][1][1]);
                }
#pragma unroll
            for (int mi = 0; mi < 4; mi++)
#pragma unroll
                for (int bt = 0; bt < 2; bt++) {
                    MMA_BF16(acc[mi][2*bt],   ah[mi], bl[bt][0][0], bl[bt][0][1]);
                    MMA_BF16(acc[mi][2*bt+1], ah[mi], bl[bt][1][0], bl[bt][1][1]);
                }
#pragma unroll
            for (int mi = 0; mi < 4; mi++)
#pragma unroll
                for (int bt = 0; bt < 2; bt++) {
                    MMA_BF16(acc[mi][2*bt],   al[mi], bh[bt][0][0], bh[bt][0][1]);
                    MMA_BF16(acc[mi][2*bt+1], al[mi], bh[bt][1][0], bh[bt][1][1]);
                }
        }
        __syncthreads();
        if (c + 2 < NC) issue(c + 2, c & 1);
        CPA_COMMIT();
    }

    const int er = bm + wm * 64 + (lane >> 2);
    const int ec = bn + wn * 32 + (lane & 3) * 2;
#pragma unroll
    for (int mi = 0; mi < 4; mi++) {
#pragma unroll
        for (int ni = 0; ni < 4; ni++) {
            const int cc = ec + ni * 8;
            if (cc < N) {
                const int r0 = er + mi * 16;
                *(float2*)(C + (size_t)r0 * N + cc) =
                    make_float2(acc[mi][ni][0], acc[mi][ni][1]);
                *(float2*)(C + (size_t)(r0 + 8) * N + cc) =
                    make_float2(acc[mi][ni][2], acc[mi][ni][3]);
            }
        }
    }
}

// ==================== fp16 2-pass GEMM (terminal): C = (Ah+Al) * B^T ====================
#define STG2_B   (3 * TILE_HB)
#define GEMM2_SMEM (2 * STG2_B)

__global__ __launch_bounds__(256, 1)
void gemm_mma2(const __half* __restrict__ Ah, const __half* __restrict__ Al,
               const __half* __restrict__ B, float* __restrict__ C,
               int M, int N, int K)
{
    extern __shared__ char sm[];
    const uint32_t sb = smem_u32(sm);
    const int tid  = threadIdx.x;
    const int wid  = tid >> 5, lane = tid & 31;
    const int wm   = wid & 1;
    const int wn   = wid >> 1;
    const int bm   = blockIdx.y * 128, bn = blockIdx.x * 128;

    const int lrow = tid >> 1;
    const int lpart = tid & 1;
    const __half* pAh = Ah + (size_t)(bm + lrow) * K;
    const __half* pAl = Al + (size_t)(bm + lrow) * K;
    const __half* pB  = B  + (size_t)(bn + lrow) * K;
    const uint32_t dofs = (uint32_t)lrow * (SH * 2) + lpart * 32;

    auto issue = [&](int c, int buf) {
        const int ho = c * 32 + lpart * 16;
        const uint32_t stg = sb + buf * STG2_B;
        const char* sAh = (const char*)(pAh + ho);
        const char* sAl = (const char*)(pAl + ho);
        const char* sB  = (const char*)(pB + ho);
        const uint32_t d0 = stg + 0 * TILE_HB + dofs;
        const uint32_t d1 = stg + 1 * TILE_HB + dofs;
        const uint32_t d2 = stg + 2 * TILE_HB + dofs;
        CPA(d0, sAh);  CPA(d0 + 16, sAh + 16);
        CPA(d1, sAl);  CPA(d1 + 16, sAl + 16);
        CPA(d2, sB);   CPA(d2 + 16, sB + 16);
    };

    float acc[4][4][4];
#pragma unroll
    for (int i = 0; i < 4; i++)
#pragma unroll
        for (int j = 0; j < 4; j++)
#pragma unroll
            for (int q = 0; q < 4; q++) acc[i][j][q] = 0.f;

    const int arow = wm * 64 + (lane & 15);
    const int akad = (lane >> 4) * 8;
    const int brow_l = wn * 32 + ((lane >> 4) & 1) * 8 + (lane & 7);
    const int bkad  = ((lane >> 3) & 1) * 8;

    const int NC = K / 32;
    issue(0, 0); CPA_COMMIT();
    issue(1, 1); CPA_COMMIT();

    for (int c = 0; c < NC; c++) {
        CPA_WAIT1();
        __syncthreads();
        const uint32_t stg = sb + (c & 1) * STG2_B;
        const uint32_t aB_h = stg + 0 * TILE_HB;
        const uint32_t aB_l = stg + 1 * TILE_HB;
        const uint32_t bB   = stg + 2 * TILE_HB;

#pragma unroll
        for (int kh = 0; kh < 2; kh++) {
            const int kofs = kh * 16;
            uint32_t ah[4][4], al[4][4];
#pragma unroll
            for (int mi = 0; mi < 4; mi++) {
                const uint32_t ao = (uint32_t)((arow + mi * 16) * SH + kofs + akad) * 2;
                LDSM_X4(ah[mi][0], ah[mi][1], ah[mi][2], ah[mi][3], aB_h + ao);
                LDSM_X4(al[mi][0], al[mi][1], al[mi][2], al[mi][3], aB_l + ao);
            }
            uint32_t bb[2][2][2];
#pragma unroll
            for (int bt = 0; bt < 2; bt++) {
                const uint32_t bo = (uint32_t)((brow_l + bt * 16) * SH + kofs + bkad) * 2;
                LDSM_X4(bb[bt][0][0], bb[bt][0][1], bb[bt][1][0], bb[bt][1][1], bB + bo);
            }
#pragma unroll
            for (int mi = 0; mi < 4; mi++)
#pragma unroll
                for (int bt = 0; bt < 2; bt++) {
                    MMA_F16(acc[mi][2*bt],   ah[mi], bb[bt][0][0], bb[bt][0][1]);
                    MMA_F16(acc[mi][2*bt+1], ah[mi], bb[bt][1][0], bb[bt][1][1]);
                }
#pragma unroll
            for (int mi = 0; mi < 4; mi++)
#pragma unroll
                for (int bt = 0; bt < 2; bt++) {
                    MMA_F16(acc[mi][2*bt],   al[mi], bb[bt][0][0], bb[bt][0][1]);
                    MMA_F16(acc[mi][2*bt+1], al[mi], bb[bt][1][0], bb[bt][1][1]);
                }
        }
        __syncthreads();
        if (c + 2 < NC) issue(c + 2, c & 1);
        CPA_COMMIT();
    }

    const int er = bm + wm * 64 + (lane >> 2);
    const int ec = bn + wn * 32 + (lane & 3) * 2;
#pragma unroll
    for (int mi = 0; mi < 4; mi++) {
#pragma unroll
        for (int ni = 0; ni < 4; ni++) {
            const int cc = ec + ni * 8;
            const int r0 = er + mi * 16;
            *(float2*)(C + (size_t)r0 * N + cc) =
                make_float2(acc[mi][ni][0], acc[mi][ni][1]);
            *(float2*)(C + (size_t)(r0 + 8) * N + cc) =
                make_float2(acc[mi][ni][2], acc[mi][ni][3]);
        }
    }
}

// ==================== elementwise ====================
__global__ __launch_bounds__(256)
void rmsnorm_split_qa(const float* __restrict__ w)
{
    __shared__ float red[256];
    __shared__ float s_inv;
    const int t = blockIdx.x;
    const float* row = g_qakvf + (size_t)t * NAB;
    float s = 0.f;
    for (int i = threadIdx.x; i < Q_LORA; i += 256) { float v = row[i]; s = fmaf(v, v, s); }
    red[threadIdx.x] = s; __syncthreads();
    for (int st = 128; st > 0; st >>= 1) {
        if (threadIdx.x < st) red[threadIdx.x] += red[threadIdx.x + st];
        __syncthreads();
    }
    if (threadIdx.x == 0) s_inv = rsqrtf(red[0] / (float)Q_LORA + EPS);
    __syncthreads();
    const float inv = s_inv;
    for (int i = threadIdx.x; i < Q_LORA; i += 256) {
        float v = row[i] * inv * w[i];
        __nv_bfloat16 h, l; split1(v, h, l);
        g_qah[(size_t)t * Q_LORA + i] = h;
        g_qal[(size_t)t * Q_LORA + i] = l;
    }
}

__global__ __launch_bounds__(256)
void kv_prep(const float* __restrict__ w, const float* __restrict__ freqs)
{
    __shared__ float red[256];
    __shared__ float s_inv;
    const int t = blockIdx.x;
    const float* row = g_qakvf + (size_t)t * NAB + Q_LORA;
    float s = 0.f;
    for (int i = threadIdx.x; i < KV_LORA; i += 256) { float v = row[i]; s = fmaf(v, v, s); }
    red[threadIdx.x] = s; __syncthreads();
    for (int st = 128; st > 0; st >>= 1) {
        if (threadIdx.x < st) red[threadIdx.x] += red[threadIdx.x + st];
        __syncthreads();
    }
    if (threadIdx.x == 0) s_inv = rsqrtf(red[0] / (float)KV_LORA + EPS);
    __syncthreads();
    const float inv = s_inv;
    for (int i = threadIdx.x; i < KV_LORA; i += 256) {
        float v = row[i] * inv * w[i];
        __nv_bfloat16 h, l; split1(v, h, l);
        g_ckvnh[(size_t)t * KV_LORA + i] = h;
        g_ckvnl[(size_t)t * KV_LORA + i] = l;
    }

    if (threadIdx.x < ROPE / 2) {
        int i = threadIdx.x;
        float x1 = row[KV_LORA + 2 * i];
        float x2 = row[KV_LORA + 2 * i + 1];
        float f = freqs[(size_t)t * (ROPE / 2) + i];
        float c = cosf(f), sn = sinf(f);
        g_kpe[(size_t)t * ROPE + 2 * i]     = x1 * c - x2 * sn;
        g_kpe[(size_t)t * ROPE + 2 * i + 1] = x1 * sn + x2 * c;
    }
}

__global__ __launch_bounds__(256)
void assemble(const float* __restrict__ freqs, int t0)
{
    const int t = t0 + blockIdx.x;
    const int tid = threadIdx.x;
    for (int idx = tid; idx < NH * NOPE; idx += 256) {
        int hh = idx >> 7, d = idx & 127;
        size_t qk = ((size_t)hh * T_LEN + t) * QKD + d;
        __nv_bfloat16 h, l;
        split1(g_q[(size_t)t * NH * QKD + hh * QKD + d], h, l);
        g_aqh[qk] = h; g_aql[qk] = l;
        split1(g_kv[(size_t)t * NH * 256 + hh * 256 + d], h, l);
        g_akh[qk] = h; g_akl[qk] = l;
        size_t vv = ((size_t)hh * T_LEN + t) * VDIM + d;
        g_avF[vv] = __float2half(g_kv[(size_t)t * NH * 256 + hh * 256 + 128 + d]);
    }
    for (int idx = tid; idx < NH * (ROPE / 2); idx += 256) {
        int hh = idx >> 5, i = idx & 31;
        float f = freqs[(size_t)t * (ROPE / 2) + i];
        float c = cosf(f), sn = sinf(f);
        const float* qp = g_q + (size_t)t * NH * QKD + hh * QKD + NOPE;
        float x1 = qp[2 * i], x2 = qp[2 * i + 1];
        size_t base = ((size_t)hh * T_LEN + t) * QKD + NOPE;
        __nv_bfloat16 h, l;
        split1(x1 * c - x2 * sn, h, l);  g_aqh[base + 2*i] = h;   g_aql[base + 2*i] = l;
        split1(x1 * sn + x2 * c, h, l);  g_aqh[base + 2*i+1] = h; g_aql[base + 2*i+1] = l;
        split1(g_kpe[(size_t)t * ROPE + 2*i], h, l);     g_akh[base + 2*i] = h;   g_akl[base + 2*i] = l;
        split1(g_kpe[(size_t)t * ROPE + 2*i + 1], h, l); g_akh[base + 2*i+1] = h; g_akl[base + 2*i+1] = l;
    }
}

// ==================== tensor-core flash attention (QK 3-pass bf16, PV 2-pass fp16) ====
#define BQ 128
#define BK 64
#define SQH 200
#define SVH 136
#define ATT_SMEM ((2 * BQ * SQH + 2 * BK * SQH + BK * SVH) * 2)

__global__ __launch_bounds__(256, 1)
void mla_attn_mma(int qstart)
{
    extern __shared__ char smraw[];
    const uint32_t sb  = smem_u32(smraw);
    const uint32_t uQh = sb;
    const uint32_t uQl = uQh + BQ * SQH * 2;
    const uint32_t uKh = uQl + BQ * SQH * 2;
    const uint32_t uKl = uKh + BK * SQH * 2;
    const uint32_t uVF = uKl + BK * SQH * 2;

    const int h  = blockIdx.x;
    const int qi = qstart + (int)gridDim.y - 1 - (int)blockIdx.y;
    const int q0 = qi * BQ;
    const int tid = threadIdx.x, wid = tid >> 5, lane = tid & 31;
    const int mrow = wid * 16;

    const __nv_bfloat16* gQh = g_aqh + ((size_t)h * T_LEN + q0) * QKD;
    const __nv_bfloat16* gQl = g_aql + ((size_t)h * T_LEN + q0) * QKD;
    const __nv_bfloat16* gKh = g_akh + (size_t)h * T_LEN * QKD;
    const __nv_bfloat16* gKl = g_akl + (size_t)h * T_LEN * QKD;
    const __half*        gVF = g_avF + (size_t)h * T_LEN * VDIM;

    for (int i = tid; i < BQ * 24; i += 256) {
        int r = i / 24, c = i % 24;
        uint32_t d = (uint32_t)(r * SQH + c * 8) * 2;
        CPA(uQh + d, (const char*)(gQh + (size_t)r * QKD + c * 8));
        CPA(uQl + d, (const char*)(gQl + (size_t)r * QKD + c * 8));
    }
    CPA_COMMIT();

    float Oa[16][4];
#pragma unroll
    for (int n = 0; n < 16; n++)
#pragma unroll
        for (int j = 0; j < 4; j++) Oa[n][j] = 0.f;
    float mr0 = -1e30f, mr1 = -1e30f, lr0 = 0.f, lr1 = 0.f;

    const uint32_t qa_base = uQh + (uint32_t)((mrow + (lane & 15)) * SQH + (lane >> 4) * 8) * 2;
    const uint32_t ql_rel  = BQ * SQH * 2;
    const int kb_row = ((lane >> 4) & 1) * 8 + (lane & 7);
    const int kb_kad = ((lane >> 3) & 1) * 8;
    const int va_row = lane & 15;
    const int va_cad = (lane >> 4) * 8;

    const int nkt = 2 * qi + 2;
    for (int kt = 0; kt < nkt; kt++) {
        for (int i = tid; i < BK * 24; i += 256) {
            int r = i / 24, c = i % 24;
            const size_t go = (size_t)(kt * BK + r) * QKD + c * 8;
            uint32_t d = (uint32_t)(r * SQH + c * 8) * 2;
            CPA(uKh + d, (const char*)(gKh + go));
            CPA(uKl + d, (const char*)(gKl + go));
        }
        for (int i = tid; i < BK * 16; i += 256) {
            int r = i / 16, c = i % 16;
            const size_t go = (size_t)(kt * BK + r) * VDIM + c * 8;
            uint32_t d = (uint32_t)(r * SVH + c * 8) * 2;
            CPA(uVF + d, (const char*)(gVF + go));
        }
        CPA_COMMIT();
        CPA_WAIT0();
        __syncthreads();

        const int kbase = kt * BK;
        const bool active = kbase <= (q0 + mrow + 15);
        if (active) {
            float Sa[8][4];
#pragma unroll
            for (int n = 0; n < 8; n++)
#pragma unroll
                for (int j = 0; j < 4; j++) Sa[n][j] = 0.f;

#pragma unroll
            for (int ks = 0; ks < 12; ks++) {
                uint32_t ah[4], al[4];
                const uint32_t qo = qa_base + ks * 32;
                LDSM_X4(ah[0], ah[1], ah[2], ah[3], qo);
                LDSM_X4(al[0], al[1], al[2], al[3], qo + ql_rel);
                uint32_t bh[8][2], bl[8][2];
#pragma unroll
                for (int np = 0; np < 4; np++) {
                    const uint32_t bo = (uint32_t)((np * 16 + kb_row) * SQH + ks * 16 + kb_kad) * 2;
                    LDSM_X4(bh[2*np][0], bh[2*np][1], bh[2*np+1][0], bh[2*np+1][1], uKh + bo);
                    LDSM_X4(bl[2*np][0], bl[2*np][1], bl[2*np+1][0], bl[2*np+1][1], uKl + bo);
                }
#pragma unroll
                for (int n = 0; n < 8; n++) MMA_BF16(Sa[n], ah, bh[n][0], bh[n][1]);
#pragma unroll
                for (int n = 0; n < 8; n++) MMA_BF16(Sa[n], ah, bl[n][0], bl[n][1]);
#pragma unroll
                for (int n = 0; n < 8; n++) MMA_BF16(Sa[n], al, bh[n][0], bh[n][1]);
            }

            const int r0g = q0 + mrow + (lane >> 2);
            const int r1g = r0g + 8;
            const bool needmask = (kbase + BK - 1) > (q0 + mrow);
            float tm0 = -INFINITY, tm1 = -INFINITY;
#pragma unroll
            for (int n = 0; n < 8; n++) {
                const int c0 = kbase + n * 8 + (lane & 3) * 2;
                float v0 = Sa[n][0] * SOFTSCALE, v1 = Sa[n][1] * SOFTSCALE;
                float v2 = Sa[n][2] * SOFTSCALE, v3 = Sa[n][3] * SOFTSCALE;
                if (needmask) {
                    if (c0     > r0g) v0 = -INFINITY;
                    if (c0 + 1 > r0g) v1 = -INFINITY;
                    if (c0     > r1g) v2 = -INFINITY;
                    if (c0 + 1 > r1g) v3 = -INFINITY;
                }
                Sa[n][0] = v0; Sa[n][1] = v1; Sa[n][2] = v2; Sa[n][3] = v3;
                tm0 = fmaxf(tm0, fmaxf(v0, v1));
                tm1 = fmaxf(tm1, fmaxf(v2, v3));
            }
            tm0 = fmaxf(tm0, __shfl_xor_sync(0xffffffffu, tm0, 1));
            tm0 = fmaxf(tm0, __shfl_xor_sync(0xffffffffu, tm0, 2));
            tm1 = fmaxf(tm1, __shfl_xor_sync(0xffffffffu, tm1, 1));
            tm1 = fmaxf(tm1, __shfl_xor_sync(0xffffffffu, tm1, 2));
            const float nm0 = fmaxf(mr0, tm0), nm1 = fmaxf(mr1, tm1);
            const float sc0 = __expf(mr0 - nm0), sc1 = __expf(mr1 - nm1);
            float rs0 = 0.f, rs1 = 0.f;
#pragma unroll
            for (int n = 0; n < 8; n++) {
                Sa[n][0] = __expf(Sa[n][0] - nm0); rs0 += Sa[n][0];
                Sa[n][1] = __expf(Sa[n][1] - nm0); rs0 += Sa[n][1];
                Sa[n][2] = __expf(Sa[n][2] - nm1); rs1 += Sa[n][2];
                Sa[n][3] = __expf(Sa[n][3] - nm1); rs1 += Sa[n][3];
            }
            rs0 += __shfl_xor_sync(0xffffffffu, rs0, 1);
            rs0 += __shfl_xor_sync(0xffffffffu, rs0, 2);
            rs1 += __shfl_xor_sync(0xffffffffu, rs1, 1);
            rs1 += __shfl_xor_sync(0xffffffffu, rs1, 2);
            lr0 = lr0 * sc0 + rs0;
            lr1 = lr1 * sc1 + rs1;
            mr0 = nm0; mr1 = nm1;
#pragma unroll
            for (int n = 0; n < 16; n++) {
                Oa[n][0] *= sc0; Oa[n][1] *= sc0;
                Oa[n][2] *= sc1; Oa[n][3] *= sc1;
            }

            // pack P frags as fp16 hi/lo (exact split; P in [0,1])
            uint32_t ph[4][4], pl[4][4];
#pragma unroll
            for (int kf = 0; kf < 4; kf++) {
                pack2h(Sa[2*kf][0],   Sa[2*kf][1],   ph[kf][0], pl[kf][0]);
                pack2h(Sa[2*kf][2],   Sa[2*kf][3],   ph[kf][1], pl[kf][1]);
                pack2h(Sa[2*kf+1][0], Sa[2*kf+1][1], ph[kf][2], pl[kf][2]);
                pack2h(Sa[2*kf+1][2], Sa[2*kf+1][3], ph[kf][3], pl[kf][3]);
            }

            // O += P @ V : fp16, 2 passes
#pragma unroll
            for (int kf = 0; kf < 4; kf++) {
                uint32_t vb[16][2];
#pragma unroll
                for (int np = 0; np < 8; np++) {
                    const uint32_t vo = (uint32_t)((kf * 16 + va_row) * SVH + np * 16 + va_cad) * 2;
                    LDSM_X4_T(vb[2*np][0], vb[2*np][1], vb[2*np+1][0], vb[2*np+1][1], uVF + vo);
                }
#pragma unroll
                for (int n = 0; n < 16; n++) MMA_F16(Oa[n], ph[kf], vb[n][0], vb[n][1]);
#pragma unroll
                for (int n = 0; n < 16; n++) MMA_F16(Oa[n], pl[kf], vb[n][0], vb[n][1]);
            }
        }
        __syncthreads();
    }

    // epilogue: normalize + fp16 hi/lo write for terminal GEMM
    const float inv0 = 1.f / lr0, inv1 = 1.f / lr1;
    const int r0g = q0 + mrow + (lane >> 2);
#pragma unroll
    for (int n = 0; n < 16; n++) {
        const int col = h * VDIM + n * 8 + (lane & 3) * 2;
        __half h0, l0, h1, l1;
        split1h(Oa[n][0] * inv0, h0, l0);
        split1h(Oa[n][1] * inv0, h1, l1);
        *(__half2*)(g_yhH + (size_t)r0g * DIMX + col) = __half2(h0, h1);
        *(__half2*)(g_ylH + (size_t)r0g * DIMX + col) = __half2(l0, l1);
        split1h(Oa[n][2] * inv1, h0, l0);
        split1h(Oa[n][3] * inv1, h1, l1);
        *(__half2*)(g_yhH + (size_t)(r0g + 8) * DIMX + col) = __half2(h0, h1);
        *(__half2*)(g_ylH + (size_t)(r0g + 8) * DIMX + col) = __half2(l0, l1);
    }
}

// ==================== launch (multi-stream DAG) ====================
extern "C" void kernel_launch(void* const* d_in, const int* in_sizes, int n_in,
                              void* d_out, int out_size)
{
    const float* x        = (const float*)d_in[0];
    const float* freqs    = (const float*)d_in[1];
    const float* wq_a     = (const float*)d_in[3];
    const float* q_norm_w = (const float*)d_in[4];
    const float* wq_b     = (const float*)d_in[5];
    const float* wkv_a    = (const float*)d_in[6];
    const float* kv_norm_w= (const float*)d_in[7];
    const float* wkv_b    = (const float*)d_in[8];
    const float* wo       = (const float*)d_in[9];
    float* out = (float*)d_out;

    float *qakvf, *q_p, *kv_p;
    cudaGetSymbolAddress((void**)&qakvf, g_qakvf);
    cudaGetSymbolAddress((void**)&q_p,   g_q);
    cudaGetSymbolAddress((void**)&kv_p,  g_kv);

    __nv_bfloat16 *xh,*xl,*wabh,*wabl,*qah,*qal,*wqbh,*wqbl,*ckvnh,*ckvnl,*wkvbh,*wkvbl;
    __half *yhH,*ylH,*woF;
    cudaGetSymbolAddress((void**)&xh, g_xh);     cudaGetSymbolAddress((void**)&xl, g_xl);
    cudaGetSymbolAddress((void**)&wabh, g_wabh); cudaGetSymbolAddress((void**)&wabl, g_wabl);
    cudaGetSymbolAddress((void**)&qah, g_qah);   cudaGetSymbolAddress((void**)&qal, g_qal);
    cudaGetSymbolAddress((void**)&wqbh, g_wqbh); cudaGetSymbolAddress((void**)&wqbl, g_wqbl);
    cudaGetSymbolAddress((void**)&ckvnh, g_ckvnh); cudaGetSymbolAddress((void**)&ckvnl, g_ckvnl);
    cudaGetSymbolAddress((void**)&wkvbh, g_wkvbh); cudaGetSymbolAddress((void**)&wkvbl, g_wkvbl);
    cudaGetSymbolAddress((void**)&yhH, g_yhH);   cudaGetSymbolAddress((void**)&ylH, g_ylH);
    cudaGetSymbolAddress((void**)&woF, g_woF);

    cudaFuncSetAttribute(gemm_mma, cudaFuncAttributeMaxDynamicSharedMemorySize, GEMM_SMEM);
    cudaFuncSetAttribute(gemm_mma2, cudaFuncAttributeMaxDynamicSharedMemorySize, GEMM2_SMEM);
    cudaFuncSetAttribute(mla_attn_mma, cudaFuncAttributeMaxDynamicSharedMemorySize, ATT_SMEM);

    static cudaStream_t s1 = nullptr, s2 = nullptr;
    static cudaEvent_t eFork, eWab, eWqb, eWkvb, eWo, eG1, eG2, eG3, eAsmL, eAH;
    if (!s1) {
        cudaStreamCreateWithFlags(&s1, cudaStreamNonBlocking);
        cudaStreamCreateWithFlags(&s2, cudaStreamNonBlocking);
        cudaEventCreateWithFlags(&eFork, cudaEventDisableTiming);
        cudaEventCreateWithFlags(&eWab,  cudaEventDisableTiming);
        cudaEventCreateWithFlags(&eWqb,  cudaEventDisableTiming);
        cudaEventCreateWithFlags(&eWkvb, cudaEventDisableTiming);
        cudaEventCreateWithFlags(&eWo,   cudaEventDisableTiming);
        cudaEventCreateWithFlags(&eG1,   cudaEventDisableTiming);
        cudaEventCreateWithFlags(&eG2,   cudaEventDisableTiming);
        cudaEventCreateWithFlags(&eG3,   cudaEventDisableTiming);
        cudaEventCreateWithFlags(&eAsmL, cudaEventDisableTiming);
        cudaEventCreateWithFlags(&eAH,   cudaEventDisableTiming);
    }

    dim3 blk256(256);
    auto splits = [&](cudaStream_t st, const float* src, __nv_bfloat16* h,
                      __nv_bfloat16* l, size_t n) {
        int n4 = (int)(n / 4);
        split_bf16<<<(n4 + 255) / 256, 256, 0, st>>>(src, h, l, n4);
    };

    cudaEventRecord(eFork, 0);
    cudaStreamWaitEvent(s1, eFork, 0);
    cudaStreamWaitEvent(s2, eFork, 0);

    // s1: weight splits/conversions
    splits(s1, wq_a, wabh, wabl, (size_t)Q_LORA * DIMX);
    splits(s1, wkv_a, wabh + (size_t)Q_LORA * DIMX, wabl + (size_t)Q_LORA * DIMX,
           (size_t)KVA_OUT * DIMX);
    cudaEventRecord(eWab, s1);
    splits(s1, wq_b, wqbh, wqbl, (size_t)NH * QKD * Q_LORA);
    cudaEventRecord(eWqb, s1);
    splits(s1, wkv_b, wkvbh, wkvbl, (size_t)4096 * KV_LORA);
    cudaEventRecord(eWkvb, s1);
    {
        int n4 = (int)((size_t)DIMX * DIMX / 4);
        conv_fp16<<<(n4 + 255) / 256, 256, 0, s1>>>(wo, woF, n4);
    }
    cudaEventRecord(eWo, s1);

    // s0: x split -> fused qa|kvf GEMM
    splits(0, x, xh, xl, (size_t)T_LEN * DIMX);
    cudaStreamWaitEvent(0, eWab, 0);
    gemm_mma<<<dim3((NAB + 127) / 128, T_LEN / 128), blk256, GEMM_SMEM>>>(
        xh, xl, wabh, wabl, qakvf, T_LEN, NAB, DIMX);
    cudaEventRecord(eG1, 0);

    // s0: q path
    rmsnorm_split_qa<<<T_LEN, blk256>>>(q_norm_w);
    cudaStreamWaitEvent(0, eWqb, 0);
    gemm_mma<<<dim3(NH * QKD / 128, T_LEN / 128), blk256, GEMM_SMEM>>>(
        qah, qal, wqbh, wqbl, q_p, T_LEN, NH * QKD, Q_LORA);
    cudaEventRecord(eG2, 0);

    // s2: kv path
    cudaStreamWaitEvent(s2, eG1, 0);
    kv_prep<<<T_LEN, blk256, 0, s2>>>(kv_norm_w, freqs);
    cudaStreamWaitEvent(s2, eWkvb, 0);
    gemm_mma<<<dim3(4096 / 128, T_LEN / 128), blk256, GEMM_SMEM, s2>>>(
        ckvnh, ckvnl, wkvbh, wkvbl, kv_p, T_LEN, 4096, KV_LORA);
    cudaEventRecord(eG3, s2);

    // assemble halves
    cudaStreamWaitEvent(0, eG3, 0);
    assemble<<<T_LEN / 2, blk256>>>(freqs, 0);
    cudaEventRecord(eAsmL, 0);
    cudaStreamWaitEvent(s2, eG2, 0);
    assemble<<<T_LEN / 2, blk256, 0, s2>>>(freqs, T_LEN / 2);

    // attention low on s0; attention high on s2
    mla_attn_mma<<<dim3(NH, 8), blk256, ATT_SMEM>>>(0);
    cudaStreamWaitEvent(s2, eAsmL, 0);
    mla_attn_mma<<<dim3(NH, 8), blk256, ATT_SMEM, s2>>>(8);
    cudaEventRecord(eAH, s2);

    // terminal fp16 2-pass GEMM, split rows
    cudaStreamWaitEvent(0, eWo, 0);
    gemm_mma2<<<dim3(DIMX / 128, (T_LEN / 2) / 128), blk256, GEMM2_SMEM>>>(
        yhH, ylH, woF, out, T_LEN / 2, DIMX, NH * VDIM);
    cudaStreamWaitEvent(0, eAH, 0);
    gemm_mma2<<<dim3(DIMX / 128, (T_LEN / 2) / 128), blk256, GEMM2_SMEM>>>(
        yhH + (size_t)(T_LEN / 2) * DIMX, ylH + (size_t)(T_LEN / 2) * DIMX,
        woF, out + (size_t)(T_LEN / 2) * DIMX, T_LEN / 2, DIMX, NH * VDIM);
}

// round 17
// speedup vs baseline: 3.9518x; 1.0026x over previous
#include <cuda_runtime.h>
#include <cuda_bf16.h>
#include <cuda_fp16.h>
#include <math.h>
#include <cstdint>

// Problem constants
#define T_LEN 2048
#define DIMX 2048
#define NH 16
#define NOPE 128
#define ROPE 64
#define VDIM 128
#define QKD 192
#define Q_LORA 768
#define KV_LORA 512
#define KVA_OUT 576
#define NAB (Q_LORA + KVA_OUT)
#define SOFTSCALE (-96.0f)
#define EPS 1e-6f

// ==================== scratch ====================
__device__ float g_qakvf[(size_t)T_LEN * NAB];

// bf16 split buffers (hi/lo)
__device__ __nv_bfloat16 g_xh [(size_t)T_LEN * DIMX],      g_xl [(size_t)T_LEN * DIMX];
__device__ __nv_bfloat16 g_wabh[(size_t)NAB * DIMX],       g_wabl[(size_t)NAB * DIMX];
__device__ __nv_bfloat16 g_qah[(size_t)T_LEN * Q_LORA],    g_qal[(size_t)T_LEN * Q_LORA];
__device__ __nv_bfloat16 g_wqbh[(size_t)NH * QKD * Q_LORA],g_wqbl[(size_t)NH * QKD * Q_LORA];
__device__ __nv_bfloat16 g_ckvnh[(size_t)T_LEN * KV_LORA], g_ckvnl[(size_t)T_LEN * KV_LORA];
__device__ __nv_bfloat16 g_wkvbh[(size_t)4096 * KV_LORA],  g_wkvbl[(size_t)4096 * KV_LORA];

// fp16 buffers for the terminal GEMM
__device__ __half g_yhH[(size_t)T_LEN * DIMX], g_ylH[(size_t)T_LEN * DIMX];
__device__ __half g_woF[(size_t)DIMX * DIMX];

// attention operands: Q/K bf16 split (logit path), V single fp16 (benign)
__device__ __nv_bfloat16 g_aqh[(size_t)NH * T_LEN * QKD], g_aql[(size_t)NH * T_LEN * QKD];
__device__ __nv_bfloat16 g_akh[(size_t)NH * T_LEN * QKD], g_akl[(size_t)NH * T_LEN * QKD];
__device__ __half        g_avF[(size_t)NH * T_LEN * VDIM];

// ==================== PTX helpers ====================
__device__ __forceinline__ uint32_t smem_u32(const void* p) {
    uint32_t a;
    asm("{ .reg .u64 t; cvta.to.shared.u64 t, %1; cvt.u32.u64 %0, t; }" : "=r"(a) : "l"(p));
    return a;
}
#define CPA(dst, src) \
    asm volatile("cp.async.cg.shared.global [%0], [%1], 16;" :: "r"(dst), "l"(src))
#define CPA_COMMIT() asm volatile("cp.async.commit_group;" ::: "memory")
#define CPA_WAIT1()  asm volatile("cp.async.wait_group 1;" ::: "memory")
#define CPA_WAIT0()  asm volatile("cp.async.wait_group 0;" ::: "memory")

#define LDSM_X4(r0, r1, r2, r3, addr) \
    asm volatile("ldmatrix.sync.aligned.m8n8.x4.shared.b16 {%0,%1,%2,%3}, [%4];" \
        : "=r"(r0), "=r"(r1), "=r"(r2), "=r"(r3) : "r"(addr))
#define LDSM_X4_T(r0, r1, r2, r3, addr) \
    asm volatile("ldmatrix.sync.aligned.m8n8.x4.trans.shared.b16 {%0,%1,%2,%3}, [%4];" \
        : "=r"(r0), "=r"(r1), "=r"(r2), "=r"(r3) : "r"(addr))

#define MMA_BF16(d, a, b0, b1) \
    asm volatile("mma.sync.aligned.m16n8k16.row.col.f32.bf16.bf16.f32 " \
        "{%0,%1,%2,%3}, {%4,%5,%6,%7}, {%8,%9}, {%0,%1,%2,%3};" \
        : "+f"((d)[0]), "+f"((d)[1]), "+f"((d)[2]), "+f"((d)[3]) \
        : "r"((a)[0]), "r"((a)[1]), "r"((a)[2]), "r"((a)[3]), "r"(b0), "r"(b1))
#define MMA_F16(d, a, b0, b1) \
    asm volatile("mma.sync.aligned.m16n8k16.row.col.f32.f16.f16.f32 " \
        "{%0,%1,%2,%3}, {%4,%5,%6,%7}, {%8,%9}, {%0,%1,%2,%3};" \
        : "+f"((d)[0]), "+f"((d)[1]), "+f"((d)[2]), "+f"((d)[3]) \
        : "r"((a)[0]), "r"((a)[1]), "r"((a)[2]), "r"((a)[3]), "r"(b0), "r"(b1))

__device__ __forceinline__ void split1(float v, __nv_bfloat16& h, __nv_bfloat16& l) {
    h = __float2bfloat16(v);
    l = __float2bfloat16(v - __bfloat162float(h));
}
__device__ __forceinline__ void split1h(float v, __half& h, __half& l) {
    h = __float2half(v);
    l = __float2half(v - __half2float(h));
}
__device__ __forceinline__ void pack2h(float x, float y, uint32_t& hi, uint32_t& lo) {
    __half hx, lx, hy, ly;
    split1h(x, hx, lx); split1h(y, hy, ly);
    __half2 H(hx, hy), L(lx, ly);
    hi = *(uint32_t*)&H; lo = *(uint32_t*)&L;
}
__device__ __forceinline__ void wsplit2(__nv_bfloat16* hi, __nv_bfloat16* lo,
                                        size_t idx, float a, float b) {
    __nv_bfloat16 h0, l0, h1, l1;
    split1(a, h0, l0); split1(b, h1, l1);
    *(__nv_bfloat162*)(hi + idx) = __nv_bfloat162(h0, h1);
    *(__nv_bfloat162*)(lo + idx) = __nv_bfloat162(l0, l1);
}

// ==================== split fp32 -> bf16 hi/lo ====================
__global__ __launch_bounds__(256)
void split_bf16(const float* __restrict__ in, __nv_bfloat16* __restrict__ hi,
                __nv_bfloat16* __restrict__ lo, int n4)
{
    int i = blockIdx.x * 256 + threadIdx.x;
    if (i >= n4) return;
    float4 v = ((const float4*)in)[i];
    __nv_bfloat16 h0, h1, h2, h3, l0, l1, l2, l3;
    split1(v.x, h0, l0); split1(v.y, h1, l1);
    split1(v.z, h2, l2); split1(v.w, h3, l3);
    ((__nv_bfloat162*)hi)[i * 2 + 0] = __nv_bfloat162(h0, h1);
    ((__nv_bfloat162*)hi)[i * 2 + 1] = __nv_bfloat162(h2, h3);
    ((__nv_bfloat162*)lo)[i * 2 + 0] = __nv_bfloat162(l0, l1);
    ((__nv_bfloat162*)lo)[i * 2 + 1] = __nv_bfloat162(l2, l3);
}

__global__ __launch_bounds__(256)
void conv_fp16(const float* __restrict__ in, __half* __restrict__ o, int n4)
{
    int i = blockIdx.x * 256 + threadIdx.x;
    if (i >= n4) return;
    float4 v = ((const float4*)in)[i];
    ((__half2*)o)[i * 2 + 0] = __half2(__float2half(v.x), __float2half(v.y));
    ((__half2*)o)[i * 2 + 1] = __half2(__float2half(v.z), __float2half(v.w));
}

// ==================== GEMM core macro ====================
#define SH 40
#define TILE_HB (128 * SH * 2)
#define STG_B   (4 * TILE_HB)
#define GEMM_SMEM (2 * STG_B)

// full 3-pass bf16 mainloop (always 3 passes — R16 post-mortem: dropping the
// al*bh pass on bf16 operands costs ~2e-3 relative error, never acceptable)
#define GEMM_BF16_BODY                                                         \
    extern __shared__ char sm[];                                               \
    const uint32_t sb = smem_u32(sm);                                          \
    const int tid  = threadIdx.x;                                              \
    const int wid  = tid >> 5, lane = tid & 31;                                \
    const int wm   = wid & 1;                                                  \
    const int wn   = wid >> 1;                                                 \
    const int bm   = blockIdx.y * 128, bn = blockIdx.x * 128;                  \
    const int lrow = tid >> 1;                                                 \
    const int lpart = tid & 1;                                                 \
    const __nv_bfloat16* pAh = Ah + (size_t)(bm + lrow) * K;                   \
    const __nv_bfloat16* pAl = Al + (size_t)(bm + lrow) * K;                   \
    const __nv_bfloat16* pBh = Bh + (size_t)(bn + lrow) * K;                   \
    const __nv_bfloat16* pBl = Bl + (size_t)(bn + lrow) * K;                   \
    const uint32_t dofs = (uint32_t)lrow * (SH * 2) + lpart * 32;              \
    auto issue = [&](int c, int buf) {                                         \
        const int ho = c * 32 + lpart * 16;                                    \
        const uint32_t stg = sb + buf * STG_B;                                 \
        CPA(stg + 0 * TILE_HB + dofs, (const char*)(pAh + ho));                \
        CPA(stg + 0 * TILE_HB + dofs + 16, (const char*)(pAh + ho) + 16);      \
        CPA(stg + 1 * TILE_HB + dofs, (const char*)(pAl + ho));                \
        CPA(stg + 1 * TILE_HB + dofs + 16, (const char*)(pAl + ho) + 16);      \
        CPA(stg + 2 * TILE_HB + dofs, (const char*)(pBh + ho));                \
        CPA(stg + 2 * TILE_HB + dofs + 16, (const char*)(pBh + ho) + 16);      \
        CPA(stg + 3 * TILE_HB + dofs, (const char*)(pBl + ho));                \
        CPA(stg + 3 * TILE_HB + dofs + 16, (const char*)(pBl + ho) + 16);      \
    };                                                                         \
    float acc[4][4][4];                                                        \
    _Pragma("unroll")                                                          \
    for (int i = 0; i < 4; i++)                                                \
        _Pragma("unroll")                                                      \
        for (int j = 0; j < 4; j++)                                            \
            _Pragma("unroll")                                                  \
            for (int q = 0; q < 4; q++) acc[i][j][q] = 0.f;                    \
    const int arow = wm * 64 + (lane & 15);                                    \
    const int akad = (lane >> 4) * 8;                                          \
    const int brow_l = wn * 32 + ((lane >> 4) & 1) * 8 + (lane & 7);           \
    const int bkad  = ((lane >> 3) & 1) * 8;                                   \
    const int NC = K / 32;                                                     \
    issue(0, 0); CPA_COMMIT();                                                 \
    issue(1, 1); CPA_COMMIT();                                                 \
    for (int c = 0; c < NC; c++) {                                             \
        CPA_WAIT1();                                                           \
        __syncthreads();                                                       \
        const uint32_t stg = sb + (c & 1) * STG_B;                             \
        const uint32_t aB_h = stg + 0 * TILE_HB;                               \
        const uint32_t aB_l = stg + 1 * TILE_HB;                               \
        const uint32_t bB_h = stg + 2 * TILE_HB;                               \
        const uint32_t bB_l = stg + 3 * TILE_HB;                               \
        _Pragma("unroll")                                                      \
        for (int kh = 0; kh < 2; kh++) {                                       \
            const int kofs = kh * 16;                                          \
            uint32_t ah[4][4], al[4][4];                                       \
            _Pragma("unroll")                                                  \
            for (int mi = 0; mi < 4; mi++) {                                   \
                const uint32_t ao = (uint32_t)((arow + mi * 16) * SH + kofs + akad) * 2; \
                LDSM_X4(ah[mi][0], ah[mi][1], ah[mi][2], ah[mi][3], aB_h + ao);\
                LDSM_X4(al[mi][0], al[mi][1], al[mi][2], al[mi][3], aB_l + ao);\
            }                                                                  \
            uint32_t bh[2][2][2], bl[2][2][2];                                 \
            _Pragma("unroll")                                                  \
            for (int bt = 0; bt < 2; bt++) {                                   \
                const uint32_t bo = (uint32_t)((brow_l + bt * 16) * SH + kofs + bkad) * 2; \
                LDSM_X4(bh[bt][0][0], bh[bt][0][1], bh[bt][1][0], bh[bt][1][1], bB_h + bo); \
                LDSM_X4(bl[bt][0][0], bl[bt][0][1], bl[bt][1][0], bl[bt][1][1], bB_l + bo); \
            }                                                                  \
            _Pragma("unroll")                                                  \
            for (int mi = 0; mi < 4; mi++)                                     \
                _Pragma("unroll")                                              \
                for (int bt = 0; bt < 2; bt++) {                               \
                    MMA_BF16(acc[mi][2*bt],   ah[mi], bh[bt][0][0], bh[bt][0][1]); \
                    MMA_BF16(acc[mi][2*bt+1], ah[mi], bh[bt][1][0], bh[bt][1][1]); \
                }                                                              \
            _Pragma("unroll")                                                  \
            for (int mi = 0; mi < 4; mi++)                                     \
                _Pragma("unroll")                                              \
                for (int bt = 0; bt < 2; bt++) {                               \
                    MMA_BF16(acc[mi][2*bt],   ah[mi], bl[bt][0][0], bl[bt][0][1]); \
                    MMA_BF16(acc[mi][2*bt+1], ah[mi], bl[bt][1][0], bl[bt][1][1]); \
                }                                                              \
            _Pragma("unroll")                                                  \
            for (int mi = 0; mi < 4; mi++)                                     \
                _Pragma("unroll")                                              \
                for (int bt = 0; bt < 2; bt++) {                               \
                    MMA_BF16(acc[mi][2*bt],   al[mi], bh[bt][0][0], bh[bt][0][1]); \
                    MMA_BF16(acc[mi][2*bt+1], al[mi], bh[bt][1][0], bh[bt][1][1]); \
                }                                                              \
        }                                                                      \
        __syncthreads();                                                       \
        if (c + 2 < NC) issue(c + 2, c & 1);                                   \
        CPA_COMMIT();                                                          \
    }                                                                          \
    const int er = bm + wm * 64 + (lane >> 2);                                 \
    const int ec = bn + wn * 32 + (lane & 3) * 2;

// ---- generic fp32-out GEMM (gemm1) ----
__global__ __launch_bounds__(256, 1)
void gemm_mma(const __nv_bfloat16* __restrict__ Ah, const __nv_bfloat16* __restrict__ Al,
              const __nv_bfloat16* __restrict__ Bh, const __nv_bfloat16* __restrict__ Bl,
              float* __restrict__ C, int M, int N, int K)
{
    GEMM_BF16_BODY
#pragma unroll
    for (int mi = 0; mi < 4; mi++) {
#pragma unroll
        for (int ni = 0; ni < 4; ni++) {
            const int cc = ec + ni * 8;
            if (cc < N) {
                const int r0 = er + mi * 16;
                *(float2*)(C + (size_t)r0 * N + cc) =
                    make_float2(acc[mi][ni][0], acc[mi][ni][1]);
                *(float2*)(C + (size_t)(r0 + 8) * N + cc) =
                    make_float2(acc[mi][ni][2], acc[mi][ni][3]);
            }
        }
    }
}

// ---- q-projection GEMM: epilogue applies RoPE + writes per-head split aq ----
__global__ __launch_bounds__(256, 1)
void gemm_mma_q(const __nv_bfloat16* __restrict__ Ah, const __nv_bfloat16* __restrict__ Al,
                const __nv_bfloat16* __restrict__ Bh, const __nv_bfloat16* __restrict__ Bl,
                const float* __restrict__ freqs, int M, int N, int K)
{
    GEMM_BF16_BODY
#pragma unroll
    for (int mi = 0; mi < 4; mi++) {
#pragma unroll
        for (int ni = 0; ni < 4; ni++) {
            const int cc = ec + ni * 8;
            const int r0 = er + mi * 16, r1 = r0 + 8;
            const int h = cc / QKD, d = cc % QKD;
            const size_t b0 = ((size_t)h * T_LEN + r0) * QKD + d;
            const size_t b1 = ((size_t)h * T_LEN + r1) * QKD + d;
            float a0 = acc[mi][ni][0], a1 = acc[mi][ni][1];
            float a2 = acc[mi][ni][2], a3 = acc[mi][ni][3];
            if (d < NOPE) {
                wsplit2(g_aqh, g_aql, b0, a0, a1);
                wsplit2(g_aqh, g_aql, b1, a2, a3);
            } else {
                const int i = (d - NOPE) >> 1;
                float f0 = freqs[(size_t)r0 * 32 + i];
                float f1 = freqs[(size_t)r1 * 32 + i];
                float c0 = cosf(f0), s0 = sinf(f0);
                float c1 = cosf(f1), s1 = sinf(f1);
                wsplit2(g_aqh, g_aql, b0, a0 * c0 - a1 * s0, a0 * s0 + a1 * c0);
                wsplit2(g_aqh, g_aql, b1, a2 * c1 - a3 * s1, a2 * s1 + a3 * c1);
            }
        }
    }
}

// ---- kv-projection GEMM (FULL 3-pass): even N-tiles -> k_nope split-bf16,
//      odd tiles -> v fp16 (output format only; math identical) ----
__global__ __launch_bounds__(256, 1)
void gemm_mma_kv(const __nv_bfloat16* __restrict__ Ah, const __nv_bfloat16* __restrict__ Al,
                 const __nv_bfloat16* __restrict__ Bh, const __nv_bfloat16* __restrict__ Bl,
                 int M, int N, int K)
{
    const bool is_k = !(blockIdx.x & 1);
    GEMM_BF16_BODY
#pragma unroll
    for (int mi = 0; mi < 4; mi++) {
#pragma unroll
        for (int ni = 0; ni < 4; ni++) {
            const int cc = ec + ni * 8;
            const int r0 = er + mi * 16, r1 = r0 + 8;
            const int h = cc >> 8, d = cc & 255;
            float a0 = acc[mi][ni][0], a1 = acc[mi][ni][1];
            float a2 = acc[mi][ni][2], a3 = acc[mi][ni][3];
            if (is_k) {
                wsplit2(g_akh, g_akl, ((size_t)h * T_LEN + r0) * QKD + d, a0, a1);
                wsplit2(g_akh, g_akl, ((size_t)h * T_LEN + r1) * QKD + d, a2, a3);
            } else {
                const int dv = d - 128;
                *(__half2*)(g_avF + ((size_t)h * T_LEN + r0) * VDIM + dv) =
                    __half2(__float2half(a0), __float2half(a1));
                *(__half2*)(g_avF + ((size_t)h * T_LEN + r1) * VDIM + dv) =
                    __half2(__float2half(a2), __float2half(a3));
            }
        }
    }
}

// ==================== fp16 2-pass terminal GEMM ====================
#define STG2_B   (3 * TILE_HB)
#define GEMM2_SMEM (2 * STG2_B)

__global__ __launch_bounds__(256, 1)
void gemm_mma2(const __half* __restrict__ Ah, const __half* __restrict__ Al,
               const __half* __restrict__ B, float* __restrict__ C,
               int M, int N, int K)
{
    extern __shared__ char sm[];
    const uint32_t sb = smem_u32(sm);
    const int tid  = threadIdx.x;
    const int wid  = tid >> 5, lane = tid & 31;
    const int wm   = wid & 1;
    const int wn   = wid >> 1;
    const int bm   = blockIdx.y * 128, bn = blockIdx.x * 128;

    const int lrow = tid >> 1;
    const int lpart = tid & 1;
    const __half* pAh = Ah + (size_t)(bm + lrow) * K;
    const __half* pAl = Al + (size_t)(bm + lrow) * K;
    const __half* pB  = B  + (size_t)(bn + lrow) * K;
    const uint32_t dofs = (uint32_t)lrow * (SH * 2) + lpart * 32;

    auto issue = [&](int c, int buf) {
        const int ho = c * 32 + lpart * 16;
        const uint32_t stg = sb + buf * STG2_B;
        CPA(stg + 0 * TILE_HB + dofs, (const char*)(pAh + ho));
        CPA(stg + 0 * TILE_HB + dofs + 16, (const char*)(pAh + ho) + 16);
        CPA(stg + 1 * TILE_HB + dofs, (const char*)(pAl + ho));
        CPA(stg + 1 * TILE_HB + dofs + 16, (const char*)(pAl + ho) + 16);
        CPA(stg + 2 * TILE_HB + dofs, (const char*)(pB + ho));
        CPA(stg + 2 * TILE_HB + dofs + 16, (const char*)(pB + ho) + 16);
    };

    float acc[4][4][4];
#pragma unroll
    for (int i = 0; i < 4; i++)
#pragma unroll
        for (int j = 0; j < 4; j++)
#pragma unroll
            for (int q = 0; q < 4; q++) acc[i][j][q] = 0.f;

    const int arow = wm * 64 + (lane & 15);
    const int akad = (lane >> 4) * 8;
    const int brow_l = wn * 32 + ((lane >> 4) & 1) * 8 + (lane & 7);
    const int bkad  = ((lane >> 3) & 1) * 8;

    const int NC = K / 32;
    issue(0, 0); CPA_COMMIT();
    issue(1, 1); CPA_COMMIT();

    for (int c = 0; c < NC; c++) {
        CPA_WAIT1();
        __syncthreads();
        const uint32_t stg = sb + (c & 1) * STG2_B;
        const uint32_t aB_h = stg + 0 * TILE_HB;
        const uint32_t aB_l = stg + 1 * TILE_HB;
        const uint32_t bB   = stg + 2 * TILE_HB;

#pragma unroll
        for (int kh = 0; kh < 2; kh++) {
            const int kofs = kh * 16;
            uint32_t ah[4][4], al[4][4];
#pragma unroll
            for (int mi = 0; mi < 4; mi++) {
                const uint32_t ao = (uint32_t)((arow + mi * 16) * SH + kofs + akad) * 2;
                LDSM_X4(ah[mi][0], ah[mi][1], ah[mi][2], ah[mi][3], aB_h + ao);
                LDSM_X4(al[mi][0], al[mi][1], al[mi][2], al[mi][3], aB_l + ao);
            }
            uint32_t bb[2][2][2];
#pragma unroll
            for (int bt = 0; bt < 2; bt++) {
                const uint32_t bo = (uint32_t)((brow_l + bt * 16) * SH + kofs + bkad) * 2;
                LDSM_X4(bb[bt][0][0], bb[bt][0][1], bb[bt][1][0], bb[bt][1][1], bB + bo);
            }
#pragma unroll
            for (int mi = 0; mi < 4; mi++)
#pragma unroll
                for (int bt = 0; bt < 2; bt++) {
                    MMA_F16(acc[mi][2*bt],   ah[mi], bb[bt][0][0], bb[bt][0][1]);
                    MMA_F16(acc[mi][2*bt+1], ah[mi], bb[bt][1][0], bb[bt][1][1]);
                }
#pragma unroll
            for (int mi = 0; mi < 4; mi++)
#pragma unroll
                for (int bt = 0; bt < 2; bt++) {
                    MMA_F16(acc[mi][2*bt],   al[mi], bb[bt][0][0], bb[bt][0][1]);
                    MMA_F16(acc[mi][2*bt+1], al[mi], bb[bt][1][0], bb[bt][1][1]);
                }
        }
        __syncthreads();
        if (c + 2 < NC) issue(c + 2, c & 1);
        CPA_COMMIT();
    }

    const int er = bm + wm * 64 + (lane >> 2);
    const int ec = bn + wn * 32 + (lane & 3) * 2;
#pragma unroll
    for (int mi = 0; mi < 4; mi++) {
#pragma unroll
        for (int ni = 0; ni < 4; ni++) {
            const int cc = ec + ni * 8;
            const int r0 = er + mi * 16;
            *(float2*)(C + (size_t)r0 * N + cc) =
                make_float2(acc[mi][ni][0], acc[mi][ni][1]);
            *(float2*)(C + (size_t)(r0 + 8) * N + cc) =
                make_float2(acc[mi][ni][2], acc[mi][ni][3]);
        }
    }
}

// ==================== elementwise ====================
__global__ __launch_bounds__(256)
void rmsnorm_split_qa(const float* __restrict__ w)
{
    __shared__ float red[256];
    __shared__ float s_inv;
    const int t = blockIdx.x;
    const float* row = g_qakvf + (size_t)t * NAB;
    float s = 0.f;
    for (int i = threadIdx.x; i < Q_LORA; i += 256) { float v = row[i]; s = fmaf(v, v, s); }
    red[threadIdx.x] = s; __syncthreads();
    for (int st = 128; st > 0; st >>= 1) {
        if (threadIdx.x < st) red[threadIdx.x] += red[threadIdx.x + st];
        __syncthreads();
    }
    if (threadIdx.x == 0) s_inv = rsqrtf(red[0] / (float)Q_LORA + EPS);
    __syncthreads();
    const float inv = s_inv;
    for (int i = threadIdx.x; i < Q_LORA; i += 256) {
        float v = row[i] * inv * w[i];
        __nv_bfloat16 h, l; split1(v, h, l);
        g_qah[(size_t)t * Q_LORA + i] = h;
        g_qal[(size_t)t * Q_LORA + i] = l;
    }
}

// kv_prep: rmsnorm+split c_kv; rope k_pe and broadcast split into all heads of ak
__global__ __launch_bounds__(256)
void kv_prep(const float* __restrict__ w, const float* __restrict__ freqs)
{
    __shared__ float red[256];
    __shared__ float s_inv;
    const int t = blockIdx.x;
    const float* row = g_qakvf + (size_t)t * NAB + Q_LORA;
    float s = 0.f;
    for (int i = threadIdx.x; i < KV_LORA; i += 256) { float v = row[i]; s = fmaf(v, v, s); }
    red[threadIdx.x] = s; __syncthreads();
    for (int st = 128; st > 0; st >>= 1) {
        if (threadIdx.x < st) red[threadIdx.x] += red[threadIdx.x + st];
        __syncthreads();
    }
    if (threadIdx.x == 0) s_inv = rsqrtf(red[0] / (float)KV_LORA + EPS);
    __syncthreads();
    const float inv = s_inv;
    for (int i = threadIdx.x; i < KV_LORA; i += 256) {
        float v = row[i] * inv * w[i];
        __nv_bfloat16 h, l; split1(v, h, l);
        g_ckvnh[(size_t)t * KV_LORA + i] = h;
        g_ckvnl[(size_t)t * KV_LORA + i] = l;
    }

    if (threadIdx.x < ROPE / 2) {
        int i = threadIdx.x;
        float x1 = row[KV_LORA + 2 * i];
        float x2 = row[KV_LORA + 2 * i + 1];
        float f = freqs[(size_t)t * (ROPE / 2) + i];
        float c = cosf(f), sn = sinf(f);
        float k1 = x1 * c - x2 * sn;
        float k2 = x1 * sn + x2 * c;
        __nv_bfloat16 h1, l1, h2, l2;
        split1(k1, h1, l1); split1(k2, h2, l2);
#pragma unroll
        for (int hh = 0; hh < NH; hh++) {
            size_t base = ((size_t)hh * T_LEN + t) * QKD + NOPE + 2 * i;
            *(__nv_bfloat162*)(g_akh + base) = __nv_bfloat162(h1, h2);
            *(__nv_bfloat162*)(g_akl + base) = __nv_bfloat162(l1, l2);
        }
    }
}

// ==================== tensor-core flash attention (QK 3-pass bf16, PV 2-pass fp16) ====
#define BQ 128
#define BK 64
#define SQH 200
#define SVH 136
#define ATT_SMEM ((2 * BQ * SQH + 2 * BK * SQH + BK * SVH) * 2)

__global__ __launch_bounds__(256, 1)
void mla_attn_mma(int qstart)
{
    extern __shared__ char smraw[];
    const uint32_t sb  = smem_u32(smraw);
    const uint32_t uQh = sb;
    const uint32_t uQl = uQh + BQ * SQH * 2;
    const uint32_t uKh = uQl + BQ * SQH * 2;
    const uint32_t uKl = uKh + BK * SQH * 2;
    const uint32_t uVF = uKl + BK * SQH * 2;

    const int h  = blockIdx.x;
    const int qi = qstart + (int)gridDim.y - 1 - (int)blockIdx.y;
    const int q0 = qi * BQ;
    const int tid = threadIdx.x, wid = tid >> 5, lane = tid & 31;
    const int mrow = wid * 16;

    const __nv_bfloat16* gQh = g_aqh + ((size_t)h * T_LEN + q0) * QKD;
    const __nv_bfloat16* gQl = g_aql + ((size_t)h * T_LEN + q0) * QKD;
    const __nv_bfloat16* gKh = g_akh + (size_t)h * T_LEN * QKD;
    const __nv_bfloat16* gKl = g_akl + (size_t)h * T_LEN * QKD;
    const __half*        gVF = g_avF + (size_t)h * T_LEN * VDIM;

    for (int i = tid; i < BQ * 24; i += 256) {
        int r = i / 24, c = i % 24;
        uint32_t d = (uint32_t)(r * SQH + c * 8) * 2;
        CPA(uQh + d, (const char*)(gQh + (size_t)r * QKD + c * 8));
        CPA(uQl + d, (const char*)(gQl + (size_t)r * QKD + c * 8));
    }
    CPA_COMMIT();

    float Oa[16][4];
#pragma unroll
    for (int n = 0; n < 16; n++)
#pragma unroll
        for (int j = 0; j < 4; j++) Oa[n][j] = 0.f;
    float mr0 = -1e30f, mr1 = -1e30f, lr0 = 0.f, lr1 = 0.f;

    const uint32_t qa_base = uQh + (uint32_t)((mrow + (lane & 15)) * SQH + (lane >> 4) * 8) * 2;
    const uint32_t ql_rel  = BQ * SQH * 2;
    const int kb_row = ((lane >> 4) & 1) * 8 + (lane & 7);
    const int kb_kad = ((lane >> 3) & 1) * 8;
    const int va_row = lane & 15;
    const int va_cad = (lane >> 4) * 8;

    const int nkt = 2 * qi + 2;
    for (int kt = 0; kt < nkt; kt++) {
        for (int i = tid; i < BK * 24; i += 256) {
            int r = i / 24, c = i % 24;
            const size_t go = (size_t)(kt * BK + r) * QKD + c * 8;
            uint32_t d = (uint32_t)(r * SQH + c * 8) * 2;
            CPA(uKh + d, (const char*)(gKh + go));
            CPA(uKl + d, (const char*)(gKl + go));
        }
        for (int i = tid; i < BK * 16; i += 256) {
            int r = i / 16, c = i % 16;
            const size_t go = (size_t)(kt * BK + r) * VDIM + c * 8;
            uint32_t d = (uint32_t)(r * SVH + c * 8) * 2;
            CPA(uVF + d, (const char*)(gVF + go));
        }
        CPA_COMMIT();
        CPA_WAIT0();
        __syncthreads();

        const int kbase = kt * BK;
        const bool active = kbase <= (q0 + mrow + 15);
        if (active) {
            float Sa[8][4];
#pragma unroll
            for (int n = 0; n < 8; n++)
#pragma unroll
                for (int j = 0; j < 4; j++) Sa[n][j] = 0.f;

#pragma unroll
            for (int ks = 0; ks < 12; ks++) {
                uint32_t ah[4], al[4];
                const uint32_t qo = qa_base + ks * 32;
                LDSM_X4(ah[0], ah[1], ah[2], ah[3], qo);
                LDSM_X4(al[0], al[1], al[2], al[3], qo + ql_rel);
                uint32_t bh[8][2], bl[8][2];
#pragma unroll
                for (int np = 0; np < 4; np++) {
                    const uint32_t bo = (uint32_t)((np * 16 + kb_row) * SQH + ks * 16 + kb_kad) * 2;
                    LDSM_X4(bh[2*np][0], bh[2*np][1], bh[2*np+1][0], bh[2*np+1][1], uKh + bo);
                    LDSM_X4(bl[2*np][0], bl[2*np][1], bl[2*np+1][0], bl[2*np+1][1], uKl + bo);
                }
#pragma unroll
                for (int n = 0; n < 8; n++) MMA_BF16(Sa[n], ah, bh[n][0], bh[n][1]);
#pragma unroll
                for (int n = 0; n < 8; n++) MMA_BF16(Sa[n], ah, bl[n][0], bl[n][1]);
#pragma unroll
                for (int n = 0; n < 8; n++) MMA_BF16(Sa[n], al, bh[n][0], bh[n][1]);
            }

            const int r0g = q0 + mrow + (lane >> 2);
            const int r1g = r0g + 8;
            const bool needmask = (kbase + BK - 1) > (q0 + mrow);
            float tm0 = -INFINITY, tm1 = -INFINITY;
#pragma unroll
            for (int n = 0; n < 8; n++) {
                const int c0 = kbase + n * 8 + (lane & 3) * 2;
                float v0 = Sa[n][0] * SOFTSCALE, v1 = Sa[n][1] * SOFTSCALE;
                float v2 = Sa[n][2] * SOFTSCALE, v3 = Sa[n][3] * SOFTSCALE;
                if (needmask) {
                    if (c0     > r0g) v0 = -INFINITY;
                    if (c0 + 1 > r0g) v1 = -INFINITY;
                    if (c0     > r1g) v2 = -INFINITY;
                    if (c0 + 1 > r1g) v3 = -INFINITY;
                }
                Sa[n][0] = v0; Sa[n][1] = v1; Sa[n][2] = v2; Sa[n][3] = v3;
                tm0 = fmaxf(tm0, fmaxf(v0, v1));
                tm1 = fmaxf(tm1, fmaxf(v2, v3));
            }
            tm0 = fmaxf(tm0, __shfl_xor_sync(0xffffffffu, tm0, 1));
            tm0 = fmaxf(tm0, __shfl_xor_sync(0xffffffffu, tm0, 2));
            tm1 = fmaxf(tm1, __shfl_xor_sync(0xffffffffu, tm1, 1));
            tm1 = fmaxf(tm1, __shfl_xor_sync(0xffffffffu, tm1, 2));
            const float nm0 = fmaxf(mr0, tm0), nm1 = fmaxf(mr1, tm1);
            const float sc0 = __expf(mr0 - nm0), sc1 = __expf(mr1 - nm1);
            float rs0 = 0.f, rs1 = 0.f;
#pragma unroll
            for (int n = 0; n < 8; n++) {
                Sa[n][0] = __expf(Sa[n][0] - nm0); rs0 += Sa[n][0];
                Sa[n][1] = __expf(Sa[n][1] - nm0); rs0 += Sa[n][1];
                Sa[n][2] = __expf(Sa[n][2] - nm1); rs1 += Sa[n][2];
                Sa[n][3] = __expf(Sa[n][3] - nm1); rs1 += Sa[n][3];
            }
            rs0 += __shfl_xor_sync(0xffffffffu, rs0, 1);
            rs0 += __shfl_xor_sync(0xffffffffu, rs0, 2);
            rs1 += __shfl_xor_sync(0xffffffffu, rs1, 1);
            rs1 += __shfl_xor_sync(0xffffffffu, rs1, 2);
            lr0 = lr0 * sc0 + rs0;
            lr1 = lr1 * sc1 + rs1;
            mr0 = nm0; mr1 = nm1;
#pragma unroll
            for (int n = 0; n < 16; n++) {
                Oa[n][0] *= sc0; Oa[n][1] *= sc0;
                Oa[n][2] *= sc1; Oa[n][3] *= sc1;
            }

            uint32_t ph[4][4], pl[4][4];
#pragma unroll
            for (int kf = 0; kf < 4; kf++) {
                pack2h(Sa[2*kf][0],   Sa[2*kf][1],   ph[kf][0], pl[kf][0]);
                pack2h(Sa[2*kf][2],   Sa[2*kf][3],   ph[kf][1], pl[kf][1]);
                pack2h(Sa[2*kf+1][0], Sa[2*kf+1][1], ph[kf][2], pl[kf][2]);
                pack2h(Sa[2*kf+1][2], Sa[2*kf+1][3], ph[kf][3], pl[kf][3]);
            }

#pragma unroll
            for (int kf = 0; kf < 4; kf++) {
                uint32_t vb[16][2];
#pragma unroll
                for (int np = 0; np < 8; np++) {
                    const uint32_t vo = (uint32_t)((kf * 16 + va_row) * SVH + np * 16 + va_cad) * 2;
                    LDSM_X4_T(vb[2*np][0], vb[2*np][1], vb[2*np+1][0], vb[2*np+1][1], uVF + vo);
                }
#pragma unroll
                for (int n = 0; n < 16; n++) MMA_F16(Oa[n], ph[kf], vb[n][0], vb[n][1]);
#pragma unroll
                for (int n = 0; n < 16; n++) MMA_F16(Oa[n], pl[kf], vb[n][0], vb[n][1]);
            }
        }
        __syncthreads();
    }

    const float inv0 = 1.f / lr0, inv1 = 1.f / lr1;
    const int r0g = q0 + mrow + (lane >> 2);
#pragma unroll
    for (int n = 0; n < 16; n++) {
        const int col = h * VDIM + n * 8 + (lane & 3) * 2;
        __half h0, l0, h1, l1;
        split1h(Oa[n][0] * inv0, h0, l0);
        split1h(Oa[n][1] * inv0, h1, l1);
        *(__half2*)(g_yhH + (size_t)r0g * DIMX + col) = __half2(h0, h1);
        *(__half2*)(g_ylH + (size_t)r0g * DIMX + col) = __half2(l0, l1);
        split1h(Oa[n][2] * inv1, h0, l0);
        split1h(Oa[n][3] * inv1, h1, l1);
        *(__half2*)(g_yhH + (size_t)(r0g + 8) * DIMX + col) = __half2(h0, h1);
        *(__half2*)(g_ylH + (size_t)(r0g + 8) * DIMX + col) = __half2(l0, l1);
    }
}

// ==================== launch (multi-stream DAG) ====================
extern "C" void kernel_launch(void* const* d_in, const int* in_sizes, int n_in,
                              void* d_out, int out_size)
{
    const float* x        = (const float*)d_in[0];
    const float* freqs    = (const float*)d_in[1];
    const float* wq_a     = (const float*)d_in[3];
    const float* q_norm_w = (const float*)d_in[4];
    const float* wq_b     = (const float*)d_in[5];
    const float* wkv_a    = (const float*)d_in[6];
    const float* kv_norm_w= (const float*)d_in[7];
    const float* wkv_b    = (const float*)d_in[8];
    const float* wo       = (const float*)d_in[9];
    float* out = (float*)d_out;

    float* qakvf;
    cudaGetSymbolAddress((void**)&qakvf, g_qakvf);

    __nv_bfloat16 *xh,*xl,*wabh,*wabl,*qah,*qal,*wqbh,*wqbl,*ckvnh,*ckvnl,*wkvbh,*wkvbl;
    __half *yhH,*ylH,*woF;
    cudaGetSymbolAddress((void**)&xh, g_xh);     cudaGetSymbolAddress((void**)&xl, g_xl);
    cudaGetSymbolAddress((void**)&wabh, g_wabh); cudaGetSymbolAddress((void**)&wabl, g_wabl);
    cudaGetSymbolAddress((void**)&qah, g_qah);   cudaGetSymbolAddress((void**)&qal, g_qal);
    cudaGetSymbolAddress((void**)&wqbh, g_wqbh); cudaGetSymbolAddress((void**)&wqbl, g_wqbl);
    cudaGetSymbolAddress((void**)&ckvnh, g_ckvnh); cudaGetSymbolAddress((void**)&ckvnl, g_ckvnl);
    cudaGetSymbolAddress((void**)&wkvbh, g_wkvbh); cudaGetSymbolAddress((void**)&wkvbl, g_wkvbl);
    cudaGetSymbolAddress((void**)&yhH, g_yhH);   cudaGetSymbolAddress((void**)&ylH, g_ylH);
    cudaGetSymbolAddress((void**)&woF, g_woF);

    cudaFuncSetAttribute(gemm_mma, cudaFuncAttributeMaxDynamicSharedMemorySize, GEMM_SMEM);
    cudaFuncSetAttribute(gemm_mma_q, cudaFuncAttributeMaxDynamicSharedMemorySize, GEMM_SMEM);
    cudaFuncSetAttribute(gemm_mma_kv, cudaFuncAttributeMaxDynamicSharedMemorySize, GEMM_SMEM);
    cudaFuncSetAttribute(gemm_mma2, cudaFuncAttributeMaxDynamicSharedMemorySize, GEMM2_SMEM);
    cudaFuncSetAttribute(mla_attn_mma, cudaFuncAttributeMaxDynamicSharedMemorySize, ATT_SMEM);

    static cudaStream_t s1 = nullptr, s2 = nullptr;
    static cudaEvent_t eFork, eWab, eWqb, eWkvb, eWo, eG1, eG2, eG3, eAH;
    if (!s1) {
        cudaStreamCreateWithFlags(&s1, cudaStreamNonBlocking);
        cudaStreamCreateWithFlags(&s2, cudaStreamNonBlocking);
        cudaEventCreateWithFlags(&eFork, cudaEventDisableTiming);
        cudaEventCreateWithFlags(&eWab,  cudaEventDisableTiming);
        cudaEventCreateWithFlags(&eWqb,  cudaEventDisableTiming);
        cudaEventCreateWithFlags(&eWkvb, cudaEventDisableTiming);
        cudaEventCreateWithFlags(&eWo,   cudaEventDisableTiming);
        cudaEventCreateWithFlags(&eG1,   cudaEventDisableTiming);
        cudaEventCreateWithFlags(&eG2,   cudaEventDisableTiming);
        cudaEventCreateWithFlags(&eG3,   cudaEventDisableTiming);
        cudaEventCreateWithFlags(&eAH,   cudaEventDisableTiming);
    }

    dim3 blk256(256);
    auto splits = [&](cudaStream_t st, const float* src, __nv_bfloat16* h,
                      __nv_bfloat16* l, size_t n) {
        int n4 = (int)(n / 4);
        split_bf16<<<(n4 + 255) / 256, 256, 0, st>>>(src, h, l, n4);
    };

    cudaEventRecord(eFork, 0);
    cudaStreamWaitEvent(s1, eFork, 0);
    cudaStreamWaitEvent(s2, eFork, 0);

    // s1: weight splits/conversions
    splits(s1, wq_a, wabh, wabl, (size_t)Q_LORA * DIMX);
    splits(s1, wkv_a, wabh + (size_t)Q_LORA * DIMX, wabl + (size_t)Q_LORA * DIMX,
           (size_t)KVA_OUT * DIMX);
    cudaEventRecord(eWab, s1);
    splits(s1, wq_b, wqbh, wqbl, (size_t)NH * QKD * Q_LORA);
    cudaEventRecord(eWqb, s1);
    splits(s1, wkv_b, wkvbh, wkvbl, (size_t)4096 * KV_LORA);
    cudaEventRecord(eWkvb, s1);
    {
        int n4 = (int)((size_t)DIMX * DIMX / 4);
        conv_fp16<<<(n4 + 255) / 256, 256, 0, s1>>>(wo, woF, n4);
    }
    cudaEventRecord(eWo, s1);

    // s0: x split -> fused qa|kvf GEMM
    splits(0, x, xh, xl, (size_t)T_LEN * DIMX);
    cudaStreamWaitEvent(0, eWab, 0);
    gemm_mma<<<dim3((NAB + 127) / 128, T_LEN / 128), blk256, GEMM_SMEM>>>(
        xh, xl, wabh, wabl, qakvf, T_LEN, NAB, DIMX);
    cudaEventRecord(eG1, 0);

    // s0: q path (RoPE fused in GEMM epilogue)
    rmsnorm_split_qa<<<T_LEN, blk256>>>(q_norm_w);
    cudaStreamWaitEvent(0, eWqb, 0);
    gemm_mma_q<<<dim3(NH * QKD / 128, T_LEN / 128), blk256, GEMM_SMEM>>>(
        qah, qal, wqbh, wqbl, freqs, T_LEN, NH * QKD, Q_LORA);
    cudaEventRecord(eG2, 0);

    // s2: kv path (kv_prep broadcasts rope-k; gemm_mma_kv writes ak/av direct)
    cudaStreamWaitEvent(s2, eG1, 0);
    kv_prep<<<T_LEN, blk256, 0, s2>>>(kv_norm_w, freqs);
    cudaStreamWaitEvent(s2, eWkvb, 0);
    gemm_mma_kv<<<dim3(4096 / 128, T_LEN / 128), blk256, GEMM_SMEM, s2>>>(
        ckvnh, ckvnl, wkvbh, wkvbl, T_LEN, 4096, KV_LORA);
    cudaEventRecord(eG3, s2);

    // attention low on s0; attention high on s2
    cudaStreamWaitEvent(0, eG3, 0);
    mla_attn_mma<<<dim3(NH, 8), blk256, ATT_SMEM>>>(0);
    cudaStreamWaitEvent(s2, eG2, 0);
    mla_attn_mma<<<dim3(NH, 8), blk256, ATT_SMEM, s2>>>(8);
    cudaEventRecord(eAH, s2);

    // terminal fp16 2-pass GEMM, split rows
    cudaStreamWaitEvent(0, eWo, 0);
    gemm_mma2<<<dim3(DIMX / 128, (T_LEN / 2) / 128), blk256, GEMM2_SMEM>>>(
        yhH, ylH, woF, out, T_LEN / 2, DIMX, NH * VDIM);
    cudaStreamWaitEvent(0, eAH, 0);
    gemm_mma2<<<dim3(DIMX / 128, (T_LEN / 2) / 128), blk256, GEMM2_SMEM>>>(
        yhH + (size_t)(T_LEN / 2) * DIMX, ylH + (size_t)(T_LEN / 2) * DIMX,
        woF, out + (size_t)(T_LEN / 2) * DIMX, T_LEN / 2, DIMX, NH * VDIM);
}